// round 1
// baseline (speedup 1.0000x reference)
#include <cuda_runtime.h>
#include <cstdint>
#include <cstddef>

#define B_SZ 1024
#define T_SZ 128
#define M_SZ 256
#define P_SZ 256
#define TS   127   // T-1 recurrence steps

// ---------------- scratch (static device globals; no runtime allocation) ----
__device__ float g_A[(size_t)T_SZ * B_SZ * M_SZ];   // (t,b,m') x-part preactivation, 134MB
__device__ float g_U[B_SZ * M_SZ];                  // per-step d-part preactivation
__device__ float g_HC[B_SZ * 2 * P_SZ];             // [h | c] per batch
__device__ float g_CTX[B_SZ * M_SZ];                // attention context
__device__ float g_YT[B_SZ];                        // y_tilde scalar per batch
__device__ float g_GATES[B_SZ * 4 * P_SZ];          // LSTM gate preactivations (h@W_hh^T)

// ---------------- init ------------------------------------------------------
__global__ void init_hc_kernel() {
    int i = blockIdx.x * blockDim.x + threadIdx.x;
    if (i < B_SZ * 2 * P_SZ) g_HC[i] = 0.0f;
}

// ---------------- generic NT GEMM: C[m][n] = sum_k A[m*lda+k]*B[n*ldb+k] ----
// grid.x = M/BM, grid.y = N/BN, threads = (BM/TM)*(BN/TN)
template<int BM, int BN, int BK, int TM, int TN>
__global__ void gemm_nt(const float* __restrict__ A, int lda,
                        const float* __restrict__ Bm, int ldb,
                        float* __restrict__ C, int ldc, int K)
{
    constexpr int THREADS = (BM / TM) * (BN / TN);
    __shared__ float As[BK][BM + 4];
    __shared__ float Bs[BK][BN + 4];

    const int tid = threadIdx.x;
    const int tx = tid % (BN / TN);
    const int ty = tid / (BN / TN);

    const float* Ab = A  + (size_t)blockIdx.x * BM * lda;
    const float* Bb = Bm + (size_t)blockIdx.y * BN * ldb;

    float acc[TM][TN];
#pragma unroll
    for (int i = 0; i < TM; i++)
#pragma unroll
        for (int j = 0; j < TN; j++) acc[i][j] = 0.0f;

    for (int k0 = 0; k0 < K; k0 += BK) {
        // load A tile (BM x BK), store transposed As[k][m]
        for (int i = tid; i < BM * (BK / 4); i += THREADS) {
            int m  = i / (BK / 4);
            int k4 = (i % (BK / 4)) * 4;
            float4 v = *(const float4*)(Ab + (size_t)m * lda + k0 + k4);
            As[k4 + 0][m] = v.x; As[k4 + 1][m] = v.y;
            As[k4 + 2][m] = v.z; As[k4 + 3][m] = v.w;
        }
        // load B tile (BN x BK), store transposed Bs[k][n]
        for (int i = tid; i < BN * (BK / 4); i += THREADS) {
            int n  = i / (BK / 4);
            int k4 = (i % (BK / 4)) * 4;
            float4 v = *(const float4*)(Bb + (size_t)n * ldb + k0 + k4);
            Bs[k4 + 0][n] = v.x; Bs[k4 + 1][n] = v.y;
            Bs[k4 + 2][n] = v.z; Bs[k4 + 3][n] = v.w;
        }
        __syncthreads();

#pragma unroll
        for (int kk = 0; kk < BK; kk++) {
            float a[TM], b[TN];
#pragma unroll
            for (int i = 0; i < TM; i++) a[i] = As[kk][ty * TM + i];
#pragma unroll
            for (int j = 0; j < TN; j++) b[j] = Bs[kk][tx * TN + j];
#pragma unroll
            for (int i = 0; i < TM; i++)
#pragma unroll
                for (int j = 0; j < TN; j++)
                    acc[i][j] = fmaf(a[i], b[j], acc[i][j]);
        }
        __syncthreads();
    }

#pragma unroll
    for (int i = 0; i < TM; i++)
#pragma unroll
        for (int j = 0; j < TN; j++)
            C[(size_t)(blockIdx.x * BM + ty * TM + i) * ldc
              + blockIdx.y * BN + tx * TN + j] = acc[i][j];
}

// ---------------- fused attention step: l -> softmax -> ctx -> y_tilde -----
// one block per batch, 256 threads (8 warps)
__global__ void attn_step_kernel(const float* __restrict__ X,     // (T,B,M)
                                 const float* __restrict__ v_d,   // (256)
                                 const float* __restrict__ Wl,    // (257)
                                 const float* __restrict__ Y,     // (B,127)
                                 int t_step)
{
    const int b    = blockIdx.x;
    const int tid  = threadIdx.x;     // 0..255
    const int lane = tid & 31;
    const int warp = tid >> 5;

    __shared__ float u_s[M_SZ], v_s[M_SZ];
    __shared__ float l_s[T_SZ], beta_s[T_SZ];
    __shared__ float redm[8], redsum[8], redy[8];

    u_s[tid] = g_U[b * M_SZ + tid];
    v_s[tid] = v_d[tid];
    __syncthreads();

    // phase 1: logits l[t] = sum_m v[m] * tanh(u[m] + A[t,b,m])
    for (int t = warp; t < T_SZ; t += 8) {
        const float* Ar = g_A + ((size_t)t * B_SZ + b) * M_SZ;
        float acc = 0.0f;
#pragma unroll
        for (int j = 0; j < 8; j++) {
            int m = lane + 32 * j;
            float x = u_s[m] + Ar[m];
            float th;
            asm("tanh.approx.f32 %0, %1;" : "=f"(th) : "f"(x));
            acc = fmaf(v_s[m], th, acc);
        }
#pragma unroll
        for (int o = 16; o; o >>= 1) acc += __shfl_xor_sync(0xffffffffu, acc, o);
        if (lane == 0) l_s[t] = acc;
    }
    __syncthreads();

    // phase 2: softmax over T=128 logits
    float lv = (tid < T_SZ) ? l_s[tid] : -1e30f;
    float mx = lv;
#pragma unroll
    for (int o = 16; o; o >>= 1) mx = fmaxf(mx, __shfl_xor_sync(0xffffffffu, mx, o));
    if (lane == 0) redm[warp] = mx;
    __syncthreads();
    mx = redm[0];
#pragma unroll
    for (int w = 1; w < 8; w++) mx = fmaxf(mx, redm[w]);

    float e = (tid < T_SZ) ? expf(lv - mx) : 0.0f;
    float sm = e;
#pragma unroll
    for (int o = 16; o; o >>= 1) sm += __shfl_xor_sync(0xffffffffu, sm, o);
    if (lane == 0) redsum[warp] = sm;
    __syncthreads();
    sm = redsum[0] + redsum[1] + redsum[2] + redsum[3]
       + redsum[4] + redsum[5] + redsum[6] + redsum[7];
    if (tid < T_SZ) beta_s[tid] = e / sm;
    __syncthreads();

    // phase 3: ctx[m] = sum_t beta[t] * X[t,b,m]   (thread = m, coalesced)
    float c = 0.0f;
    const float* Xb = X + (size_t)b * M_SZ + tid;
#pragma unroll 4
    for (int t = 0; t < T_SZ; t++)
        c = fmaf(beta_s[t], Xb[(size_t)t * B_SZ * M_SZ], c);
    g_CTX[b * M_SZ + tid] = c;

    // phase 4: y_tilde = Wl[0]*y_t + sum_m Wl[1+m]*ctx[m]
    float yv = Wl[1 + tid] * c;
#pragma unroll
    for (int o = 16; o; o >>= 1) yv += __shfl_xor_sync(0xffffffffu, yv, o);
    if (lane == 0) redy[warp] = yv;
    __syncthreads();
    if (tid == 0) {
        float s = redy[0] + redy[1] + redy[2] + redy[3]
                + redy[4] + redy[5] + redy[6] + redy[7];
        g_YT[b] = fmaf(Wl[0], Y[(size_t)b * TS + t_step], s);
    }
}

// ---------------- LSTM pointwise update ------------------------------------
__global__ void lstm_step_kernel(const float* __restrict__ W_ih,
                                 const float* __restrict__ b_ih,
                                 const float* __restrict__ b_hh)
{
    const int b = blockIdx.x;
    const int p = threadIdx.x;   // 0..255
    const float yt = g_YT[b];
    const float* gr = g_GATES + (size_t)b * 4 * P_SZ;

    float ig = gr[p]            + yt * W_ih[p]            + b_ih[p]            + b_hh[p];
    float fg = gr[P_SZ + p]     + yt * W_ih[P_SZ + p]     + b_ih[P_SZ + p]     + b_hh[P_SZ + p];
    float gg = gr[2 * P_SZ + p] + yt * W_ih[2 * P_SZ + p] + b_ih[2 * P_SZ + p] + b_hh[2 * P_SZ + p];
    float og = gr[3 * P_SZ + p] + yt * W_ih[3 * P_SZ + p] + b_ih[3 * P_SZ + p] + b_hh[3 * P_SZ + p];

    float c  = g_HC[(size_t)b * 2 * P_SZ + P_SZ + p];
    float si = 1.0f / (1.0f + expf(-ig));
    float sf = 1.0f / (1.0f + expf(-fg));
    float so = 1.0f / (1.0f + expf(-og));
    float cn = sf * c + si * tanhf(gg);
    float hn = so * tanhf(cn);

    g_HC[(size_t)b * 2 * P_SZ + p]        = hn;
    g_HC[(size_t)b * 2 * P_SZ + P_SZ + p] = cn;
}

// ---------------- final head: out = ([h,ctx] @ Wb^T + b) @ vb^T + vb_b -----
__global__ void final_head_kernel(const float* __restrict__ Wb_w,
                                  const float* __restrict__ Wb_b,
                                  const float* __restrict__ vb_w,
                                  const float* __restrict__ vb_b,
                                  float* __restrict__ out)
{
    const int b   = blockIdx.x;
    const int tid = threadIdx.x;  // 0..255 = p
    __shared__ float hc_s[2 * P_SZ];
    __shared__ float red[8];

    hc_s[tid]        = g_HC[(size_t)b * 2 * P_SZ + tid];   // h
    hc_s[P_SZ + tid] = g_CTX[(size_t)b * M_SZ + tid];      // ctx
    __syncthreads();

    const float* wr = Wb_w + (size_t)tid * (P_SZ + M_SZ);
    float t = Wb_b[tid];
#pragma unroll 4
    for (int k = 0; k < 2 * P_SZ; k++)
        t = fmaf(wr[k], hc_s[k], t);
    float val = vb_w[tid] * t;

    int lane = tid & 31, warp = tid >> 5;
#pragma unroll
    for (int o = 16; o; o >>= 1) val += __shfl_xor_sync(0xffffffffu, val, o);
    if (lane == 0) red[warp] = val;
    __syncthreads();
    if (tid == 0)
        out[b] = vb_b[0] + red[0] + red[1] + red[2] + red[3]
                         + red[4] + red[5] + red[6] + red[7];
}

// ---------------- launch ----------------------------------------------------
extern "C" void kernel_launch(void* const* d_in, const int* in_sizes, int n_in,
                              void* d_out, int out_size)
{
    const float* Y    = (const float*)d_in[0];
    const float* X    = (const float*)d_in[1];
    const float* WU_d = (const float*)d_in[2];
    const float* v_d  = (const float*)d_in[3];
    const float* Wl   = (const float*)d_in[4];
    const float* W_ih = (const float*)d_in[5];
    const float* W_hh = (const float*)d_in[6];
    const float* b_ih = (const float*)d_in[7];
    const float* b_hh = (const float*)d_in[8];
    const float* Wb_w = (const float*)d_in[9];
    const float* Wb_b = (const float*)d_in[10];
    const float* vb_w = (const float*)d_in[11];
    const float* vb_b = (const float*)d_in[12];
    float* out = (float*)d_out;

    float *pA, *pU, *pHC, *pGATES;
    cudaGetSymbolAddress((void**)&pA,     g_A);
    cudaGetSymbolAddress((void**)&pU,     g_U);
    cudaGetSymbolAddress((void**)&pHC,    g_HC);
    cudaGetSymbolAddress((void**)&pGATES, g_GATES);

    // init h, c = 0
    init_hc_kernel<<<(B_SZ * 2 * P_SZ + 255) / 256, 256>>>();

    // precompute A[(t,b),m'] = X[(t,b),:] @ WU_dx^T  (WU_dx = WU_d cols 512..767)
    gemm_nt<64, 64, 16, 4, 4><<<dim3((T_SZ * B_SZ) / 64, M_SZ / 64), 256>>>(
        X, M_SZ, WU_d + 512, 2 * P_SZ + M_SZ, pA, M_SZ, M_SZ);

    for (int t = 0; t < TS; t++) {
        // u = [h,c] @ WU_dd^T   (1024x512 @ 512x256)
        gemm_nt<64, 32, 16, 4, 2><<<dim3(B_SZ / 64, M_SZ / 32), 256>>>(
            pHC, 2 * P_SZ, WU_d, 2 * P_SZ + M_SZ, pU, M_SZ, 2 * P_SZ);

        // gates_hh = h @ W_hh^T (1024x256 @ 256x1024); independent of attn
        gemm_nt<64, 64, 16, 4, 4><<<dim3(B_SZ / 64, (4 * P_SZ) / 64), 256>>>(
            pHC, 2 * P_SZ, W_hh, P_SZ, pGATES, 4 * P_SZ, P_SZ);

        // attention: logits, softmax, ctx, y_tilde
        attn_step_kernel<<<B_SZ, 256>>>(X, v_d, Wl, Y, t);

        // LSTM pointwise update of h, c
        lstm_step_kernel<<<B_SZ, 256>>>(W_ih, b_ih, b_hh);
    }

    final_head_kernel<<<B_SZ, 256>>>(Wb_w, Wb_b, vb_w, vb_b, out);
}

// round 2
// speedup vs baseline: 1.1130x; 1.1130x over previous
#include <cuda_runtime.h>
#include <cuda_fp16.h>
#include <cstdint>
#include <cstddef>

#define B_SZ 1024
#define T_SZ 128
#define M_SZ 256
#define P_SZ 256
#define TS   127   // T-1 recurrence steps

// ---------------- scratch (static device globals; no runtime allocation) ----
__device__ __half g_Ah[(size_t)T_SZ * B_SZ * M_SZ];  // (t,b,m') x-part preact, fp16, 67MB
__device__ __half g_Xh[(size_t)T_SZ * B_SZ * M_SZ];  // fp16 copy of X, 67MB
__device__ float  g_U[B_SZ * M_SZ];                  // per-step d-part preactivation
__device__ float  g_HC[B_SZ * 2 * P_SZ];             // [h | c] per batch
__device__ float  g_CTX[B_SZ * M_SZ];                // attention context
__device__ float  g_GATES[B_SZ * 4 * P_SZ];          // h @ W_hh^T

// ---------------- init ------------------------------------------------------
__global__ void init_hc_kernel() {
    int i = blockIdx.x * blockDim.x + threadIdx.x;
    if (i < B_SZ * 2 * P_SZ) g_HC[i] = 0.0f;
}

// ---------------- X -> fp16 copy -------------------------------------------
__global__ void convert_x_kernel(const float* __restrict__ X) {
    size_t i = ((size_t)blockIdx.x * blockDim.x + threadIdx.x) * 4;
    float4 v = *(const float4*)(X + i);
    __half2* dst = (__half2*)(g_Xh + i);
    dst[0] = __floats2half2_rn(v.x, v.y);
    dst[1] = __floats2half2_rn(v.z, v.w);
}

// ---------------- generic NT GEMM: C[m][n] = sum_k A[m*lda+k]*B[n*ldb+k] ----
// OUT_HALF=true packs the epilogue to __half (requires TN==4).
template<int BM, int BN, int BK, int TM, int TN, bool OUT_HALF>
__global__ void gemm_nt(const float* __restrict__ A, int lda,
                        const float* __restrict__ Bm, int ldb,
                        void* __restrict__ Cv, int ldc, int K)
{
    constexpr int THREADS = (BM / TM) * (BN / TN);
    __shared__ float As[BK][BM + 4];
    __shared__ float Bs[BK][BN + 4];

    const int tid = threadIdx.x;
    const int tx = tid % (BN / TN);
    const int ty = tid / (BN / TN);

    const float* Ab = A  + (size_t)blockIdx.x * BM * lda;
    const float* Bb = Bm + (size_t)blockIdx.y * BN * ldb;

    float acc[TM][TN];
#pragma unroll
    for (int i = 0; i < TM; i++)
#pragma unroll
        for (int j = 0; j < TN; j++) acc[i][j] = 0.0f;

    for (int k0 = 0; k0 < K; k0 += BK) {
#pragma unroll
        for (int i = tid; i < BM * (BK / 4); i += THREADS) {
            int m  = i / (BK / 4);
            int k4 = (i % (BK / 4)) * 4;
            float4 v = *(const float4*)(Ab + (size_t)m * lda + k0 + k4);
            As[k4 + 0][m] = v.x; As[k4 + 1][m] = v.y;
            As[k4 + 2][m] = v.z; As[k4 + 3][m] = v.w;
        }
#pragma unroll
        for (int i = tid; i < BN * (BK / 4); i += THREADS) {
            int n  = i / (BK / 4);
            int k4 = (i % (BK / 4)) * 4;
            float4 v = *(const float4*)(Bb + (size_t)n * ldb + k0 + k4);
            Bs[k4 + 0][n] = v.x; Bs[k4 + 1][n] = v.y;
            Bs[k4 + 2][n] = v.z; Bs[k4 + 3][n] = v.w;
        }
        __syncthreads();

#pragma unroll
        for (int kk = 0; kk < BK; kk++) {
            float a[TM], b[TN];
#pragma unroll
            for (int i = 0; i < TM; i++) a[i] = As[kk][ty * TM + i];
#pragma unroll
            for (int j = 0; j < TN; j++) b[j] = Bs[kk][tx * TN + j];
#pragma unroll
            for (int i = 0; i < TM; i++)
#pragma unroll
                for (int j = 0; j < TN; j++)
                    acc[i][j] = fmaf(a[i], b[j], acc[i][j]);
        }
        __syncthreads();
    }

    if (OUT_HALF) {
#pragma unroll
        for (int i = 0; i < TM; i++) {
            __half2* crow = (__half2*)((__half*)Cv
                + (size_t)(blockIdx.x * BM + ty * TM + i) * ldc
                + blockIdx.y * BN + tx * TN);
            crow[0] = __floats2half2_rn(acc[i][0], acc[i][1]);
            crow[1] = __floats2half2_rn(acc[i][2], acc[i][3]);
        }
    } else {
#pragma unroll
        for (int i = 0; i < TM; i++)
#pragma unroll
            for (int j = 0; j < TN; j++)
                ((float*)Cv)[(size_t)(blockIdx.x * BM + ty * TM + i) * ldc
                             + blockIdx.y * BN + tx * TN + j] = acc[i][j];
    }
}

// ---------------- per-step combined GEMM: U and GATES in one launch ---------
// grid = (16, 20): by 0..3 -> U = HC @ WU_dd^T   (K=512, N=256)
//                  by 4..19 -> GATES = h @ W_hh^T (K=256, N=1024)
__global__ void step_gemm_kernel(const float* __restrict__ WU_d,
                                 const float* __restrict__ W_hh)
{
    constexpr int BM = 64, BN = 64, BK = 16, TM = 4, TN = 4;
    constexpr int THREADS = 256;
    __shared__ float As[BK][BM + 4];
    __shared__ float Bs[BK][BN + 4];

    const bool isU = (blockIdx.y < 4);
    const float* Bm; int ldb, K, ldc, ncol; float* C;
    if (isU) { Bm = WU_d; ldb = 768; K = 512; C = g_U;     ldc = 256;  ncol = blockIdx.y; }
    else     { Bm = W_hh; ldb = 256; K = 256; C = g_GATES; ldc = 1024; ncol = blockIdx.y - 4; }

    const int tid = threadIdx.x;
    const int tx = tid % (BN / TN);
    const int ty = tid / (BN / TN);

    const float* Ab = g_HC + (size_t)blockIdx.x * BM * 512;
    const float* Bb = Bm + (size_t)ncol * BN * ldb;

    float acc[TM][TN];
#pragma unroll
    for (int i = 0; i < TM; i++)
#pragma unroll
        for (int j = 0; j < TN; j++) acc[i][j] = 0.0f;

    for (int k0 = 0; k0 < K; k0 += BK) {
        {   // A tile: 64x16 -> 256 float4 loads, 1 per thread
            int m  = tid / (BK / 4);
            int k4 = (tid % (BK / 4)) * 4;
            float4 v = *(const float4*)(Ab + (size_t)m * 512 + k0 + k4);
            As[k4 + 0][m] = v.x; As[k4 + 1][m] = v.y;
            As[k4 + 2][m] = v.z; As[k4 + 3][m] = v.w;
        }
        {   // B tile
            int n  = tid / (BK / 4);
            int k4 = (tid % (BK / 4)) * 4;
            float4 v = *(const float4*)(Bb + (size_t)n * ldb + k0 + k4);
            Bs[k4 + 0][n] = v.x; Bs[k4 + 1][n] = v.y;
            Bs[k4 + 2][n] = v.z; Bs[k4 + 3][n] = v.w;
        }
        __syncthreads();

#pragma unroll
        for (int kk = 0; kk < BK; kk++) {
            float a[TM], b[TN];
#pragma unroll
            for (int i = 0; i < TM; i++) a[i] = As[kk][ty * TM + i];
#pragma unroll
            for (int j = 0; j < TN; j++) b[j] = Bs[kk][tx * TN + j];
#pragma unroll
            for (int i = 0; i < TM; i++)
#pragma unroll
                for (int j = 0; j < TN; j++)
                    acc[i][j] = fmaf(a[i], b[j], acc[i][j]);
        }
        __syncthreads();
    }

#pragma unroll
    for (int i = 0; i < TM; i++)
#pragma unroll
        for (int j = 0; j < TN; j++)
            C[(size_t)(blockIdx.x * BM + ty * TM + i) * ldc
              + ncol * BN + tx * TN + j] = acc[i][j];
}

// ---------------- fused attention + LSTM step -------------------------------
// one block per batch, 256 threads (8 warps)
__global__ void attn_lstm_kernel(const float* __restrict__ v_d,
                                 const float* __restrict__ Wl,
                                 const float* __restrict__ Y,
                                 const float* __restrict__ W_ih,
                                 const float* __restrict__ b_ih,
                                 const float* __restrict__ b_hh,
                                 int t_step)
{
    const int b    = blockIdx.x;
    const int tid  = threadIdx.x;     // 0..255
    const int lane = tid & 31;
    const int warp = tid >> 5;

    __shared__ float u_s[M_SZ], v_s[M_SZ];
    __shared__ float l_s[T_SZ], beta_s[T_SZ];
    __shared__ float redm[8], redsum[8], redy[8];
    __shared__ float yt_s;

    u_s[tid] = g_U[b * M_SZ + tid];
    v_s[tid] = v_d[tid];
    __syncthreads();

    // phase 1: logits l[t] = sum_m v[m] * tanh(u[m] + A[t,b,m]); A in fp16
    for (int t = warp; t < T_SZ; t += 8) {
        const float4 raw = __ldg((const float4*)(g_Ah + ((size_t)t * B_SZ + b) * M_SZ) + lane);
        const __half2* hp = (const __half2*)&raw;   // 8 halves: m = lane*8 .. lane*8+7
        float acc = 0.0f;
#pragma unroll
        for (int j = 0; j < 4; j++) {
            float2 av = __half22float2(hp[j]);
            int m = lane * 8 + 2 * j;
            float x0 = u_s[m]     + av.x;
            float x1 = u_s[m + 1] + av.y;
            float t0, t1;
            asm("tanh.approx.f32 %0, %1;" : "=f"(t0) : "f"(x0));
            asm("tanh.approx.f32 %0, %1;" : "=f"(t1) : "f"(x1));
            acc = fmaf(v_s[m], t0, acc);
            acc = fmaf(v_s[m + 1], t1, acc);
        }
#pragma unroll
        for (int o = 16; o; o >>= 1) acc += __shfl_xor_sync(0xffffffffu, acc, o);
        if (lane == 0) l_s[t] = acc;
    }
    __syncthreads();

    // phase 2: softmax over T=128 logits
    float lv = (tid < T_SZ) ? l_s[tid] : -1e30f;
    float mx = lv;
#pragma unroll
    for (int o = 16; o; o >>= 1) mx = fmaxf(mx, __shfl_xor_sync(0xffffffffu, mx, o));
    if (lane == 0) redm[warp] = mx;
    __syncthreads();
    mx = redm[0];
#pragma unroll
    for (int w = 1; w < 8; w++) mx = fmaxf(mx, redm[w]);

    float e = (tid < T_SZ) ? expf(lv - mx) : 0.0f;
    float sm = e;
#pragma unroll
    for (int o = 16; o; o >>= 1) sm += __shfl_xor_sync(0xffffffffu, sm, o);
    if (lane == 0) redsum[warp] = sm;
    __syncthreads();
    sm = redsum[0] + redsum[1] + redsum[2] + redsum[3]
       + redsum[4] + redsum[5] + redsum[6] + redsum[7];
    if (tid < T_SZ) beta_s[tid] = e / sm;
    __syncthreads();

    // phase 3: ctx[m] = sum_t beta[t] * X[t,b,m]  (X in fp16; thread = m)
    float c = 0.0f;
    const __half* Xb = g_Xh + (size_t)b * M_SZ + tid;
#pragma unroll 4
    for (int t = 0; t < T_SZ; t++)
        c = fmaf(beta_s[t], __half2float(__ldg(Xb + (size_t)t * B_SZ * M_SZ)), c);
    g_CTX[b * M_SZ + tid] = c;

    // phase 4: y_tilde = Wl[0]*y_t + sum_m Wl[1+m]*ctx[m]
    float yv = Wl[1 + tid] * c;
#pragma unroll
    for (int o = 16; o; o >>= 1) yv += __shfl_xor_sync(0xffffffffu, yv, o);
    if (lane == 0) redy[warp] = yv;
    __syncthreads();
    if (tid == 0) {
        float s = redy[0] + redy[1] + redy[2] + redy[3]
                + redy[4] + redy[5] + redy[6] + redy[7];
        yt_s = fmaf(Wl[0], Y[(size_t)b * TS + t_step], s);
    }
    __syncthreads();

    // phase 5: fused LSTM pointwise update (gates_hh precomputed in g_GATES)
    const float yt = yt_s;
    const int p = tid;
    const float* gr = g_GATES + (size_t)b * 4 * P_SZ;
    float ig = gr[p]            + yt * W_ih[p]            + b_ih[p]            + b_hh[p];
    float fg = gr[P_SZ + p]     + yt * W_ih[P_SZ + p]     + b_ih[P_SZ + p]     + b_hh[P_SZ + p];
    float gg = gr[2 * P_SZ + p] + yt * W_ih[2 * P_SZ + p] + b_ih[2 * P_SZ + p] + b_hh[2 * P_SZ + p];
    float og = gr[3 * P_SZ + p] + yt * W_ih[3 * P_SZ + p] + b_ih[3 * P_SZ + p] + b_hh[3 * P_SZ + p];

    float cold = g_HC[(size_t)b * 2 * P_SZ + P_SZ + p];
    float si = 1.0f / (1.0f + expf(-ig));
    float sf = 1.0f / (1.0f + expf(-fg));
    float so = 1.0f / (1.0f + expf(-og));
    float cn = sf * cold + si * tanhf(gg);
    float hn = so * tanhf(cn);

    g_HC[(size_t)b * 2 * P_SZ + p]        = hn;
    g_HC[(size_t)b * 2 * P_SZ + P_SZ + p] = cn;
}

// ---------------- final head: out = ([h,ctx] @ Wb^T + b) @ vb^T + vb_b -----
__global__ void final_head_kernel(const float* __restrict__ Wb_w,
                                  const float* __restrict__ Wb_b,
                                  const float* __restrict__ vb_w,
                                  const float* __restrict__ vb_b,
                                  float* __restrict__ out)
{
    const int b   = blockIdx.x;
    const int tid = threadIdx.x;  // 0..255 = p
    __shared__ float hc_s[2 * P_SZ];
    __shared__ float red[8];

    hc_s[tid]        = g_HC[(size_t)b * 2 * P_SZ + tid];   // h
    hc_s[P_SZ + tid] = g_CTX[(size_t)b * M_SZ + tid];      // ctx
    __syncthreads();

    const float* wr = Wb_w + (size_t)tid * (P_SZ + M_SZ);
    float t = Wb_b[tid];
#pragma unroll 4
    for (int k = 0; k < 2 * P_SZ; k++)
        t = fmaf(wr[k], hc_s[k], t);
    float val = vb_w[tid] * t;

    int lane = tid & 31, warp = tid >> 5;
#pragma unroll
    for (int o = 16; o; o >>= 1) val += __shfl_xor_sync(0xffffffffu, val, o);
    if (lane == 0) red[warp] = val;
    __syncthreads();
    if (tid == 0)
        out[b] = vb_b[0] + red[0] + red[1] + red[2] + red[3]
                         + red[4] + red[5] + red[6] + red[7];
}

// ---------------- launch ----------------------------------------------------
extern "C" void kernel_launch(void* const* d_in, const int* in_sizes, int n_in,
                              void* d_out, int out_size)
{
    const float* Y    = (const float*)d_in[0];
    const float* X    = (const float*)d_in[1];
    const float* WU_d = (const float*)d_in[2];
    const float* v_d  = (const float*)d_in[3];
    const float* Wl   = (const float*)d_in[4];
    const float* W_ih = (const float*)d_in[5];
    const float* W_hh = (const float*)d_in[6];
    const float* b_ih = (const float*)d_in[7];
    const float* b_hh = (const float*)d_in[8];
    const float* Wb_w = (const float*)d_in[9];
    const float* Wb_b = (const float*)d_in[10];
    const float* vb_w = (const float*)d_in[11];
    const float* vb_b = (const float*)d_in[12];
    float* out = (float*)d_out;

    void* pAh;
    cudaGetSymbolAddress(&pAh, g_Ah);

    // init h, c = 0
    init_hc_kernel<<<(B_SZ * 2 * P_SZ + 255) / 256, 256>>>();

    // X -> fp16 copy (for ctx phase)
    convert_x_kernel<<<(T_SZ * B_SZ * M_SZ / 4) / 256, 256>>>(X);

    // precompute A[(t,b),m'] = X[(t,b),:] @ WU_dx^T  -> fp16 (WU_dx = cols 512..767)
    gemm_nt<128, 64, 16, 8, 4, true><<<dim3((T_SZ * B_SZ) / 128, M_SZ / 64), 256>>>(
        X, M_SZ, WU_d + 512, 2 * P_SZ + M_SZ, pAh, M_SZ, M_SZ);

    for (int t = 0; t < TS; t++) {
        // one launch: U = [h,c] @ WU_dd^T  AND  GATES = h @ W_hh^T
        step_gemm_kernel<<<dim3(B_SZ / 64, 20), 256>>>(WU_d, W_hh);

        // attention + softmax + ctx + y_tilde + fused LSTM update
        attn_lstm_kernel<<<B_SZ, 256>>>(v_d, Wl, Y, W_ih, b_ih, b_hh, t);
    }

    final_head_kernel<<<B_SZ, 256>>>(Wb_w, Wb_b, vb_w, vb_b, out);
}

// round 3
// speedup vs baseline: 1.2839x; 1.1536x over previous
#include <cuda_runtime.h>
#include <cuda_fp16.h>
#include <cstdint>
#include <cstddef>

#define B_SZ 1024
#define T_SZ 128
#define M_SZ 256
#define P_SZ 256
#define TS   127   // T-1 recurrence steps

// ---------------- scratch (static device globals) ---------------------------
__device__ __half g_Ah[(size_t)B_SZ * T_SZ * M_SZ];  // (b,t,m) x-part preact fp16
__device__ __half g_Xt[(size_t)B_SZ * M_SZ * T_SZ];  // (b,m,t) fp16 transposed X
__device__ float  g_U1[B_SZ * M_SZ];                 // d-part preact, K-half 1
__device__ float  g_U2[B_SZ * M_SZ];                 // d-part preact, K-half 2
__device__ float  g_HC[B_SZ * 2 * P_SZ];             // [h | c] per batch
__device__ float  g_CTX[B_SZ * M_SZ];                // attention context
__device__ float  g_GATES[B_SZ * 4 * P_SZ];          // h @ W_hh^T

// ---------------- init ------------------------------------------------------
__global__ void init_hc_kernel() {
    int i = blockIdx.x * blockDim.x + threadIdx.x;
    if (i < B_SZ * 2 * P_SZ) g_HC[i] = 0.0f;
}

// ---------------- X (T,B,M) fp32 -> g_Xt (b,m,t) fp16 -----------------------
// grid (B, M/32), 256 threads
__global__ void transpose_x_kernel(const float* __restrict__ X) {
    __shared__ __half s[32][130];
    const int b  = blockIdx.x;
    const int m0 = blockIdx.y * 32;
    const int tid = threadIdx.x;

    // load: t-major, mi fast (coalesced 128B per warp)
#pragma unroll
    for (int it = 0; it < 16; it++) {
        int idx = tid + it * 256;           // 0 .. 4095
        int t  = idx >> 5;
        int mi = idx & 31;
        float v = __ldg(X + (size_t)t * B_SZ * M_SZ + (size_t)b * M_SZ + m0 + mi);
        s[mi][t] = __float2half_rn(v);
    }
    __syncthreads();

    // store: each thread writes 8 consecutive t's (16B)
#pragma unroll
    for (int it = 0; it < 2; it++) {
        int idx = tid + it * 256;           // 0 .. 511
        int mi = idx >> 4;
        int tc = idx & 15;
        const uint32_t* sp = (const uint32_t*)&s[mi][tc * 8];
        uint4 val = make_uint4(sp[0], sp[1], sp[2], sp[3]);
        *(uint4*)(g_Xt + ((size_t)b * M_SZ + m0 + mi) * T_SZ + tc * 8) = val;
    }
}

// ---------------- precompute A[b,t,m'] = X[t,b,:] @ WU_dx^T -> fp16 ---------
// BM=128 covers exactly t=0..127 for batch b = blockIdx.x. grid (B, 4), 256 thr
__global__ void precompute_A_kernel(const float* __restrict__ X,
                                    const float* __restrict__ W)   // WU_d + 512
{
    constexpr int BM = 128, BN = 64, BK = 16, TM = 8, TN = 4;
    __shared__ float As[BK][BM + 4];
    __shared__ float Bs[BK][BN + 4];

    const int tid = threadIdx.x;
    const int tx = tid % (BN / TN);   // 0..15
    const int ty = tid / (BN / TN);   // 0..15
    const int b  = blockIdx.x;

    const float* Bb = W + (size_t)blockIdx.y * BN * 768;

    float acc[TM][TN];
#pragma unroll
    for (int i = 0; i < TM; i++)
#pragma unroll
        for (int j = 0; j < TN; j++) acc[i][j] = 0.0f;

    for (int k0 = 0; k0 < M_SZ; k0 += BK) {
        // A tile: rows m = t (0..127), X row = t*B + b
#pragma unroll
        for (int i = tid; i < BM * (BK / 4); i += 256) {
            int m  = i / (BK / 4);
            int k4 = (i % (BK / 4)) * 4;
            float4 v = *(const float4*)(X + ((size_t)m * B_SZ + b) * M_SZ + k0 + k4);
            As[k4 + 0][m] = v.x; As[k4 + 1][m] = v.y;
            As[k4 + 2][m] = v.z; As[k4 + 3][m] = v.w;
        }
        {
            int n  = tid / (BK / 4);
            int k4 = (tid % (BK / 4)) * 4;
            float4 v = *(const float4*)(Bb + (size_t)n * 768 + k0 + k4);
            Bs[k4 + 0][n] = v.x; Bs[k4 + 1][n] = v.y;
            Bs[k4 + 2][n] = v.z; Bs[k4 + 3][n] = v.w;
        }
        __syncthreads();

#pragma unroll
        for (int kk = 0; kk < BK; kk++) {
            float a[TM], bb[TN];
#pragma unroll
            for (int i = 0; i < TM; i++) a[i] = As[kk][ty * TM + i];
#pragma unroll
            for (int j = 0; j < TN; j++) bb[j] = Bs[kk][tx * TN + j];
#pragma unroll
            for (int i = 0; i < TM; i++)
#pragma unroll
                for (int j = 0; j < TN; j++)
                    acc[i][j] = fmaf(a[i], bb[j], acc[i][j]);
        }
        __syncthreads();
    }

#pragma unroll
    for (int i = 0; i < TM; i++) {
        __half2* crow = (__half2*)(g_Ah
            + ((size_t)b * T_SZ + ty * TM + i) * M_SZ
            + blockIdx.y * BN + tx * TN);
        crow[0] = __floats2half2_rn(acc[i][0], acc[i][1]);
        crow[1] = __floats2half2_rn(acc[i][2], acc[i][3]);
    }
}

// ---------------- per-step GEMMs: U1, U2, GATES, uniform K=256 ---------------
// grid (32, 24): y 0..3 -> U1 (HC[:, :256] @ WU_dd[:, :256]^T)
//                y 4..7 -> U2 (HC[:, 256:] @ WU_dd[:, 256:]^T)
//                y 8..23 -> GATES (h @ W_hh^T)
__global__ void step_gemm_kernel(const float* __restrict__ WU_d,
                                 const float* __restrict__ W_hh)
{
    constexpr int BK = 16;
    __shared__ float As[BK][36];   // 32 + 4
    __shared__ float Bs[BK][68];   // 64 + 4

    const int tid = threadIdx.x;
    const int tx = tid & 15;       // col group (TN=4)
    const int ty = tid >> 4;       // row group (TM=2)
    const int y  = blockIdx.y;

    const float* Bw; int ldb, koff, ncol, ldc; float* C;
    if (y < 4)       { C = g_U1;    ldc = 256;  ncol = y;     Bw = WU_d; ldb = 768; koff = 0;   }
    else if (y < 8)  { C = g_U2;    ldc = 256;  ncol = y - 4; Bw = WU_d; ldb = 768; koff = 256; }
    else             { C = g_GATES; ldc = 1024; ncol = y - 8; Bw = W_hh; ldb = 256; koff = 0;   }

    const float* Ab = g_HC + (size_t)blockIdx.x * 32 * 512 + koff;
    const float* Bb = Bw + (size_t)ncol * 64 * ldb + koff;

    float acc[2][4] = {{0, 0, 0, 0}, {0, 0, 0, 0}};

    for (int k0 = 0; k0 < 256; k0 += BK) {
        if (tid < 128) {
            int m  = tid >> 2;
            int k4 = (tid & 3) * 4;
            float4 v = *(const float4*)(Ab + (size_t)m * 512 + k0 + k4);
            As[k4 + 0][m] = v.x; As[k4 + 1][m] = v.y;
            As[k4 + 2][m] = v.z; As[k4 + 3][m] = v.w;
        }
        {
            int n  = tid >> 2;
            int k4 = (tid & 3) * 4;
            float4 v = *(const float4*)(Bb + (size_t)n * ldb + k0 + k4);
            Bs[k4 + 0][n] = v.x; Bs[k4 + 1][n] = v.y;
            Bs[k4 + 2][n] = v.z; Bs[k4 + 3][n] = v.w;
        }
        __syncthreads();

#pragma unroll
        for (int kk = 0; kk < BK; kk++) {
            float2 a  = *(const float2*)&As[kk][ty * 2];
            float4 bv = *(const float4*)&Bs[kk][tx * 4];
            acc[0][0] = fmaf(a.x, bv.x, acc[0][0]);
            acc[0][1] = fmaf(a.x, bv.y, acc[0][1]);
            acc[0][2] = fmaf(a.x, bv.z, acc[0][2]);
            acc[0][3] = fmaf(a.x, bv.w, acc[0][3]);
            acc[1][0] = fmaf(a.y, bv.x, acc[1][0]);
            acc[1][1] = fmaf(a.y, bv.y, acc[1][1]);
            acc[1][2] = fmaf(a.y, bv.z, acc[1][2]);
            acc[1][3] = fmaf(a.y, bv.w, acc[1][3]);
        }
        __syncthreads();
    }

    const int row0 = blockIdx.x * 32 + ty * 2;
    const int col0 = ncol * 64 + tx * 4;
#pragma unroll
    for (int i = 0; i < 2; i++)
        *(float4*)(C + (size_t)(row0 + i) * ldc + col0) =
            make_float4(acc[i][0], acc[i][1], acc[i][2], acc[i][3]);
}

// ---------------- fused attention + LSTM step -------------------------------
// one block per batch, 256 threads (8 warps)
__global__ void attn_lstm_kernel(const float* __restrict__ v_d,
                                 const float* __restrict__ Wl,
                                 const float* __restrict__ Y,
                                 const float* __restrict__ W_ih,
                                 const float* __restrict__ b_ih,
                                 const float* __restrict__ b_hh,
                                 int t_step)
{
    const int b    = blockIdx.x;
    const int tid  = threadIdx.x;     // 0..255
    const int lane = tid & 31;
    const int warp = tid >> 5;

    __shared__ float l_s[T_SZ], beta_s[T_SZ];
    __shared__ float redm[8], redsum[8], redy[8];
    __shared__ float yt_s;

    // per-lane u,v slices in registers (m = lane*8 .. lane*8+7), reused 16x
    float ureg[8], vreg[8];
    {
        const int mb = lane * 8;
        float4 u1a = __ldg((const float4*)(g_U1 + b * M_SZ + mb));
        float4 u1b = __ldg((const float4*)(g_U1 + b * M_SZ + mb + 4));
        float4 u2a = __ldg((const float4*)(g_U2 + b * M_SZ + mb));
        float4 u2b = __ldg((const float4*)(g_U2 + b * M_SZ + mb + 4));
        float4 va  = __ldg((const float4*)(v_d + mb));
        float4 vb  = __ldg((const float4*)(v_d + mb + 4));
        ureg[0] = u1a.x + u2a.x; ureg[1] = u1a.y + u2a.y;
        ureg[2] = u1a.z + u2a.z; ureg[3] = u1a.w + u2a.w;
        ureg[4] = u1b.x + u2b.x; ureg[5] = u1b.y + u2b.y;
        ureg[6] = u1b.z + u2b.z; ureg[7] = u1b.w + u2b.w;
        vreg[0] = va.x; vreg[1] = va.y; vreg[2] = va.z; vreg[3] = va.w;
        vreg[4] = vb.x; vreg[5] = vb.y; vreg[6] = vb.z; vreg[7] = vb.w;
    }

    // phase 1: logits l[t] = sum_m v[m] * tanh(u[m] + A[b,t,m]); no smem inner
    const __half* Abase = g_Ah + (size_t)b * T_SZ * M_SZ;
#pragma unroll 2
    for (int t = warp; t < T_SZ; t += 8) {
        const float4 raw = __ldg((const float4*)(Abase + (size_t)t * M_SZ) + lane);
        const __half2* hp = (const __half2*)&raw;   // m = lane*8 .. lane*8+7
        float acc = 0.0f;
#pragma unroll
        for (int j = 0; j < 4; j++) {
            float2 av = __half22float2(hp[j]);
            float x0 = ureg[2 * j]     + av.x;
            float x1 = ureg[2 * j + 1] + av.y;
            float t0, t1;
            asm("tanh.approx.f32 %0, %1;" : "=f"(t0) : "f"(x0));
            asm("tanh.approx.f32 %0, %1;" : "=f"(t1) : "f"(x1));
            acc = fmaf(vreg[2 * j],     t0, acc);
            acc = fmaf(vreg[2 * j + 1], t1, acc);
        }
#pragma unroll
        for (int o = 16; o; o >>= 1) acc += __shfl_xor_sync(0xffffffffu, acc, o);
        if (lane == 0) l_s[t] = acc;
    }
    __syncthreads();

    // phase 2: softmax over T=128 logits
    float lv = (tid < T_SZ) ? l_s[tid] : -1e30f;
    float mx = lv;
#pragma unroll
    for (int o = 16; o; o >>= 1) mx = fmaxf(mx, __shfl_xor_sync(0xffffffffu, mx, o));
    if (lane == 0) redm[warp] = mx;
    __syncthreads();
    mx = redm[0];
#pragma unroll
    for (int w = 1; w < 8; w++) mx = fmaxf(mx, redm[w]);

    float e = (tid < T_SZ) ? expf(lv - mx) : 0.0f;
    float sm = e;
#pragma unroll
    for (int o = 16; o; o >>= 1) sm += __shfl_xor_sync(0xffffffffu, sm, o);
    if (lane == 0) redsum[warp] = sm;
    __syncthreads();
    sm = redsum[0] + redsum[1] + redsum[2] + redsum[3]
       + redsum[4] + redsum[5] + redsum[6] + redsum[7];
    if (tid < T_SZ) beta_s[tid] = e / sm;
    __syncthreads();

    // phase 3: ctx[m] = sum_t beta[t] * X[b,m,t]  (contiguous t per thread)
    float c = 0.0f;
    {
        const uint4* Xb = (const uint4*)(g_Xt + ((size_t)b * M_SZ + tid) * T_SZ);
#pragma unroll
        for (int j = 0; j < 16; j++) {
            uint4 raw = __ldg(Xb + j);
            const __half2* hp = (const __half2*)&raw;
#pragma unroll
            for (int q = 0; q < 4; q++) {
                float2 xv = __half22float2(hp[q]);
                c = fmaf(beta_s[j * 8 + 2 * q],     xv.x, c);
                c = fmaf(beta_s[j * 8 + 2 * q + 1], xv.y, c);
            }
        }
    }
    g_CTX[b * M_SZ + tid] = c;

    // phase 4: y_tilde = Wl[0]*y_t + sum_m Wl[1+m]*ctx[m]
    float yv = __ldg(Wl + 1 + tid) * c;
#pragma unroll
    for (int o = 16; o; o >>= 1) yv += __shfl_xor_sync(0xffffffffu, yv, o);
    if (lane == 0) redy[warp] = yv;
    __syncthreads();
    if (tid == 0) {
        float s = redy[0] + redy[1] + redy[2] + redy[3]
                + redy[4] + redy[5] + redy[6] + redy[7];
        yt_s = fmaf(__ldg(Wl), Y[(size_t)b * TS + t_step], s);
    }
    __syncthreads();

    // phase 5: fused LSTM pointwise update
    const float yt = yt_s;
    const int p = tid;
    const float* gr = g_GATES + (size_t)b * 4 * P_SZ;
    float ig = gr[p]            + yt * __ldg(W_ih + p)            + __ldg(b_ih + p)            + __ldg(b_hh + p);
    float fg = gr[P_SZ + p]     + yt * __ldg(W_ih + P_SZ + p)     + __ldg(b_ih + P_SZ + p)     + __ldg(b_hh + P_SZ + p);
    float gg = gr[2 * P_SZ + p] + yt * __ldg(W_ih + 2 * P_SZ + p) + __ldg(b_ih + 2 * P_SZ + p) + __ldg(b_hh + 2 * P_SZ + p);
    float og = gr[3 * P_SZ + p] + yt * __ldg(W_ih + 3 * P_SZ + p) + __ldg(b_ih + 3 * P_SZ + p) + __ldg(b_hh + 3 * P_SZ + p);

    float cold = g_HC[(size_t)b * 2 * P_SZ + P_SZ + p];
    float si = 1.0f / (1.0f + expf(-ig));
    float sf = 1.0f / (1.0f + expf(-fg));
    float so = 1.0f / (1.0f + expf(-og));
    float cn = sf * cold + si * tanhf(gg);
    float hn = so * tanhf(cn);

    g_HC[(size_t)b * 2 * P_SZ + p]        = hn;
    g_HC[(size_t)b * 2 * P_SZ + P_SZ + p] = cn;
}

// ---------------- final head: out = ([h,ctx] @ Wb^T + b) @ vb^T + vb_b -----
__global__ void final_head_kernel(const float* __restrict__ Wb_w,
                                  const float* __restrict__ Wb_b,
                                  const float* __restrict__ vb_w,
                                  const float* __restrict__ vb_b,
                                  float* __restrict__ out)
{
    const int b   = blockIdx.x;
    const int tid = threadIdx.x;  // 0..255 = p
    __shared__ float hc_s[2 * P_SZ];
    __shared__ float red[8];

    hc_s[tid]        = g_HC[(size_t)b * 2 * P_SZ + tid];   // h
    hc_s[P_SZ + tid] = g_CTX[(size_t)b * M_SZ + tid];      // ctx
    __syncthreads();

    const float* wr = Wb_w + (size_t)tid * (P_SZ + M_SZ);
    float t = __ldg(Wb_b + tid);
#pragma unroll 4
    for (int k = 0; k < 2 * P_SZ; k++)
        t = fmaf(__ldg(wr + k), hc_s[k], t);
    float val = __ldg(vb_w + tid) * t;

    int lane = tid & 31, warp = tid >> 5;
#pragma unroll
    for (int o = 16; o; o >>= 1) val += __shfl_xor_sync(0xffffffffu, val, o);
    if (lane == 0) red[warp] = val;
    __syncthreads();
    if (tid == 0)
        out[b] = vb_b[0] + red[0] + red[1] + red[2] + red[3]
                         + red[4] + red[5] + red[6] + red[7];
}

// ---------------- launch ----------------------------------------------------
extern "C" void kernel_launch(void* const* d_in, const int* in_sizes, int n_in,
                              void* d_out, int out_size)
{
    const float* Y    = (const float*)d_in[0];
    const float* X    = (const float*)d_in[1];
    const float* WU_d = (const float*)d_in[2];
    const float* v_d  = (const float*)d_in[3];
    const float* Wl   = (const float*)d_in[4];
    const float* W_ih = (const float*)d_in[5];
    const float* W_hh = (const float*)d_in[6];
    const float* b_ih = (const float*)d_in[7];
    const float* b_hh = (const float*)d_in[8];
    const float* Wb_w = (const float*)d_in[9];
    const float* Wb_b = (const float*)d_in[10];
    const float* vb_w = (const float*)d_in[11];
    const float* vb_b = (const float*)d_in[12];
    float* out = (float*)d_out;

    // init h, c = 0
    init_hc_kernel<<<(B_SZ * 2 * P_SZ + 255) / 256, 256>>>();

    // X -> (b,m,t) fp16
    transpose_x_kernel<<<dim3(B_SZ, M_SZ / 32), 256>>>(X);

    // A[b,t,m'] = X[t,b,:] @ WU_dx^T -> fp16 (WU_dx = WU_d cols 512..767)
    precompute_A_kernel<<<dim3(B_SZ, M_SZ / 64), 256>>>(X, WU_d + 512);

    for (int t = 0; t < TS; t++) {
        step_gemm_kernel<<<dim3(B_SZ / 32, 24), 256>>>(WU_d, W_hh);
        attn_lstm_kernel<<<B_SZ, 256>>>(v_d, Wl, Y, W_ih, b_ih, b_hh, t);
    }

    final_head_kernel<<<B_SZ, 256>>>(Wb_w, Wb_b, vb_w, vb_b, out);
}

// round 4
// speedup vs baseline: 1.4092x; 1.0976x over previous
#include <cuda_runtime.h>
#include <cuda_fp16.h>
#include <cstdint>
#include <cstddef>

#define B_SZ 1024
#define T_SZ 128
#define M_SZ 256
#define P_SZ 256
#define TS   127   // T-1 recurrence steps

// ---------------- scratch (static device globals) ---------------------------
__device__ __half g_Ah[(size_t)B_SZ * T_SZ * M_SZ];  // (b,t,m) x-part preact fp16
__device__ __half g_X16[(size_t)B_SZ * T_SZ * M_SZ]; // (b,t,m) fp16 X
__device__ float  g_U1[B_SZ * M_SZ];                 // d-part preact, K-half 1
__device__ float  g_U2[B_SZ * M_SZ];                 // d-part preact, K-half 2
__device__ float  g_HC[B_SZ * 2 * P_SZ];             // [h | c] per batch
__device__ float  g_CTX[B_SZ * M_SZ];                // attention context
__device__ float  g_GATES[B_SZ * 4 * P_SZ];          // h @ W_hh^T

// ---------------- init ------------------------------------------------------
__global__ void init_hc_kernel() {
    int i = blockIdx.x * blockDim.x + threadIdx.x;
    if (i < B_SZ * 2 * P_SZ) g_HC[i] = 0.0f;
}

// ---------------- X (t,b,m) fp32 -> g_X16 (b,t,m) fp16 ----------------------
// 256 threads handle 4 rows of 256 elems; rows stay coalesced on both sides
__global__ void convert_x_kernel(const float* __restrict__ X) {
    int row = blockIdx.x * 4 + (threadIdx.x >> 6);   // row = t*B + b
    int c4  = (threadIdx.x & 63) * 4;
    int t = row >> 10;
    int b = row & 1023;
    float4 v = __ldg((const float4*)(X + (size_t)row * M_SZ + c4));
    __half2* dst = (__half2*)(g_X16 + ((size_t)(b << 7) + t) * M_SZ + c4);
    dst[0] = __floats2half2_rn(v.x, v.y);
    dst[1] = __floats2half2_rn(v.z, v.w);
}

// ---------------- precompute A[b,t,m'] = X[t,b,:] @ WU_dx^T -> fp16 ---------
// BM=128 covers t=0..127 for batch b = blockIdx.x. grid (B, 4), 256 thr
__global__ void precompute_A_kernel(const float* __restrict__ X,
                                    const float* __restrict__ W)   // WU_d + 512
{
    constexpr int BM = 128, BN = 64, BK = 16, TM = 8, TN = 4;
    __shared__ float As[BK][BM + 4];
    __shared__ float Bs[BK][BN + 4];

    const int tid = threadIdx.x;
    const int tx = tid % (BN / TN);   // 0..15
    const int ty = tid / (BN / TN);   // 0..15
    const int b  = blockIdx.x;

    const float* Bb = W + (size_t)blockIdx.y * BN * 768;

    float acc[TM][TN];
#pragma unroll
    for (int i = 0; i < TM; i++)
#pragma unroll
        for (int j = 0; j < TN; j++) acc[i][j] = 0.0f;

    for (int k0 = 0; k0 < M_SZ; k0 += BK) {
#pragma unroll
        for (int i = tid; i < BM * (BK / 4); i += 256) {
            int m  = i / (BK / 4);
            int k4 = (i % (BK / 4)) * 4;
            float4 v = *(const float4*)(X + ((size_t)m * B_SZ + b) * M_SZ + k0 + k4);
            As[k4 + 0][m] = v.x; As[k4 + 1][m] = v.y;
            As[k4 + 2][m] = v.z; As[k4 + 3][m] = v.w;
        }
        {
            int n  = tid / (BK / 4);
            int k4 = (tid % (BK / 4)) * 4;
            float4 v = *(const float4*)(Bb + (size_t)n * 768 + k0 + k4);
            Bs[k4 + 0][n] = v.x; Bs[k4 + 1][n] = v.y;
            Bs[k4 + 2][n] = v.z; Bs[k4 + 3][n] = v.w;
        }
        __syncthreads();

#pragma unroll
        for (int kk = 0; kk < BK; kk++) {
            float a[TM], bb[TN];
#pragma unroll
            for (int i = 0; i < TM; i++) a[i] = As[kk][ty * TM + i];
#pragma unroll
            for (int j = 0; j < TN; j++) bb[j] = Bs[kk][tx * TN + j];
#pragma unroll
            for (int i = 0; i < TM; i++)
#pragma unroll
                for (int j = 0; j < TN; j++)
                    acc[i][j] = fmaf(a[i], bb[j], acc[i][j]);
        }
        __syncthreads();
    }

#pragma unroll
    for (int i = 0; i < TM; i++) {
        __half2* crow = (__half2*)(g_Ah
            + ((size_t)b * T_SZ + ty * TM + i) * M_SZ
            + blockIdx.y * BN + tx * TN);
        crow[0] = __floats2half2_rn(acc[i][0], acc[i][1]);
        crow[1] = __floats2half2_rn(acc[i][2], acc[i][3]);
    }
}

// ---------------- per-step GEMMs (double-buffered): U1, U2, GATES -----------
// grid (32, 24): y 0..3 -> U1, y 4..7 -> U2, y 8..23 -> GATES. Uniform K=256.
__global__ void step_gemm_kernel(const float* __restrict__ WU_d,
                                 const float* __restrict__ W_hh)
{
    __shared__ float As[2][16][36];
    __shared__ float Bs[2][16][68];

    const int tid = threadIdx.x;
    const int tx = tid & 15;       // col group (TN=4)
    const int ty = tid >> 4;       // row group (TM=2)
    const int y  = blockIdx.y;

    const float* Bw; int ldb, koff, ncol, ldc; float* C;
    if (y < 4)       { C = g_U1;    ldc = 256;  ncol = y;     Bw = WU_d; ldb = 768; koff = 0;   }
    else if (y < 8)  { C = g_U2;    ldc = 256;  ncol = y - 4; Bw = WU_d; ldb = 768; koff = 256; }
    else             { C = g_GATES; ldc = 1024; ncol = y - 8; Bw = W_hh; ldb = 256; koff = 0;   }

    const float* Ab = g_HC + (size_t)blockIdx.x * 32 * 512 + koff;
    const float* Bb = Bw + (size_t)ncol * 64 * ldb + koff;

    const int am = tid >> 2;            // 0..63 (A uses 0..31)
    const int ak = (tid & 3) * 4;       // 0,4,8,12
    const bool hasA = (tid < 128);

    // load tile 0
    if (hasA) {
        float4 v = *(const float4*)(Ab + (size_t)am * 512 + ak);
        As[0][ak + 0][am] = v.x; As[0][ak + 1][am] = v.y;
        As[0][ak + 2][am] = v.z; As[0][ak + 3][am] = v.w;
    }
    {
        float4 v = *(const float4*)(Bb + (size_t)am * ldb + ak);
        Bs[0][ak + 0][am] = v.x; Bs[0][ak + 1][am] = v.y;
        Bs[0][ak + 2][am] = v.z; Bs[0][ak + 3][am] = v.w;
    }
    __syncthreads();

    float acc[2][4] = {{0, 0, 0, 0}, {0, 0, 0, 0}};
    int cur = 0;

#pragma unroll 1
    for (int k0 = 16; k0 <= 256; k0 += 16) {
        float4 pa, pb;
        const bool last = (k0 == 256);
        if (!last) {
            if (hasA) pa = *(const float4*)(Ab + (size_t)am * 512 + k0 + ak);
            pb = *(const float4*)(Bb + (size_t)am * ldb + k0 + ak);
        }

#pragma unroll
        for (int kk = 0; kk < 16; kk++) {
            float2 a  = *(const float2*)&As[cur][kk][ty * 2];
            float4 bv = *(const float4*)&Bs[cur][kk][tx * 4];
            acc[0][0] = fmaf(a.x, bv.x, acc[0][0]);
            acc[0][1] = fmaf(a.x, bv.y, acc[0][1]);
            acc[0][2] = fmaf(a.x, bv.z, acc[0][2]);
            acc[0][3] = fmaf(a.x, bv.w, acc[0][3]);
            acc[1][0] = fmaf(a.y, bv.x, acc[1][0]);
            acc[1][1] = fmaf(a.y, bv.y, acc[1][1]);
            acc[1][2] = fmaf(a.y, bv.z, acc[1][2]);
            acc[1][3] = fmaf(a.y, bv.w, acc[1][3]);
        }

        if (!last) {
            int nxt = cur ^ 1;
            if (hasA) {
                As[nxt][ak + 0][am] = pa.x; As[nxt][ak + 1][am] = pa.y;
                As[nxt][ak + 2][am] = pa.z; As[nxt][ak + 3][am] = pa.w;
            }
            Bs[nxt][ak + 0][am] = pb.x; Bs[nxt][ak + 1][am] = pb.y;
            Bs[nxt][ak + 2][am] = pb.z; Bs[nxt][ak + 3][am] = pb.w;
            __syncthreads();
            cur = nxt;
        }
    }

    const int row0 = blockIdx.x * 32 + ty * 2;
    const int col0 = ncol * 64 + tx * 4;
#pragma unroll
    for (int i = 0; i < 2; i++)
        *(float4*)(C + (size_t)(row0 + i) * ldc + col0) =
            make_float4(acc[i][0], acc[i][1], acc[i][2], acc[i][3]);
}

// ---------------- fused attention + LSTM step -------------------------------
// one block per batch, 256 threads (8 warps)
__global__ void attn_lstm_kernel(const float* __restrict__ v_d,
                                 const float* __restrict__ Wl,
                                 const float* __restrict__ Y,
                                 const float* __restrict__ W_ih,
                                 const float* __restrict__ b_ih,
                                 const float* __restrict__ b_hh,
                                 int t_step)
{
    const int b    = blockIdx.x;
    const int tid  = threadIdx.x;     // 0..255
    const int lane = tid & 31;
    const int warp = tid >> 5;

    __shared__ float l_s[T_SZ], beta_s[T_SZ];
    __shared__ float ctx_ws[8][M_SZ];
    __shared__ float redm[8], redsum[8], redy[8];
    __shared__ float yt_s;

    // per-lane u,v slices in registers (m = lane*8 .. lane*8+7), reused 16x
    float ureg[8], vreg[8];
    {
        const int mb = lane * 8;
        float4 u1a = __ldg((const float4*)(g_U1 + b * M_SZ + mb));
        float4 u1b = __ldg((const float4*)(g_U1 + b * M_SZ + mb + 4));
        float4 u2a = __ldg((const float4*)(g_U2 + b * M_SZ + mb));
        float4 u2b = __ldg((const float4*)(g_U2 + b * M_SZ + mb + 4));
        float4 va  = __ldg((const float4*)(v_d + mb));
        float4 vb  = __ldg((const float4*)(v_d + mb + 4));
        ureg[0] = u1a.x + u2a.x; ureg[1] = u1a.y + u2a.y;
        ureg[2] = u1a.z + u2a.z; ureg[3] = u1a.w + u2a.w;
        ureg[4] = u1b.x + u2b.x; ureg[5] = u1b.y + u2b.y;
        ureg[6] = u1b.z + u2b.z; ureg[7] = u1b.w + u2b.w;
        vreg[0] = va.x; vreg[1] = va.y; vreg[2] = va.z; vreg[3] = va.w;
        vreg[4] = vb.x; vreg[5] = vb.y; vreg[6] = vb.z; vreg[7] = vb.w;
    }

    // phase 1: logits l[t] = sum_m v[m] * tanh(u[m] + A[b,t,m])
    const __half* Abase = g_Ah + (size_t)b * T_SZ * M_SZ;
#pragma unroll 2
    for (int t = warp; t < T_SZ; t += 8) {
        const float4 raw = __ldg((const float4*)(Abase + (size_t)t * M_SZ) + lane);
        const __half2* hp = (const __half2*)&raw;   // m = lane*8 .. lane*8+7
        float acc = 0.0f;
#pragma unroll
        for (int j = 0; j < 4; j++) {
            float2 av = __half22float2(hp[j]);
            float x0 = ureg[2 * j]     + av.x;
            float x1 = ureg[2 * j + 1] + av.y;
            float t0, t1;
            asm("tanh.approx.f32 %0, %1;" : "=f"(t0) : "f"(x0));
            asm("tanh.approx.f32 %0, %1;" : "=f"(t1) : "f"(x1));
            acc = fmaf(vreg[2 * j],     t0, acc);
            acc = fmaf(vreg[2 * j + 1], t1, acc);
        }
#pragma unroll
        for (int o = 16; o; o >>= 1) acc += __shfl_xor_sync(0xffffffffu, acc, o);
        if (lane == 0) l_s[t] = acc;
    }
    __syncthreads();

    // phase 2: softmax over T=128 logits
    float lv = (tid < T_SZ) ? l_s[tid] : -1e30f;
    float mx = lv;
#pragma unroll
    for (int o = 16; o; o >>= 1) mx = fmaxf(mx, __shfl_xor_sync(0xffffffffu, mx, o));
    if (lane == 0) redm[warp] = mx;
    __syncthreads();
    mx = redm[0];
#pragma unroll
    for (int w = 1; w < 8; w++) mx = fmaxf(mx, redm[w]);

    float e = (tid < T_SZ) ? __expf(lv - mx) : 0.0f;
    float sm = e;
#pragma unroll
    for (int o = 16; o; o >>= 1) sm += __shfl_xor_sync(0xffffffffu, sm, o);
    if (lane == 0) redsum[warp] = sm;
    __syncthreads();
    sm = redsum[0] + redsum[1] + redsum[2] + redsum[3]
       + redsum[4] + redsum[5] + redsum[6] + redsum[7];
    if (tid < T_SZ) beta_s[tid] = e / sm;
    __syncthreads();

    // phase 3: ctx[m] = sum_t beta[t] * X[b,t,m]; coalesced rows, per-lane acc
    float cacc[8] = {0, 0, 0, 0, 0, 0, 0, 0};
    const __half* Xbase = g_X16 + (size_t)b * T_SZ * M_SZ;
#pragma unroll 2
    for (int t = warp; t < T_SZ; t += 8) {
        const float4 raw = __ldg((const float4*)(Xbase + (size_t)t * M_SZ) + lane);
        const __half2* hp = (const __half2*)&raw;
        const float bt = beta_s[t];
#pragma unroll
        for (int j = 0; j < 4; j++) {
            float2 xv = __half22float2(hp[j]);
            cacc[2 * j]     = fmaf(bt, xv.x, cacc[2 * j]);
            cacc[2 * j + 1] = fmaf(bt, xv.y, cacc[2 * j + 1]);
        }
    }
    *(float4*)&ctx_ws[warp][lane * 8]     = make_float4(cacc[0], cacc[1], cacc[2], cacc[3]);
    *(float4*)&ctx_ws[warp][lane * 8 + 4] = make_float4(cacc[4], cacc[5], cacc[6], cacc[7]);
    __syncthreads();

    float c = ctx_ws[0][tid];
#pragma unroll
    for (int w = 1; w < 8; w++) c += ctx_ws[w][tid];
    g_CTX[b * M_SZ + tid] = c;

    // phase 4: y_tilde = Wl[0]*y_t + sum_m Wl[1+m]*ctx[m]
    float yv = __ldg(Wl + 1 + tid) * c;
#pragma unroll
    for (int o = 16; o; o >>= 1) yv += __shfl_xor_sync(0xffffffffu, yv, o);
    if (lane == 0) redy[warp] = yv;
    __syncthreads();
    if (tid == 0) {
        float s = redy[0] + redy[1] + redy[2] + redy[3]
                + redy[4] + redy[5] + redy[6] + redy[7];
        yt_s = fmaf(__ldg(Wl), Y[(size_t)b * TS + t_step], s);
    }
    __syncthreads();

    // phase 5: fused LSTM pointwise update
    const float yt = yt_s;
    const int p = tid;
    const float* gr = g_GATES + (size_t)b * 4 * P_SZ;
    float ig = gr[p]            + yt * __ldg(W_ih + p)            + __ldg(b_ih + p)            + __ldg(b_hh + p);
    float fg = gr[P_SZ + p]     + yt * __ldg(W_ih + P_SZ + p)     + __ldg(b_ih + P_SZ + p)     + __ldg(b_hh + P_SZ + p);
    float gg = gr[2 * P_SZ + p] + yt * __ldg(W_ih + 2 * P_SZ + p) + __ldg(b_ih + 2 * P_SZ + p) + __ldg(b_hh + 2 * P_SZ + p);
    float og = gr[3 * P_SZ + p] + yt * __ldg(W_ih + 3 * P_SZ + p) + __ldg(b_ih + 3 * P_SZ + p) + __ldg(b_hh + 3 * P_SZ + p);

    float cold = g_HC[(size_t)b * 2 * P_SZ + P_SZ + p];
    float si = 1.0f / (1.0f + __expf(-ig));
    float sf = 1.0f / (1.0f + __expf(-fg));
    float so = 1.0f / (1.0f + __expf(-og));
    float cn = sf * cold + si * tanhf(gg);
    float hn = so * tanhf(cn);

    g_HC[(size_t)b * 2 * P_SZ + p]        = hn;
    g_HC[(size_t)b * 2 * P_SZ + P_SZ + p] = cn;
}

// ---------------- final head: out = ([h,ctx] @ Wb^T + b) @ vb^T + vb_b -----
__global__ void final_head_kernel(const float* __restrict__ Wb_w,
                                  const float* __restrict__ Wb_b,
                                  const float* __restrict__ vb_w,
                                  const float* __restrict__ vb_b,
                                  float* __restrict__ out)
{
    const int b   = blockIdx.x;
    const int tid = threadIdx.x;  // 0..255 = p
    __shared__ float hc_s[2 * P_SZ];
    __shared__ float red[8];

    hc_s[tid]        = g_HC[(size_t)b * 2 * P_SZ + tid];   // h
    hc_s[P_SZ + tid] = g_CTX[(size_t)b * M_SZ + tid];      // ctx
    __syncthreads();

    const float* wr = Wb_w + (size_t)tid * (P_SZ + M_SZ);
    float t = __ldg(Wb_b + tid);
#pragma unroll 4
    for (int k = 0; k < 2 * P_SZ; k++)
        t = fmaf(__ldg(wr + k), hc_s[k], t);
    float val = __ldg(vb_w + tid) * t;

    int lane = tid & 31, warp = tid >> 5;
#pragma unroll
    for (int o = 16; o; o >>= 1) val += __shfl_xor_sync(0xffffffffu, val, o);
    if (lane == 0) red[warp] = val;
    __syncthreads();
    if (tid == 0)
        out[b] = vb_b[0] + red[0] + red[1] + red[2] + red[3]
                         + red[4] + red[5] + red[6] + red[7];
}

// ---------------- launch ----------------------------------------------------
extern "C" void kernel_launch(void* const* d_in, const int* in_sizes, int n_in,
                              void* d_out, int out_size)
{
    const float* Y    = (const float*)d_in[0];
    const float* X    = (const float*)d_in[1];
    const float* WU_d = (const float*)d_in[2];
    const float* v_d  = (const float*)d_in[3];
    const float* Wl   = (const float*)d_in[4];
    const float* W_ih = (const float*)d_in[5];
    const float* W_hh = (const float*)d_in[6];
    const float* b_ih = (const float*)d_in[7];
    const float* b_hh = (const float*)d_in[8];
    const float* Wb_w = (const float*)d_in[9];
    const float* Wb_b = (const float*)d_in[10];
    const float* vb_w = (const float*)d_in[11];
    const float* vb_b = (const float*)d_in[12];
    float* out = (float*)d_out;

    // init h, c = 0
    init_hc_kernel<<<(B_SZ * 2 * P_SZ + 255) / 256, 256>>>();

    // X -> (b,t,m) fp16
    convert_x_kernel<<<(T_SZ * B_SZ) / 4, 256>>>(X);

    // A[b,t,m'] = X[t,b,:] @ WU_dx^T -> fp16 (WU_dx = WU_d cols 512..767)
    precompute_A_kernel<<<dim3(B_SZ, M_SZ / 64), 256>>>(X, WU_d + 512);

    for (int t = 0; t < TS; t++) {
        step_gemm_kernel<<<dim3(B_SZ / 32, 24), 256>>>(WU_d, W_hh);
        attn_lstm_kernel<<<B_SZ, 256>>>(v_d, Wl, Y, W_ih, b_ih, b_hh, t);
    }

    final_head_kernel<<<B_SZ, 256>>>(Wb_w, Wb_b, vb_w, vb_b, out);
}

// round 5
// speedup vs baseline: 2.2717x; 1.6120x over previous
#include <cuda_runtime.h>
#include <cuda_fp16.h>
#include <cstdint>
#include <cstddef>

#define B_SZ 1024
#define T_SZ 128
#define M_SZ 256
#define P_SZ 256
#define TS   127   // T-1 recurrence steps

// ---------------- scratch (static device globals) ---------------------------
__device__ __half g_Ah[(size_t)B_SZ * T_SZ * M_SZ];  // (b,t,m) x-part preact fp16
__device__ __half g_X16[(size_t)B_SZ * T_SZ * M_SZ]; // (b,t,m) fp16 X
__device__ __half g_HCh[B_SZ * 512];                 // fp16 mirror of [h|c]
__device__ __half g_Wdd16[256 * 512];                // WU_d[:, :512] fp16
__device__ __half g_Whh16[1024 * 256];               // W_hh fp16
__device__ __half g_Wdx16[256 * 256];                // WU_d[:, 512:768] fp16
__device__ float  g_U[B_SZ * M_SZ];                  // d-part preactivation
__device__ float  g_HC[B_SZ * 512];                  // fp32 master [h|c]
__device__ float  g_CTX[B_SZ * M_SZ];                // attention context
__device__ float  g_GATES[B_SZ * 4 * P_SZ];          // h @ W_hh^T

// ---------------- init ------------------------------------------------------
__global__ void init_hc_kernel() {
    int i = blockIdx.x * blockDim.x + threadIdx.x;
    if (i < B_SZ * 512) { g_HC[i] = 0.0f; g_HCh[i] = __float2half_rn(0.0f); }
}

// ---------------- X (t,b,m) fp32 -> g_X16 (b,t,m) fp16 ----------------------
__global__ void convert_x_kernel(const float* __restrict__ X) {
    int row = blockIdx.x * 4 + (threadIdx.x >> 6);   // row = t*B + b
    int c4  = (threadIdx.x & 63) * 4;
    int t = row >> 10;
    int b = row & 1023;
    float4 v = __ldg((const float4*)(X + (size_t)row * M_SZ + c4));
    __half2* dst = (__half2*)(g_X16 + ((size_t)(b << 7) + t) * M_SZ + c4);
    dst[0] = __floats2half2_rn(v.x, v.y);
    dst[1] = __floats2half2_rn(v.z, v.w);
}

// ---------------- weights -> fp16 -------------------------------------------
__global__ void convert_w_kernel(const float* __restrict__ WU_d,
                                 const float* __restrict__ W_hh) {
    int i = blockIdx.x * 256 + threadIdx.x;          // 0 .. 262143
    if (i < 256 * 512) {
        int r = i >> 9, k = i & 511;
        g_Wdd16[i] = __float2half_rn(WU_d[r * 768 + k]);
    }
    if (i < 256 * 256) {
        int r = i >> 8, k = i & 255;
        g_Wdx16[i] = __float2half_rn(WU_d[r * 768 + 512 + k]);
    }
    if (i < 1024 * 256) {
        g_Whh16[i] = __float2half_rn(W_hh[i]);
    }
}

// ---------------- HMMA helpers ----------------------------------------------
__device__ __forceinline__ void ldsm4(uint32_t* r, uint32_t addr) {
    asm volatile("ldmatrix.sync.aligned.m8n8.x4.shared.b16 {%0,%1,%2,%3}, [%4];"
                 : "=r"(r[0]), "=r"(r[1]), "=r"(r[2]), "=r"(r[3]) : "r"(addr));
}

__device__ __forceinline__ void mma_16816(float* acc, const uint32_t* a,
                                          uint32_t b0, uint32_t b1) {
    asm volatile(
        "mma.sync.aligned.m16n8k16.row.col.f32.f16.f16.f32 "
        "{%0,%1,%2,%3},{%4,%5,%6,%7},{%8,%9},{%0,%1,%2,%3};"
        : "+f"(acc[0]), "+f"(acc[1]), "+f"(acc[2]), "+f"(acc[3])
        : "r"(a[0]), "r"(a[1]), "r"(a[2]), "r"(a[3]), "r"(b0), "r"(b1));
}

// 64x64 block tile, 256 threads (8 warps as 2m x 4n, warp tile 32x16).
// A (row-major M x K fp16, lda), B (N x K fp16 row-major = col-major KxN, ldb).
// K = nit*32. Smem rows padded to 40 halves (80B) -> conflict-free LDSM.
#define HM_STRIDE 40
#define HM_BUFH   (64 * HM_STRIDE)
__device__ __forceinline__ void hmma_block(
    const __half* __restrict__ Ag0, int lda,
    const __half* __restrict__ Bg0, int ldb,
    int nit, float acc[2][2][4], __half* As, __half* Bs)
{
    const int tid  = threadIdx.x;
    const int lane = tid & 31, warp = tid >> 5;

    const __half* Ag = Ag0 + (size_t)(tid >> 2) * lda + (tid & 3) * 8;
    const __half* Bg = Bg0 + (size_t)(tid >> 2) * ldb + (tid & 3) * 8;
    const uint32_t st_off = ((tid >> 2) * HM_STRIDE + (tid & 3) * 8) * 2;
    const uint32_t as_base = (uint32_t)__cvta_generic_to_shared(As);
    const uint32_t bs_base = (uint32_t)__cvta_generic_to_shared(Bs);

    const int arow = (warp >> 2) * 32 + (lane & 7) + ((lane >> 3) & 1) * 8;
    const uint32_t a_off0 = (arow * HM_STRIDE + (lane >> 4) * 8) * 2;
    const uint32_t a_off1 = a_off0 + 16 * HM_STRIDE * 2;
    const int brow = (warp & 3) * 16 + (lane & 7) + (lane >> 4) * 8;
    const uint32_t b_off = (brow * HM_STRIDE + ((lane >> 3) & 1) * 8) * 2;

    *(uint4*)((char*)As + st_off) = *(const uint4*)Ag;
    *(uint4*)((char*)Bs + st_off) = *(const uint4*)Bg;
    __syncthreads();

    const uint32_t BUFB = HM_BUFH * 2;
    int buf = 0;
#pragma unroll 1
    for (int it = 0; it < nit; it++) {
        uint4 pa, pb;
        const bool more = (it + 1 < nit);
        if (more) {
            pa = *(const uint4*)(Ag + (it + 1) * 32);
            pb = *(const uint4*)(Bg + (it + 1) * 32);
        }
        const uint32_t ab = as_base + buf * BUFB;
        const uint32_t bb = bs_base + buf * BUFB;
#pragma unroll
        for (int kk = 0; kk < 2; kk++) {
            uint32_t af0[4], af1[4], bf[4];
            ldsm4(af0, ab + a_off0 + kk * 32);
            ldsm4(af1, ab + a_off1 + kk * 32);
            ldsm4(bf,  bb + b_off  + kk * 32);
            mma_16816(acc[0][0], af0, bf[0], bf[1]);
            mma_16816(acc[0][1], af0, bf[2], bf[3]);
            mma_16816(acc[1][0], af1, bf[0], bf[1]);
            mma_16816(acc[1][1], af1, bf[2], bf[3]);
        }
        if (more) {
            const int nb = buf ^ 1;
            *(uint4*)((char*)As + nb * BUFB + st_off) = pa;
            *(uint4*)((char*)Bs + nb * BUFB + st_off) = pb;
            __syncthreads();
            buf = nb;
        }
    }
}

// ---------------- per-step GEMMs via HMMA: U and GATES -----------------------
// grid (16, 20): y 0..3 -> U = [h,c]@WU_dd^T (K=512); y 4..19 -> GATES (K=256)
__global__ void step_gemm_hmma() {
    __shared__ __half As[2][HM_BUFH];
    __shared__ __half Bs[2][HM_BUFH];

    const int y = blockIdx.y;
    const __half* Bg; float* C; int ldb, ldc, col0, nit;
    if (y < 4) { Bg = g_Wdd16 + (size_t)y * 64 * 512;       ldb = 512; C = g_U;     ldc = 256;  col0 = y * 64;       nit = 16; }
    else       { Bg = g_Whh16 + (size_t)(y - 4) * 64 * 256; ldb = 256; C = g_GATES; ldc = 1024; col0 = (y - 4) * 64; nit = 8;  }

    float acc[2][2][4] = {};
    hmma_block(g_HCh + (size_t)blockIdx.x * 64 * 512, 512, Bg, ldb, nit,
               acc, &As[0][0], &Bs[0][0]);

    const int lane = threadIdx.x & 31, warp = threadIdx.x >> 5;
    const int gid = lane >> 2, tig = lane & 3;
    const int mrow0 = blockIdx.x * 64 + (warp >> 2) * 32;
    const int c0 = col0 + (warp & 3) * 16;
#pragma unroll
    for (int mt = 0; mt < 2; mt++)
#pragma unroll
        for (int nt = 0; nt < 2; nt++) {
            const float* a = acc[mt][nt];
            const int r  = mrow0 + mt * 16 + gid;
            const int cc = c0 + nt * 8 + tig * 2;
            *(float2*)&C[(size_t)r * ldc + cc]       = make_float2(a[0], a[1]);
            *(float2*)&C[(size_t)(r + 8) * ldc + cc] = make_float2(a[2], a[3]);
        }
}

// ---------------- A precompute via HMMA: g_Ah = g_X16 @ Wdx^T (fp16 out) ----
// grid (2048, 4): rows = b*128+t (131072), K=256
__global__ void precompute_A_hmma() {
    __shared__ __half As[2][HM_BUFH];
    __shared__ __half Bs[2][HM_BUFH];

    float acc[2][2][4] = {};
    hmma_block(g_X16 + (size_t)blockIdx.x * 64 * 256, 256,
               g_Wdx16 + (size_t)blockIdx.y * 64 * 256, 256, 8,
               acc, &As[0][0], &Bs[0][0]);

    const int lane = threadIdx.x & 31, warp = threadIdx.x >> 5;
    const int gid = lane >> 2, tig = lane & 3;
    const int mrow0 = blockIdx.x * 64 + (warp >> 2) * 32;
    const int c0 = blockIdx.y * 64 + (warp & 3) * 16;
#pragma unroll
    for (int mt = 0; mt < 2; mt++)
#pragma unroll
        for (int nt = 0; nt < 2; nt++) {
            const float* a = acc[mt][nt];
            const int r  = mrow0 + mt * 16 + gid;
            const int cc = c0 + nt * 8 + tig * 2;
            *(__half2*)&g_Ah[(size_t)r * 256 + cc]       = __floats2half2_rn(a[0], a[1]);
            *(__half2*)&g_Ah[(size_t)(r + 8) * 256 + cc] = __floats2half2_rn(a[2], a[3]);
        }
}

// ---------------- fused attention + LSTM step -------------------------------
// one block per batch, 256 threads (8 warps)
__global__ void attn_lstm_kernel(const float* __restrict__ v_d,
                                 const float* __restrict__ Wl,
                                 const float* __restrict__ Y,
                                 const float* __restrict__ W_ih,
                                 const float* __restrict__ b_ih,
                                 const float* __restrict__ b_hh,
                                 int t_step)
{
    const int b    = blockIdx.x;
    const int tid  = threadIdx.x;     // 0..255
    const int lane = tid & 31;
    const int warp = tid >> 5;

    __shared__ float l_s[T_SZ], beta_s[T_SZ];
    __shared__ float ctx_ws[8][M_SZ];
    __shared__ float redm[8], redsum[8], redy[8];
    __shared__ float yt_s;

    // per-lane u,v slices in registers (m = lane*8 .. lane*8+7), reused 16x
    float ureg[8], vreg[8];
    {
        const int mb = lane * 8;
        float4 ua = __ldg((const float4*)(g_U + b * M_SZ + mb));
        float4 ub = __ldg((const float4*)(g_U + b * M_SZ + mb + 4));
        float4 va = __ldg((const float4*)(v_d + mb));
        float4 vb = __ldg((const float4*)(v_d + mb + 4));
        ureg[0] = ua.x; ureg[1] = ua.y; ureg[2] = ua.z; ureg[3] = ua.w;
        ureg[4] = ub.x; ureg[5] = ub.y; ureg[6] = ub.z; ureg[7] = ub.w;
        vreg[0] = va.x; vreg[1] = va.y; vreg[2] = va.z; vreg[3] = va.w;
        vreg[4] = vb.x; vreg[5] = vb.y; vreg[6] = vb.z; vreg[7] = vb.w;
    }

    // phase 1: logits l[t] = sum_m v[m] * tanh(u[m] + A[b,t,m])
    const __half* Abase = g_Ah + (size_t)b * T_SZ * M_SZ;
#pragma unroll 2
    for (int t = warp; t < T_SZ; t += 8) {
        const float4 raw = __ldg((const float4*)(Abase + (size_t)t * M_SZ) + lane);
        const __half2* hp = (const __half2*)&raw;   // m = lane*8 .. lane*8+7
        float acc = 0.0f;
#pragma unroll
        for (int j = 0; j < 4; j++) {
            float2 av = __half22float2(hp[j]);
            float x0 = ureg[2 * j]     + av.x;
            float x1 = ureg[2 * j + 1] + av.y;
            float t0, t1;
            asm("tanh.approx.f32 %0, %1;" : "=f"(t0) : "f"(x0));
            asm("tanh.approx.f32 %0, %1;" : "=f"(t1) : "f"(x1));
            acc = fmaf(vreg[2 * j],     t0, acc);
            acc = fmaf(vreg[2 * j + 1], t1, acc);
        }
#pragma unroll
        for (int o = 16; o; o >>= 1) acc += __shfl_xor_sync(0xffffffffu, acc, o);
        if (lane == 0) l_s[t] = acc;
    }
    __syncthreads();

    // phase 2: softmax over T=128 logits
    float lv = (tid < T_SZ) ? l_s[tid] : -1e30f;
    float mx = lv;
#pragma unroll
    for (int o = 16; o; o >>= 1) mx = fmaxf(mx, __shfl_xor_sync(0xffffffffu, mx, o));
    if (lane == 0) redm[warp] = mx;
    __syncthreads();
    mx = redm[0];
#pragma unroll
    for (int w = 1; w < 8; w++) mx = fmaxf(mx, redm[w]);

    float e = (tid < T_SZ) ? __expf(lv - mx) : 0.0f;
    float sm = e;
#pragma unroll
    for (int o = 16; o; o >>= 1) sm += __shfl_xor_sync(0xffffffffu, sm, o);
    if (lane == 0) redsum[warp] = sm;
    __syncthreads();
    sm = redsum[0] + redsum[1] + redsum[2] + redsum[3]
       + redsum[4] + redsum[5] + redsum[6] + redsum[7];
    if (tid < T_SZ) beta_s[tid] = e / sm;
    __syncthreads();

    // phase 3: ctx[m] = sum_t beta[t] * X[b,t,m]; per-lane register partials
    float cacc[8] = {0, 0, 0, 0, 0, 0, 0, 0};
    const __half* Xbase = g_X16 + (size_t)b * T_SZ * M_SZ;
#pragma unroll 2
    for (int t = warp; t < T_SZ; t += 8) {
        const float4 raw = __ldg((const float4*)(Xbase + (size_t)t * M_SZ) + lane);
        const __half2* hp = (const __half2*)&raw;
        const float bt = beta_s[t];
#pragma unroll
        for (int j = 0; j < 4; j++) {
            float2 xv = __half22float2(hp[j]);
            cacc[2 * j]     = fmaf(bt, xv.x, cacc[2 * j]);
            cacc[2 * j + 1] = fmaf(bt, xv.y, cacc[2 * j + 1]);
        }
    }
    *(float4*)&ctx_ws[warp][lane * 8]     = make_float4(cacc[0], cacc[1], cacc[2], cacc[3]);
    *(float4*)&ctx_ws[warp][lane * 8 + 4] = make_float4(cacc[4], cacc[5], cacc[6], cacc[7]);
    __syncthreads();

    float c = ctx_ws[0][tid];
#pragma unroll
    for (int w = 1; w < 8; w++) c += ctx_ws[w][tid];
    g_CTX[b * M_SZ + tid] = c;

    // phase 4: y_tilde = Wl[0]*y_t + sum_m Wl[1+m]*ctx[m]
    float yv = __ldg(Wl + 1 + tid) * c;
#pragma unroll
    for (int o = 16; o; o >>= 1) yv += __shfl_xor_sync(0xffffffffu, yv, o);
    if (lane == 0) redy[warp] = yv;
    __syncthreads();
    if (tid == 0) {
        float s = redy[0] + redy[1] + redy[2] + redy[3]
                + redy[4] + redy[5] + redy[6] + redy[7];
        yt_s = fmaf(__ldg(Wl), Y[(size_t)b * TS + t_step], s);
    }
    __syncthreads();

    // phase 5: fused LSTM pointwise update
    const float yt = yt_s;
    const int p = tid;
    const float* gr = g_GATES + (size_t)b * 4 * P_SZ;
    float ig = gr[p]            + yt * __ldg(W_ih + p)            + __ldg(b_ih + p)            + __ldg(b_hh + p);
    float fg = gr[P_SZ + p]     + yt * __ldg(W_ih + P_SZ + p)     + __ldg(b_ih + P_SZ + p)     + __ldg(b_hh + P_SZ + p);
    float gg = gr[2 * P_SZ + p] + yt * __ldg(W_ih + 2 * P_SZ + p) + __ldg(b_ih + 2 * P_SZ + p) + __ldg(b_hh + 2 * P_SZ + p);
    float og = gr[3 * P_SZ + p] + yt * __ldg(W_ih + 3 * P_SZ + p) + __ldg(b_ih + 3 * P_SZ + p) + __ldg(b_hh + 3 * P_SZ + p);

    float cold = g_HC[(size_t)b * 512 + 256 + p];
    float si = 1.0f / (1.0f + __expf(-ig));
    float sf = 1.0f / (1.0f + __expf(-fg));
    float so = 1.0f / (1.0f + __expf(-og));
    float cn = sf * cold + si * tanhf(gg);
    float hn = so * tanhf(cn);

    g_HC[(size_t)b * 512 + p]        = hn;
    g_HC[(size_t)b * 512 + 256 + p]  = cn;
    g_HCh[(size_t)b * 512 + p]       = __float2half_rn(hn);
    g_HCh[(size_t)b * 512 + 256 + p] = __float2half_rn(cn);
}

// ---------------- final head: out = ([h,ctx] @ Wb^T + b) @ vb^T + vb_b -----
__global__ void final_head_kernel(const float* __restrict__ Wb_w,
                                  const float* __restrict__ Wb_b,
                                  const float* __restrict__ vb_w,
                                  const float* __restrict__ vb_b,
                                  float* __restrict__ out)
{
    const int b   = blockIdx.x;
    const int tid = threadIdx.x;  // 0..255 = p
    __shared__ float hc_s[512];
    __shared__ float red[8];

    hc_s[tid]        = g_HC[(size_t)b * 512 + tid];        // h
    hc_s[P_SZ + tid] = g_CTX[(size_t)b * M_SZ + tid];      // ctx
    __syncthreads();

    const float* wr = Wb_w + (size_t)tid * (P_SZ + M_SZ);
    float t = __ldg(Wb_b + tid);
#pragma unroll 4
    for (int k = 0; k < 2 * P_SZ; k++)
        t = fmaf(__ldg(wr + k), hc_s[k], t);
    float val = __ldg(vb_w + tid) * t;

    int lane = tid & 31, warp = tid >> 5;
#pragma unroll
    for (int o = 16; o; o >>= 1) val += __shfl_xor_sync(0xffffffffu, val, o);
    if (lane == 0) red[warp] = val;
    __syncthreads();
    if (tid == 0)
        out[b] = vb_b[0] + red[0] + red[1] + red[2] + red[3]
                         + red[4] + red[5] + red[6] + red[7];
}

// ---------------- launch ----------------------------------------------------
extern "C" void kernel_launch(void* const* d_in, const int* in_sizes, int n_in,
                              void* d_out, int out_size)
{
    const float* Y    = (const float*)d_in[0];
    const float* X    = (const float*)d_in[1];
    const float* WU_d = (const float*)d_in[2];
    const float* v_d  = (const float*)d_in[3];
    const float* Wl   = (const float*)d_in[4];
    const float* W_ih = (const float*)d_in[5];
    const float* W_hh = (const float*)d_in[6];
    const float* b_ih = (const float*)d_in[7];
    const float* b_hh = (const float*)d_in[8];
    const float* Wb_w = (const float*)d_in[9];
    const float* Wb_b = (const float*)d_in[10];
    const float* vb_w = (const float*)d_in[11];
    const float* vb_b = (const float*)d_in[12];
    float* out = (float*)d_out;

    // init h, c = 0 (fp32 + fp16 mirrors)
    init_hc_kernel<<<(B_SZ * 512 + 255) / 256, 256>>>();

    // X -> (b,t,m) fp16 ; weights -> fp16
    convert_x_kernel<<<(T_SZ * B_SZ) / 4, 256>>>(X);
    convert_w_kernel<<<1024, 256>>>(WU_d, W_hh);

    // A[b,t,m'] = X16 @ Wdx^T -> fp16 (HMMA)
    precompute_A_hmma<<<dim3((B_SZ * T_SZ) / 64, M_SZ / 64), 256>>>();

    for (int t = 0; t < TS; t++) {
        step_gemm_hmma<<<dim3(B_SZ / 64, 20), 256>>>();
        attn_lstm_kernel<<<B_SZ, 256>>>(v_d, Wl, Y, W_ih, b_ih, b_hh, t);
    }

    final_head_kernel<<<B_SZ, 256>>>(Wb_w, Wb_b, vb_w, vb_b, out);
}

// round 6
// speedup vs baseline: 2.6504x; 1.1667x over previous
#include <cuda_runtime.h>
#include <cuda_fp16.h>
#include <cstdint>
#include <cstddef>

#define B_SZ 1024
#define T_SZ 128
#define M_SZ 256
#define P_SZ 256
#define TS   127   // T-1 recurrence steps

// dynamic smem for attn kernel: X tile + reduction scratch
#define SMEM_ATTN_BYTES 74880

// ---------------- scratch (static device globals) ---------------------------
__device__ __half g_Ah[(size_t)B_SZ * T_SZ * M_SZ];  // (b,t,m) x-part preact fp16
__device__ __half g_X16[(size_t)B_SZ * T_SZ * M_SZ]; // (b,t,m) fp16 X
__device__ __half g_HCh[B_SZ * 512];                 // fp16 mirror of [h|c]
__device__ __half g_Wdd16[256 * 512];                // WU_d[:, :512] fp16
__device__ __half g_Whh16[1024 * 256];               // W_hh fp16
__device__ __half g_Wdx16[256 * 256];                // WU_d[:, 512:768] fp16
__device__ float  g_U[B_SZ * M_SZ];                  // d-part preactivation
__device__ float  g_HC[B_SZ * 512];                  // fp32 master [h|c]
__device__ float  g_CTX[B_SZ * M_SZ];                // attention context (last step)
__device__ float  g_GATES[B_SZ * 4 * P_SZ];          // h @ W_hh^T

// ---------------- init ------------------------------------------------------
__global__ void init_hc_kernel() {
    int i = blockIdx.x * blockDim.x + threadIdx.x;
    if (i < B_SZ * 512) { g_HC[i] = 0.0f; g_HCh[i] = __float2half_rn(0.0f); }
}

// ---------------- X (t,b,m) fp32 -> g_X16 (b,t,m) fp16 ----------------------
__global__ void convert_x_kernel(const float* __restrict__ X) {
    int row = blockIdx.x * 4 + (threadIdx.x >> 6);   // row = t*B + b
    int c4  = (threadIdx.x & 63) * 4;
    int t = row >> 10;
    int b = row & 1023;
    float4 v = __ldg((const float4*)(X + (size_t)row * M_SZ + c4));
    __half2* dst = (__half2*)(g_X16 + ((size_t)(b << 7) + t) * M_SZ + c4);
    dst[0] = __floats2half2_rn(v.x, v.y);
    dst[1] = __floats2half2_rn(v.z, v.w);
}

// ---------------- weights -> fp16 -------------------------------------------
__global__ void convert_w_kernel(const float* __restrict__ WU_d,
                                 const float* __restrict__ W_hh) {
    int i = blockIdx.x * 256 + threadIdx.x;          // 0 .. 262143
    if (i < 256 * 512) {
        int r = i >> 9, k = i & 511;
        g_Wdd16[i] = __float2half_rn(WU_d[r * 768 + k]);
    }
    if (i < 256 * 256) {
        int r = i >> 8, k = i & 255;
        g_Wdx16[i] = __float2half_rn(WU_d[r * 768 + 512 + k]);
    }
    if (i < 1024 * 256) {
        g_Whh16[i] = __float2half_rn(W_hh[i]);
    }
}

// ---------------- HMMA helpers ----------------------------------------------
__device__ __forceinline__ void ldsm4(uint32_t* r, uint32_t addr) {
    asm volatile("ldmatrix.sync.aligned.m8n8.x4.shared.b16 {%0,%1,%2,%3}, [%4];"
                 : "=r"(r[0]), "=r"(r[1]), "=r"(r[2]), "=r"(r[3]) : "r"(addr));
}

__device__ __forceinline__ void mma_16816(float* acc, const uint32_t* a,
                                          uint32_t b0, uint32_t b1) {
    asm volatile(
        "mma.sync.aligned.m16n8k16.row.col.f32.f16.f16.f32 "
        "{%0,%1,%2,%3},{%4,%5,%6,%7},{%8,%9},{%0,%1,%2,%3};"
        : "+f"(acc[0]), "+f"(acc[1]), "+f"(acc[2]), "+f"(acc[3])
        : "r"(a[0]), "r"(a[1]), "r"(a[2]), "r"(a[3]), "r"(b0), "r"(b1));
}

// 64x64 block tile, 256 threads (8 warps as 2m x 4n, warp tile 32x16).
#define HM_STRIDE 40
#define HM_BUFH   (64 * HM_STRIDE)
__device__ __forceinline__ void hmma_block(
    const __half* __restrict__ Ag0, int lda,
    const __half* __restrict__ Bg0, int ldb,
    int nit, float acc[2][2][4], __half* As, __half* Bs)
{
    const int tid  = threadIdx.x;
    const int lane = tid & 31, warp = tid >> 5;

    const __half* Ag = Ag0 + (size_t)(tid >> 2) * lda + (tid & 3) * 8;
    const __half* Bg = Bg0 + (size_t)(tid >> 2) * ldb + (tid & 3) * 8;
    const uint32_t st_off = ((tid >> 2) * HM_STRIDE + (tid & 3) * 8) * 2;
    const uint32_t as_base = (uint32_t)__cvta_generic_to_shared(As);
    const uint32_t bs_base = (uint32_t)__cvta_generic_to_shared(Bs);

    const int arow = (warp >> 2) * 32 + (lane & 7) + ((lane >> 3) & 1) * 8;
    const uint32_t a_off0 = (arow * HM_STRIDE + (lane >> 4) * 8) * 2;
    const uint32_t a_off1 = a_off0 + 16 * HM_STRIDE * 2;
    const int brow = (warp & 3) * 16 + (lane & 7) + (lane >> 4) * 8;
    const uint32_t b_off = (brow * HM_STRIDE + ((lane >> 3) & 1) * 8) * 2;

    *(uint4*)((char*)As + st_off) = *(const uint4*)Ag;
    *(uint4*)((char*)Bs + st_off) = *(const uint4*)Bg;
    __syncthreads();

    const uint32_t BUFB = HM_BUFH * 2;
    int buf = 0;
#pragma unroll 1
    for (int it = 0; it < nit; it++) {
        uint4 pa, pb;
        const bool more = (it + 1 < nit);
        if (more) {
            pa = *(const uint4*)(Ag + (it + 1) * 32);
            pb = *(const uint4*)(Bg + (it + 1) * 32);
        }
        const uint32_t ab = as_base + buf * BUFB;
        const uint32_t bb = bs_base + buf * BUFB;
#pragma unroll
        for (int kk = 0; kk < 2; kk++) {
            uint32_t af0[4], af1[4], bf[4];
            ldsm4(af0, ab + a_off0 + kk * 32);
            ldsm4(af1, ab + a_off1 + kk * 32);
            ldsm4(bf,  bb + b_off  + kk * 32);
            mma_16816(acc[0][0], af0, bf[0], bf[1]);
            mma_16816(acc[0][1], af0, bf[2], bf[3]);
            mma_16816(acc[1][0], af1, bf[0], bf[1]);
            mma_16816(acc[1][1], af1, bf[2], bf[3]);
        }
        if (more) {
            const int nb = buf ^ 1;
            *(uint4*)((char*)As + nb * BUFB + st_off) = pa;
            *(uint4*)((char*)Bs + nb * BUFB + st_off) = pb;
            __syncthreads();
            buf = nb;
        }
    }
}

// ---------------- per-step GEMMs via HMMA: U and GATES -----------------------
__global__ void step_gemm_hmma() {
    __shared__ __half As[2][HM_BUFH];
    __shared__ __half Bs[2][HM_BUFH];

    const int y = blockIdx.y;
    const __half* Bg; float* C; int ldb, ldc, col0, nit;
    if (y < 4) { Bg = g_Wdd16 + (size_t)y * 64 * 512;       ldb = 512; C = g_U;     ldc = 256;  col0 = y * 64;       nit = 16; }
    else       { Bg = g_Whh16 + (size_t)(y - 4) * 64 * 256; ldb = 256; C = g_GATES; ldc = 1024; col0 = (y - 4) * 64; nit = 8;  }

    float acc[2][2][4] = {};
    hmma_block(g_HCh + (size_t)blockIdx.x * 64 * 512, 512, Bg, ldb, nit,
               acc, &As[0][0], &Bs[0][0]);

    const int lane = threadIdx.x & 31, warp = threadIdx.x >> 5;
    const int gid = lane >> 2, tig = lane & 3;
    const int mrow0 = blockIdx.x * 64 + (warp >> 2) * 32;
    const int c0 = col0 + (warp & 3) * 16;
#pragma unroll
    for (int mt = 0; mt < 2; mt++)
#pragma unroll
        for (int nt = 0; nt < 2; nt++) {
            const float* a = acc[mt][nt];
            const int r  = mrow0 + mt * 16 + gid;
            const int cc = c0 + nt * 8 + tig * 2;
            *(float2*)&C[(size_t)r * ldc + cc]       = make_float2(a[0], a[1]);
            *(float2*)&C[(size_t)(r + 8) * ldc + cc] = make_float2(a[2], a[3]);
        }
}

// ---------------- A precompute via HMMA: g_Ah = g_X16 @ Wdx^T (fp16 out) ----
__global__ void precompute_A_hmma() {
    __shared__ __half As[2][HM_BUFH];
    __shared__ __half Bs[2][HM_BUFH];

    float acc[2][2][4] = {};
    hmma_block(g_X16 + (size_t)blockIdx.x * 64 * 256, 256,
               g_Wdx16 + (size_t)blockIdx.y * 64 * 256, 256, 8,
               acc, &As[0][0], &Bs[0][0]);

    const int lane = threadIdx.x & 31, warp = threadIdx.x >> 5;
    const int gid = lane >> 2, tig = lane & 3;
    const int mrow0 = blockIdx.x * 64 + (warp >> 2) * 32;
    const int c0 = blockIdx.y * 64 + (warp & 3) * 16;
#pragma unroll
    for (int mt = 0; mt < 2; mt++)
#pragma unroll
        for (int nt = 0; nt < 2; nt++) {
            const float* a = acc[mt][nt];
            const int r  = mrow0 + mt * 16 + gid;
            const int cc = c0 + nt * 8 + tig * 2;
            *(__half2*)&g_Ah[(size_t)r * 256 + cc]       = __floats2half2_rn(a[0], a[1]);
            *(__half2*)&g_Ah[(size_t)(r + 8) * 256 + cc] = __floats2half2_rn(a[2], a[3]);
        }
}

// ---------------- fused attention + LSTM step -------------------------------
// one block per batch, 256 threads (8 warps); dynamic smem holds the X tile
__global__ void attn_lstm_kernel(const float* __restrict__ v_d,
                                 const float* __restrict__ Wl,
                                 const float* __restrict__ Y,
                                 const float* __restrict__ W_ih,
                                 const float* __restrict__ b_ih,
                                 const float* __restrict__ b_hh,
                                 int t_step)
{
    extern __shared__ char sm[];
    __half* Xs     = (__half*)sm;                      // [128][256] fp16
    float*  l_s    = (float*)(sm + 65536);             // [128]
    float*  beta_s = l_s + 128;                        // [128]
    float*  ctx_ws = beta_s + 128;                     // [8][256]
    float*  redm   = ctx_ws + 8 * 256;                 // [8]
    float*  redsum = redm + 8;                         // [8]
    float*  redy   = redsum + 8;                       // [8]
    float*  yt_sp  = redy + 8;                         // [1]

    const int b    = blockIdx.x;
    const int tid  = threadIdx.x;     // 0..255
    const int lane = tid & 31;
    const int warp = tid >> 5;

    // fire-and-forget: X rows -> smem via cp.async (overlaps phase-1 A stream)
    const __half* Xbase = g_X16 + (size_t)b * T_SZ * M_SZ;
    {
        const uint32_t xs_base = (uint32_t)__cvta_generic_to_shared(Xs);
#pragma unroll
        for (int i = 0; i < 16; i++) {
            const int t = warp + i * 8;
            const uint32_t saddr = xs_base + (uint32_t)(t * 256 + lane * 8) * 2;
            const void* gp = Xbase + (size_t)t * 256 + lane * 8;
            asm volatile("cp.async.cg.shared.global [%0], [%1], 16;\n"
                         :: "r"(saddr), "l"(gp));
        }
        asm volatile("cp.async.commit_group;\n");
    }

    // per-lane u,v slices in registers (m = lane*8 .. lane*8+7), reused 16x
    float ureg[8], vreg[8];
    {
        const int mb = lane * 8;
        float4 ua = __ldg((const float4*)(g_U + b * M_SZ + mb));
        float4 ub = __ldg((const float4*)(g_U + b * M_SZ + mb + 4));
        float4 va = __ldg((const float4*)(v_d + mb));
        float4 vb = __ldg((const float4*)(v_d + mb + 4));
        ureg[0] = ua.x; ureg[1] = ua.y; ureg[2] = ua.z; ureg[3] = ua.w;
        ureg[4] = ub.x; ureg[5] = ub.y; ureg[6] = ub.z; ureg[7] = ub.w;
        vreg[0] = va.x; vreg[1] = va.y; vreg[2] = va.z; vreg[3] = va.w;
        vreg[4] = vb.x; vreg[5] = vb.y; vreg[6] = vb.z; vreg[7] = vb.w;
    }

    // phase 1: logits l[t] = sum_m v[m]*tanh(u[m]+A[b,t,m]); depth-3 pipeline
    const __half* Abase = g_Ah + (size_t)b * T_SZ * M_SZ;
    {
        float4 cur = __ldg((const float4*)(Abase + (size_t)warp * 256) + lane);
        float4 nx  = __ldg((const float4*)(Abase + (size_t)(warp + 8) * 256) + lane);
#pragma unroll
        for (int i = 0; i < 16; i++) {
            const int t = warp + i * 8;
            float4 fut = cur;
            if (i < 14)
                fut = __ldg((const float4*)(Abase + (size_t)(t + 16) * 256) + lane);
            const __half2* hp = (const __half2*)&cur;
            float acc = 0.0f;
#pragma unroll
            for (int j = 0; j < 4; j++) {
                float2 av = __half22float2(hp[j]);
                float x0 = ureg[2 * j]     + av.x;
                float x1 = ureg[2 * j + 1] + av.y;
                float t0, t1;
                asm("tanh.approx.f32 %0, %1;" : "=f"(t0) : "f"(x0));
                asm("tanh.approx.f32 %0, %1;" : "=f"(t1) : "f"(x1));
                acc = fmaf(vreg[2 * j],     t0, acc);
                acc = fmaf(vreg[2 * j + 1], t1, acc);
            }
#pragma unroll
            for (int o = 16; o; o >>= 1) acc += __shfl_xor_sync(0xffffffffu, acc, o);
            if (lane == 0) l_s[t] = acc;
            cur = nx; nx = fut;
        }
    }
    __syncthreads();

    // phase 2: softmax over T=128 logits
    float lv = (tid < T_SZ) ? l_s[tid] : -1e30f;
    float mx = lv;
#pragma unroll
    for (int o = 16; o; o >>= 1) mx = fmaxf(mx, __shfl_xor_sync(0xffffffffu, mx, o));
    if (lane == 0) redm[warp] = mx;
    __syncthreads();
    mx = redm[0];
#pragma unroll
    for (int w = 1; w < 8; w++) mx = fmaxf(mx, redm[w]);

    float e = (tid < T_SZ) ? __expf(lv - mx) : 0.0f;
    float sm2 = e;
#pragma unroll
    for (int o = 16; o; o >>= 1) sm2 += __shfl_xor_sync(0xffffffffu, sm2, o);
    if (lane == 0) redsum[warp] = sm2;
    __syncthreads();
    sm2 = redsum[0] + redsum[1] + redsum[2] + redsum[3]
        + redsum[4] + redsum[5] + redsum[6] + redsum[7];
    if (tid < T_SZ) beta_s[tid] = e / sm2;

    // X tile must be resident before phase 3
    asm volatile("cp.async.wait_group 0;\n");
    __syncthreads();

    // phase 3: ctx[m] = sum_t beta[t] * Xs[t][m]; per-lane register partials
    float cacc[8] = {0, 0, 0, 0, 0, 0, 0, 0};
#pragma unroll 4
    for (int t = warp; t < T_SZ; t += 8) {
        const float4 raw = *(const float4*)(Xs + (size_t)t * 256 + lane * 8);
        const __half2* hp = (const __half2*)&raw;
        const float bt = beta_s[t];
#pragma unroll
        for (int j = 0; j < 4; j++) {
            float2 xv = __half22float2(hp[j]);
            cacc[2 * j]     = fmaf(bt, xv.x, cacc[2 * j]);
            cacc[2 * j + 1] = fmaf(bt, xv.y, cacc[2 * j + 1]);
        }
    }
    *(float4*)&ctx_ws[warp * 256 + lane * 8]     = make_float4(cacc[0], cacc[1], cacc[2], cacc[3]);
    *(float4*)&ctx_ws[warp * 256 + lane * 8 + 4] = make_float4(cacc[4], cacc[5], cacc[6], cacc[7]);
    __syncthreads();

    float c = ctx_ws[tid];
#pragma unroll
    for (int w = 1; w < 8; w++) c += ctx_ws[w * 256 + tid];
    if (t_step == TS - 1) g_CTX[b * M_SZ + tid] = c;

    // phase 4: y_tilde = Wl[0]*y_t + sum_m Wl[1+m]*ctx[m]
    float yv = __ldg(Wl + 1 + tid) * c;
#pragma unroll
    for (int o = 16; o; o >>= 1) yv += __shfl_xor_sync(0xffffffffu, yv, o);
    if (lane == 0) redy[warp] = yv;
    __syncthreads();
    if (tid == 0) {
        float s = redy[0] + redy[1] + redy[2] + redy[3]
                + redy[4] + redy[5] + redy[6] + redy[7];
        *yt_sp = fmaf(__ldg(Wl), Y[(size_t)b * TS + t_step], s);
    }
    __syncthreads();

    // phase 5: fused LSTM pointwise update
    const float yt = *yt_sp;
    const int p = tid;
    const float* gr = g_GATES + (size_t)b * 4 * P_SZ;
    float ig = gr[p]            + yt * __ldg(W_ih + p)            + __ldg(b_ih + p)            + __ldg(b_hh + p);
    float fg = gr[P_SZ + p]     + yt * __ldg(W_ih + P_SZ + p)     + __ldg(b_ih + P_SZ + p)     + __ldg(b_hh + P_SZ + p);
    float gg = gr[2 * P_SZ + p] + yt * __ldg(W_ih + 2 * P_SZ + p) + __ldg(b_ih + 2 * P_SZ + p) + __ldg(b_hh + 2 * P_SZ + p);
    float og = gr[3 * P_SZ + p] + yt * __ldg(W_ih + 3 * P_SZ + p) + __ldg(b_ih + 3 * P_SZ + p) + __ldg(b_hh + 3 * P_SZ + p);

    float cold = g_HC[(size_t)b * 512 + 256 + p];
    float si = 1.0f / (1.0f + __expf(-ig));
    float sf = 1.0f / (1.0f + __expf(-fg));
    float so = 1.0f / (1.0f + __expf(-og));
    float cn = sf * cold + si * tanhf(gg);
    float hn = so * tanhf(cn);

    g_HC[(size_t)b * 512 + p]        = hn;
    g_HC[(size_t)b * 512 + 256 + p]  = cn;
    g_HCh[(size_t)b * 512 + p]       = __float2half_rn(hn);
    g_HCh[(size_t)b * 512 + 256 + p] = __float2half_rn(cn);
}

// ---------------- final head: out = ([h,ctx] @ Wb^T + b) @ vb^T + vb_b -----
__global__ void final_head_kernel(const float* __restrict__ Wb_w,
                                  const float* __restrict__ Wb_b,
                                  const float* __restrict__ vb_w,
                                  const float* __restrict__ vb_b,
                                  float* __restrict__ out)
{
    const int b   = blockIdx.x;
    const int tid = threadIdx.x;  // 0..255 = p
    __shared__ float hc_s[512];
    __shared__ float red[8];

    hc_s[tid]        = g_HC[(size_t)b * 512 + tid];        // h
    hc_s[P_SZ + tid] = g_CTX[(size_t)b * M_SZ + tid];      // ctx
    __syncthreads();

    const float* wr = Wb_w + (size_t)tid * (P_SZ + M_SZ);
    float t = __ldg(Wb_b + tid);
#pragma unroll 4
    for (int k = 0; k < 2 * P_SZ; k++)
        t = fmaf(__ldg(wr + k), hc_s[k], t);
    float val = __ldg(vb_w + tid) * t;

    int lane = tid & 31, warp = tid >> 5;
#pragma unroll
    for (int o = 16; o; o >>= 1) val += __shfl_xor_sync(0xffffffffu, val, o);
    if (lane == 0) red[warp] = val;
    __syncthreads();
    if (tid == 0)
        out[b] = vb_b[0] + red[0] + red[1] + red[2] + red[3]
                         + red[4] + red[5] + red[6] + red[7];
}

// ---------------- launch ----------------------------------------------------
extern "C" void kernel_launch(void* const* d_in, const int* in_sizes, int n_in,
                              void* d_out, int out_size)
{
    const float* Y    = (const float*)d_in[0];
    const float* X    = (const float*)d_in[1];
    const float* WU_d = (const float*)d_in[2];
    const float* v_d  = (const float*)d_in[3];
    const float* Wl   = (const float*)d_in[4];
    const float* W_ih = (const float*)d_in[5];
    const float* W_hh = (const float*)d_in[6];
    const float* b_ih = (const float*)d_in[7];
    const float* b_hh = (const float*)d_in[8];
    const float* Wb_w = (const float*)d_in[9];
    const float* Wb_b = (const float*)d_in[10];
    const float* vb_w = (const float*)d_in[11];
    const float* vb_b = (const float*)d_in[12];
    float* out = (float*)d_out;

    cudaFuncSetAttribute(attn_lstm_kernel,
                         cudaFuncAttributeMaxDynamicSharedMemorySize,
                         SMEM_ATTN_BYTES);

    // init h, c = 0 (fp32 + fp16 mirrors)
    init_hc_kernel<<<(B_SZ * 512 + 255) / 256, 256>>>();

    // X -> (b,t,m) fp16 ; weights -> fp16
    convert_x_kernel<<<(T_SZ * B_SZ) / 4, 256>>>(X);
    convert_w_kernel<<<1024, 256>>>(WU_d, W_hh);

    // A[b,t,m'] = X16 @ Wdx^T -> fp16 (HMMA)
    precompute_A_hmma<<<dim3((B_SZ * T_SZ) / 64, M_SZ / 64), 256>>>();

    for (int t = 0; t < TS; t++) {
        step_gemm_hmma<<<dim3(B_SZ / 64, 20), 256>>>();
        attn_lstm_kernel<<<B_SZ, 256, SMEM_ATTN_BYTES>>>(
            v_d, Wl, Y, W_ih, b_ih, b_hh, t);
    }

    final_head_kernel<<<B_SZ, 256>>>(Wb_w, Wb_b, vb_w, vb_b, out);
}

// round 7
// speedup vs baseline: 2.9475x; 1.1121x over previous
#include <cuda_runtime.h>
#include <cuda_fp16.h>
#include <cstdint>
#include <cstddef>

#define B_SZ 1024
#define T_SZ 128
#define M_SZ 256
#define P_SZ 256
#define TS   127   // T-1 recurrence steps

// ---------------- scratch (static device globals) ---------------------------
__device__ __half g_Ah[(size_t)B_SZ * T_SZ * M_SZ];  // (b,t,m) x-part preact fp16
__device__ __half g_X16[(size_t)B_SZ * T_SZ * M_SZ]; // (b,t,m) fp16 X
__device__ __half g_HCh[B_SZ * 512];                 // fp16 mirror of [h|c]
__device__ __half g_Wdd16[256 * 512];                // WU_d[:, :512] fp16
__device__ __half g_Whh16[1024 * 256];               // W_hh fp16
__device__ __half g_Wdx16[256 * 256];                // WU_d[:, 512:768] fp16
__device__ float  g_bias[4 * P_SZ];                  // b_ih + b_hh
__device__ float  g_U[B_SZ * M_SZ];                  // d-part preactivation
__device__ float  g_HC[B_SZ * 512];                  // fp32 master [h|c]
__device__ float  g_CTX[B_SZ * M_SZ];                // attention context (last step)
__device__ float  g_GATES[B_SZ * 4 * P_SZ];          // h @ W_hh^T

// ---------------- init ------------------------------------------------------
__global__ void init_hc_kernel() {
    int i = blockIdx.x * blockDim.x + threadIdx.x;
    if (i < B_SZ * 512) { g_HC[i] = 0.0f; g_HCh[i] = __float2half_rn(0.0f); }
}

// ---------------- X (t,b,m) fp32 -> g_X16 (b,t,m) fp16 ----------------------
__global__ void convert_x_kernel(const float* __restrict__ X) {
    int row = blockIdx.x * 4 + (threadIdx.x >> 6);   // row = t*B + b
    int c4  = (threadIdx.x & 63) * 4;
    int t = row >> 10;
    int b = row & 1023;
    float4 v = __ldg((const float4*)(X + (size_t)row * M_SZ + c4));
    __half2* dst = (__half2*)(g_X16 + ((size_t)(b << 7) + t) * M_SZ + c4);
    dst[0] = __floats2half2_rn(v.x, v.y);
    dst[1] = __floats2half2_rn(v.z, v.w);
}

// ---------------- weights -> fp16, fused bias -------------------------------
__global__ void convert_w_kernel(const float* __restrict__ WU_d,
                                 const float* __restrict__ W_hh,
                                 const float* __restrict__ b_ih,
                                 const float* __restrict__ b_hh) {
    int i = blockIdx.x * 256 + threadIdx.x;          // 0 .. 262143
    if (i < 256 * 512) {
        int r = i >> 9, k = i & 511;
        g_Wdd16[i] = __float2half_rn(WU_d[r * 768 + k]);
    }
    if (i < 256 * 256) {
        int r = i >> 8, k = i & 255;
        g_Wdx16[i] = __float2half_rn(WU_d[r * 768 + 512 + k]);
    }
    if (i < 1024 * 256) {
        g_Whh16[i] = __float2half_rn(W_hh[i]);
    }
    if (i < 1024) {
        g_bias[i] = b_ih[i] + b_hh[i];
    }
}

// ---------------- HMMA helpers ----------------------------------------------
__device__ __forceinline__ void ldsm4(uint32_t* r, uint32_t addr) {
    asm volatile("ldmatrix.sync.aligned.m8n8.x4.shared.b16 {%0,%1,%2,%3}, [%4];"
                 : "=r"(r[0]), "=r"(r[1]), "=r"(r[2]), "=r"(r[3]) : "r"(addr));
}

__device__ __forceinline__ void mma_16816(float* acc, const uint32_t* a,
                                          uint32_t b0, uint32_t b1) {
    asm volatile(
        "mma.sync.aligned.m16n8k16.row.col.f32.f16.f16.f32 "
        "{%0,%1,%2,%3},{%4,%5,%6,%7},{%8,%9},{%0,%1,%2,%3};"
        : "+f"(acc[0]), "+f"(acc[1]), "+f"(acc[2]), "+f"(acc[3])
        : "r"(a[0]), "r"(a[1]), "r"(a[2]), "r"(a[3]), "r"(b0), "r"(b1));
}

// 64x64 block tile, 256 threads (8 warps as 2m x 4n, warp tile 32x16).
#define HM_STRIDE 40
#define HM_BUFH   (64 * HM_STRIDE)
__device__ __forceinline__ void hmma_block(
    const __half* __restrict__ Ag0, int lda,
    const __half* __restrict__ Bg0, int ldb,
    int nit, float acc[2][2][4], __half* As, __half* Bs)
{
    const int tid  = threadIdx.x;
    const int lane = tid & 31, warp = tid >> 5;

    const __half* Ag = Ag0 + (size_t)(tid >> 2) * lda + (tid & 3) * 8;
    const __half* Bg = Bg0 + (size_t)(tid >> 2) * ldb + (tid & 3) * 8;
    const uint32_t st_off = ((tid >> 2) * HM_STRIDE + (tid & 3) * 8) * 2;
    const uint32_t as_base = (uint32_t)__cvta_generic_to_shared(As);
    const uint32_t bs_base = (uint32_t)__cvta_generic_to_shared(Bs);

    const int arow = (warp >> 2) * 32 + (lane & 7) + ((lane >> 3) & 1) * 8;
    const uint32_t a_off0 = (arow * HM_STRIDE + (lane >> 4) * 8) * 2;
    const uint32_t a_off1 = a_off0 + 16 * HM_STRIDE * 2;
    const int brow = (warp & 3) * 16 + (lane & 7) + (lane >> 4) * 8;
    const uint32_t b_off = (brow * HM_STRIDE + ((lane >> 3) & 1) * 8) * 2;

    *(uint4*)((char*)As + st_off) = *(const uint4*)Ag;
    *(uint4*)((char*)Bs + st_off) = *(const uint4*)Bg;
    __syncthreads();

    const uint32_t BUFB = HM_BUFH * 2;
    int buf = 0;
#pragma unroll 1
    for (int it = 0; it < nit; it++) {
        uint4 pa, pb;
        const bool more = (it + 1 < nit);
        if (more) {
            pa = *(const uint4*)(Ag + (it + 1) * 32);
            pb = *(const uint4*)(Bg + (it + 1) * 32);
        }
        const uint32_t ab = as_base + buf * BUFB;
        const uint32_t bb = bs_base + buf * BUFB;
#pragma unroll
        for (int kk = 0; kk < 2; kk++) {
            uint32_t af0[4], af1[4], bf[4];
            ldsm4(af0, ab + a_off0 + kk * 32);
            ldsm4(af1, ab + a_off1 + kk * 32);
            ldsm4(bf,  bb + b_off  + kk * 32);
            mma_16816(acc[0][0], af0, bf[0], bf[1]);
            mma_16816(acc[0][1], af0, bf[2], bf[3]);
            mma_16816(acc[1][0], af1, bf[0], bf[1]);
            mma_16816(acc[1][1], af1, bf[2], bf[3]);
        }
        if (more) {
            const int nb = buf ^ 1;
            *(uint4*)((char*)As + nb * BUFB + st_off) = pa;
            *(uint4*)((char*)Bs + nb * BUFB + st_off) = pb;
            __syncthreads();
            buf = nb;
        }
    }
}

// ---------------- per-step GEMMs via HMMA: U and GATES -----------------------
__global__ void step_gemm_hmma() {
    __shared__ __half As[2][HM_BUFH];
    __shared__ __half Bs[2][HM_BUFH];

    const int y = blockIdx.y;
    const __half* Bg; float* C; int ldb, ldc, col0, nit;
    if (y < 4) { Bg = g_Wdd16 + (size_t)y * 64 * 512;       ldb = 512; C = g_U;     ldc = 256;  col0 = y * 64;       nit = 16; }
    else       { Bg = g_Whh16 + (size_t)(y - 4) * 64 * 256; ldb = 256; C = g_GATES; ldc = 1024; col0 = (y - 4) * 64; nit = 8;  }

    float acc[2][2][4] = {};
    hmma_block(g_HCh + (size_t)blockIdx.x * 64 * 512, 512, Bg, ldb, nit,
               acc, &As[0][0], &Bs[0][0]);

    const int lane = threadIdx.x & 31, warp = threadIdx.x >> 5;
    const int gid = lane >> 2, tig = lane & 3;
    const int mrow0 = blockIdx.x * 64 + (warp >> 2) * 32;
    const int c0 = col0 + (warp & 3) * 16;
#pragma unroll
    for (int mt = 0; mt < 2; mt++)
#pragma unroll
        for (int nt = 0; nt < 2; nt++) {
            const float* a = acc[mt][nt];
            const int r  = mrow0 + mt * 16 + gid;
            const int cc = c0 + nt * 8 + tig * 2;
            *(float2*)&C[(size_t)r * ldc + cc]       = make_float2(a[0], a[1]);
            *(float2*)&C[(size_t)(r + 8) * ldc + cc] = make_float2(a[2], a[3]);
        }
}

// ---------------- A precompute via HMMA: g_Ah = g_X16 @ Wdx^T (fp16 out) ----
__global__ void precompute_A_hmma() {
    __shared__ __half As[2][HM_BUFH];
    __shared__ __half Bs[2][HM_BUFH];

    float acc[2][2][4] = {};
    hmma_block(g_X16 + (size_t)blockIdx.x * 64 * 256, 256,
               g_Wdx16 + (size_t)blockIdx.y * 64 * 256, 256, 8,
               acc, &As[0][0], &Bs[0][0]);

    const int lane = threadIdx.x & 31, warp = threadIdx.x >> 5;
    const int gid = lane >> 2, tig = lane & 3;
    const int mrow0 = blockIdx.x * 64 + (warp >> 2) * 32;
    const int c0 = blockIdx.y * 64 + (warp & 3) * 16;
#pragma unroll
    for (int mt = 0; mt < 2; mt++)
#pragma unroll
        for (int nt = 0; nt < 2; nt++) {
            const float* a = acc[mt][nt];
            const int r  = mrow0 + mt * 16 + gid;
            const int cc = c0 + nt * 8 + tig * 2;
            *(__half2*)&g_Ah[(size_t)r * 256 + cc]       = __floats2half2_rn(a[0], a[1]);
            *(__half2*)&g_Ah[(size_t)(r + 8) * 256 + cc] = __floats2half2_rn(a[2], a[3]);
        }
}

// ---------------- fused attention (online softmax) + LSTM step --------------
// one block per batch, 256 threads (8 warps); single pass over A and X
__global__ void __launch_bounds__(256)
attn_lstm_kernel(const float* __restrict__ v_d,
                 const float* __restrict__ Wl,
                 const float* __restrict__ Y,
                 const float* __restrict__ W_ih,
                 int t_step)
{
    __shared__ float ctx_ws[8][M_SZ];
    __shared__ float wM[8], wS[8], redy[8];
    __shared__ float yt_s;

    const int b    = blockIdx.x;
    const int tid  = threadIdx.x;     // 0..255
    const int lane = tid & 31;
    const int warp = tid >> 5;

    // per-lane u,v slices in registers (m = lane*8 .. lane*8+7), reused 16x
    float ureg[8], vreg[8];
    {
        const int mb = lane * 8;
        float4 ua = __ldg((const float4*)(g_U + b * M_SZ + mb));
        float4 ub = __ldg((const float4*)(g_U + b * M_SZ + mb + 4));
        float4 va = __ldg((const float4*)(v_d + mb));
        float4 vb = __ldg((const float4*)(v_d + mb + 4));
        ureg[0] = ua.x; ureg[1] = ua.y; ureg[2] = ua.z; ureg[3] = ua.w;
        ureg[4] = ub.x; ureg[5] = ub.y; ureg[6] = ub.z; ureg[7] = ub.w;
        vreg[0] = va.x; vreg[1] = va.y; vreg[2] = va.z; vreg[3] = va.w;
        vreg[4] = vb.x; vreg[5] = vb.y; vreg[6] = vb.z; vreg[7] = vb.w;
    }

    // single pass: logits + online softmax + ctx accumulation
    const float4* Arow = (const float4*)(g_Ah + (size_t)b * T_SZ * M_SZ) + lane;
    const float4* Xrow = (const float4*)(g_X16 + (size_t)b * T_SZ * M_SZ) + lane;

    float C[8] = {0, 0, 0, 0, 0, 0, 0, 0};
    float Mx = -1e30f, S = 0.0f;

    float4 a_cur = __ldg(Arow + (size_t)warp * 32);
    float4 x_cur = __ldg(Xrow + (size_t)warp * 32);

#pragma unroll
    for (int i = 0; i < 16; i++) {
        const int t = warp + i * 8;
        float4 a_nx, x_nx;
        if (i < 15) {
            a_nx = __ldg(Arow + (size_t)(t + 8) * 32);
            x_nx = __ldg(Xrow + (size_t)(t + 8) * 32);
        }

        // logit partial from this lane's 8 m-values
        const __half2* ahp = (const __half2*)&a_cur;
        float acc = 0.0f;
        float xv[8];
#pragma unroll
        for (int j = 0; j < 4; j++) {
            float2 av = __half22float2(ahp[j]);
            float x0 = ureg[2 * j]     + av.x;
            float x1 = ureg[2 * j + 1] + av.y;
            float t0, t1;
            asm("tanh.approx.f32 %0, %1;" : "=f"(t0) : "f"(x0));
            asm("tanh.approx.f32 %0, %1;" : "=f"(t1) : "f"(x1));
            acc = fmaf(vreg[2 * j],     t0, acc);
            acc = fmaf(vreg[2 * j + 1], t1, acc);
            float2 xf = __half22float2(((const __half2*)&x_cur)[j]);
            xv[2 * j] = xf.x; xv[2 * j + 1] = xf.y;
        }
#pragma unroll
        for (int o = 16; o; o >>= 1) acc += __shfl_xor_sync(0xffffffffu, acc, o);
        // acc = l_t, uniform across warp

        if (acc <= Mx) {                 // warp-uniform branch
            float e = __expf(acc - Mx);
            S += e;
#pragma unroll
            for (int j = 0; j < 8; j++) C[j] = fmaf(e, xv[j], C[j]);
        } else {
            float f = __expf(Mx - acc);
            S = fmaf(S, f, 1.0f);
#pragma unroll
            for (int j = 0; j < 8; j++) C[j] = fmaf(C[j], f, xv[j]);
            Mx = acc;
        }

        a_cur = a_nx; x_cur = x_nx;
    }

    // per-warp results -> smem
    if (lane == 0) { wM[warp] = Mx; wS[warp] = S; }
    *(float4*)&ctx_ws[warp][lane * 8]     = make_float4(C[0], C[1], C[2], C[3]);
    *(float4*)&ctx_ws[warp][lane * 8 + 4] = make_float4(C[4], C[5], C[6], C[7]);
    __syncthreads();

    // combine warps: global max, rescale, normalize
    float Mg = wM[0];
#pragma unroll
    for (int w = 1; w < 8; w++) Mg = fmaxf(Mg, wM[w]);
    float fw[8], Sg = 0.0f;
#pragma unroll
    for (int w = 0; w < 8; w++) { fw[w] = __expf(wM[w] - Mg); Sg = fmaf(wS[w], fw[w], Sg); }
    float c = 0.0f;
#pragma unroll
    for (int w = 0; w < 8; w++) c = fmaf(fw[w], ctx_ws[w][tid], c);
    c /= Sg;

    if (t_step == TS - 1) g_CTX[b * M_SZ + tid] = c;

    // y_tilde = Wl[0]*y_t + sum_m Wl[1+m]*ctx[m]
    float yv = __ldg(Wl + 1 + tid) * c;
#pragma unroll
    for (int o = 16; o; o >>= 1) yv += __shfl_xor_sync(0xffffffffu, yv, o);
    if (lane == 0) redy[warp] = yv;
    __syncthreads();
    if (tid == 0) {
        float s = redy[0] + redy[1] + redy[2] + redy[3]
                + redy[4] + redy[5] + redy[6] + redy[7];
        yt_s = fmaf(__ldg(Wl), Y[(size_t)b * TS + t_step], s);
    }
    __syncthreads();

    // fused LSTM pointwise update
    const float yt = yt_s;
    const int p = tid;
    const float* gr = g_GATES + (size_t)b * 4 * P_SZ;
    float ig = gr[p]            + yt * __ldg(W_ih + p)            + g_bias[p];
    float fg = gr[P_SZ + p]     + yt * __ldg(W_ih + P_SZ + p)     + g_bias[P_SZ + p];
    float gg = gr[2 * P_SZ + p] + yt * __ldg(W_ih + 2 * P_SZ + p) + g_bias[2 * P_SZ + p];
    float og = gr[3 * P_SZ + p] + yt * __ldg(W_ih + 3 * P_SZ + p) + g_bias[3 * P_SZ + p];

    float cold = g_HC[(size_t)b * 512 + 256 + p];
    float si = 1.0f / (1.0f + __expf(-ig));
    float sf = 1.0f / (1.0f + __expf(-fg));
    float so = 1.0f / (1.0f + __expf(-og));
    float cn = sf * cold + si * tanhf(gg);
    float hn = so * tanhf(cn);

    g_HC[(size_t)b * 512 + p]        = hn;
    g_HC[(size_t)b * 512 + 256 + p]  = cn;
    g_HCh[(size_t)b * 512 + p]       = __float2half_rn(hn);
    g_HCh[(size_t)b * 512 + 256 + p] = __float2half_rn(cn);
}

// ---------------- final head: out = ([h,ctx] @ Wb^T + b) @ vb^T + vb_b -----
__global__ void final_head_kernel(const float* __restrict__ Wb_w,
                                  const float* __restrict__ Wb_b,
                                  const float* __restrict__ vb_w,
                                  const float* __restrict__ vb_b,
                                  float* __restrict__ out)
{
    const int b   = blockIdx.x;
    const int tid = threadIdx.x;  // 0..255 = p
    __shared__ float hc_s[512];
    __shared__ float red[8];

    hc_s[tid]        = g_HC[(size_t)b * 512 + tid];        // h
    hc_s[P_SZ + tid] = g_CTX[(size_t)b * M_SZ + tid];      // ctx
    __syncthreads();

    const float* wr = Wb_w + (size_t)tid * (P_SZ + M_SZ);
    float t = __ldg(Wb_b + tid);
#pragma unroll 4
    for (int k = 0; k < 2 * P_SZ; k++)
        t = fmaf(__ldg(wr + k), hc_s[k], t);
    float val = __ldg(vb_w + tid) * t;

    int lane = tid & 31, warp = tid >> 5;
#pragma unroll
    for (int o = 16; o; o >>= 1) val += __shfl_xor_sync(0xffffffffu, val, o);
    if (lane == 0) red[warp] = val;
    __syncthreads();
    if (tid == 0)
        out[b] = vb_b[0] + red[0] + red[1] + red[2] + red[3]
                         + red[4] + red[5] + red[6] + red[7];
}

// ---------------- launch ----------------------------------------------------
extern "C" void kernel_launch(void* const* d_in, const int* in_sizes, int n_in,
                              void* d_out, int out_size)
{
    const float* Y    = (const float*)d_in[0];
    const float* X    = (const float*)d_in[1];
    const float* WU_d = (const float*)d_in[2];
    const float* v_d  = (const float*)d_in[3];
    const float* Wl   = (const float*)d_in[4];
    const float* W_ih = (const float*)d_in[5];
    const float* W_hh = (const float*)d_in[6];
    const float* b_ih = (const float*)d_in[7];
    const float* b_hh = (const float*)d_in[8];
    const float* Wb_w = (const float*)d_in[9];
    const float* Wb_b = (const float*)d_in[10];
    const float* vb_w = (const float*)d_in[11];
    const float* vb_b = (const float*)d_in[12];
    float* out = (float*)d_out;

    // init h, c = 0 (fp32 + fp16 mirrors)
    init_hc_kernel<<<(B_SZ * 512 + 255) / 256, 256>>>();

    // X -> (b,t,m) fp16 ; weights -> fp16 ; fused bias
    convert_x_kernel<<<(T_SZ * B_SZ) / 4, 256>>>(X);
    convert_w_kernel<<<1024, 256>>>(WU_d, W_hh, b_ih, b_hh);

    // A[b,t,m'] = X16 @ Wdx^T -> fp16 (HMMA)
    precompute_A_hmma<<<dim3((B_SZ * T_SZ) / 64, M_SZ / 64), 256>>>();

    for (int t = 0; t < TS; t++) {
        step_gemm_hmma<<<dim3(B_SZ / 64, 20), 256>>>();
        attn_lstm_kernel<<<B_SZ, 256>>>(v_d, Wl, Y, W_ih, t);
    }

    final_head_kernel<<<B_SZ, 256>>>(Wb_w, Wb_b, vb_w, vb_b, out);
}

// round 8
// speedup vs baseline: 3.1310x; 1.0622x over previous
#include <cuda_runtime.h>
#include <cuda_fp16.h>
#include <cstdint>
#include <cstddef>

#define B_SZ 1024
#define T_SZ 128
#define M_SZ 256
#define P_SZ 256
#define TS   127   // T-1 recurrence steps

// ---------------- scratch (static device globals) ---------------------------
// interleaved per-(b,t) row: [ A[0..255] | X[0..255] ] fp16, stride 512
__device__ __half g_AX[(size_t)B_SZ * T_SZ * 512];
__device__ __half g_HCh[B_SZ * 512];                 // fp16 mirror of [h|c]
__device__ __half g_Wdd16[256 * 512];                // WU_d[:, :512] fp16
__device__ __half g_Whh16[1024 * 256];               // W_hh fp16
__device__ __half g_Wdx16[256 * 256];                // WU_d[:, 512:768] fp16
__device__ float  g_bias[4 * P_SZ];                  // b_ih + b_hh
__device__ float  g_U1[B_SZ * M_SZ];                 // d-part preact, K 0:256
__device__ float  g_U2[B_SZ * M_SZ];                 // d-part preact, K 256:512
__device__ float  g_HC[B_SZ * 512];                  // fp32 master [h|c]
__device__ float  g_CTX[B_SZ * M_SZ];                // attention context (last step)
__device__ float  g_GATES[B_SZ * 4 * P_SZ];          // h @ W_hh^T

// ---------------- init ------------------------------------------------------
__global__ void init_hc_kernel() {
    int i = blockIdx.x * blockDim.x + threadIdx.x;
    if (i < B_SZ * 512) { g_HC[i] = 0.0f; g_HCh[i] = __float2half_rn(0.0f); }
}

// ---------------- X (t,b,m) fp32 -> g_AX[b,t, 256+m] fp16 -------------------
__global__ void convert_x_kernel(const float* __restrict__ X) {
    int row = blockIdx.x * 4 + (threadIdx.x >> 6);   // row = t*B + b
    int c4  = (threadIdx.x & 63) * 4;
    int t = row >> 10;
    int b = row & 1023;
    float4 v = __ldg((const float4*)(X + (size_t)row * M_SZ + c4));
    __half2* dst = (__half2*)(g_AX + ((size_t)(b << 7) + t) * 512 + 256 + c4);
    dst[0] = __floats2half2_rn(v.x, v.y);
    dst[1] = __floats2half2_rn(v.z, v.w);
}

// ---------------- weights -> fp16, fused bias -------------------------------
__global__ void convert_w_kernel(const float* __restrict__ WU_d,
                                 const float* __restrict__ W_hh,
                                 const float* __restrict__ b_ih,
                                 const float* __restrict__ b_hh) {
    int i = blockIdx.x * 256 + threadIdx.x;          // 0 .. 262143
    if (i < 256 * 512) {
        int r = i >> 9, k = i & 511;
        g_Wdd16[i] = __float2half_rn(WU_d[r * 768 + k]);
    }
    if (i < 256 * 256) {
        int r = i >> 8, k = i & 255;
        g_Wdx16[i] = __float2half_rn(WU_d[r * 768 + 512 + k]);
    }
    if (i < 1024 * 256) {
        g_Whh16[i] = __float2half_rn(W_hh[i]);
    }
    if (i < 1024) {
        g_bias[i] = b_ih[i] + b_hh[i];
    }
}

// ---------------- HMMA helpers ----------------------------------------------
__device__ __forceinline__ void ldsm4(uint32_t* r, uint32_t addr) {
    asm volatile("ldmatrix.sync.aligned.m8n8.x4.shared.b16 {%0,%1,%2,%3}, [%4];"
                 : "=r"(r[0]), "=r"(r[1]), "=r"(r[2]), "=r"(r[3]) : "r"(addr));
}

__device__ __forceinline__ void mma_16816(float* acc, const uint32_t* a,
                                          uint32_t b0, uint32_t b1) {
    asm volatile(
        "mma.sync.aligned.m16n8k16.row.col.f32.f16.f16.f32 "
        "{%0,%1,%2,%3},{%4,%5,%6,%7},{%8,%9},{%0,%1,%2,%3};"
        : "+f"(acc[0]), "+f"(acc[1]), "+f"(acc[2]), "+f"(acc[3])
        : "r"(a[0]), "r"(a[1]), "r"(a[2]), "r"(a[3]), "r"(b0), "r"(b1));
}

// 64x64 block tile, 256 threads (8 warps as 2m x 4n, warp tile 32x16).
#define HM_STRIDE 40
#define HM_BUFH   (64 * HM_STRIDE)
__device__ __forceinline__ void hmma_block(
    const __half* __restrict__ Ag0, int lda,
    const __half* __restrict__ Bg0, int ldb,
    int nit, float acc[2][2][4], __half* As, __half* Bs)
{
    const int tid  = threadIdx.x;
    const int lane = tid & 31, warp = tid >> 5;

    const __half* Ag = Ag0 + (size_t)(tid >> 2) * lda + (tid & 3) * 8;
    const __half* Bg = Bg0 + (size_t)(tid >> 2) * ldb + (tid & 3) * 8;
    const uint32_t st_off = ((tid >> 2) * HM_STRIDE + (tid & 3) * 8) * 2;
    const uint32_t as_base = (uint32_t)__cvta_generic_to_shared(As);
    const uint32_t bs_base = (uint32_t)__cvta_generic_to_shared(Bs);

    const int arow = (warp >> 2) * 32 + (lane & 7) + ((lane >> 3) & 1) * 8;
    const uint32_t a_off0 = (arow * HM_STRIDE + (lane >> 4) * 8) * 2;
    const uint32_t a_off1 = a_off0 + 16 * HM_STRIDE * 2;
    const int brow = (warp & 3) * 16 + (lane & 7) + (lane >> 4) * 8;
    const uint32_t b_off = (brow * HM_STRIDE + ((lane >> 3) & 1) * 8) * 2;

    *(uint4*)((char*)As + st_off) = *(const uint4*)Ag;
    *(uint4*)((char*)Bs + st_off) = *(const uint4*)Bg;
    __syncthreads();

    const uint32_t BUFB = HM_BUFH * 2;
    int buf = 0;
#pragma unroll 1
    for (int it = 0; it < nit; it++) {
        uint4 pa, pb;
        const bool more = (it + 1 < nit);
        if (more) {
            pa = *(const uint4*)(Ag + (it + 1) * 32);
            pb = *(const uint4*)(Bg + (it + 1) * 32);
        }
        const uint32_t ab = as_base + buf * BUFB;
        const uint32_t bb = bs_base + buf * BUFB;
#pragma unroll
        for (int kk = 0; kk < 2; kk++) {
            uint32_t af0[4], af1[4], bf[4];
            ldsm4(af0, ab + a_off0 + kk * 32);
            ldsm4(af1, ab + a_off1 + kk * 32);
            ldsm4(bf,  bb + b_off  + kk * 32);
            mma_16816(acc[0][0], af0, bf[0], bf[1]);
            mma_16816(acc[0][1], af0, bf[2], bf[3]);
            mma_16816(acc[1][0], af1, bf[0], bf[1]);
            mma_16816(acc[1][1], af1, bf[2], bf[3]);
        }
        if (more) {
            const int nb = buf ^ 1;
            *(uint4*)((char*)As + nb * BUFB + st_off) = pa;
            *(uint4*)((char*)Bs + nb * BUFB + st_off) = pb;
            __syncthreads();
            buf = nb;
        }
    }
}

// ---------------- per-step GEMMs via HMMA, uniform K=256 tiles ---------------
// grid (16, 24): y 0..3 -> U1 (K 0:256); y 4..7 -> U2 (K 256:512);
//                y 8..23 -> GATES (K=256)
__global__ void step_gemm_hmma() {
    __shared__ __half As[2][HM_BUFH];
    __shared__ __half Bs[2][HM_BUFH];

    const int y = blockIdx.y;
    const __half* Bg; float* C; int ldb, ldc, col0, koff;
    if (y < 8) {
        const int half = y >> 2;                 // 0 -> U1, 1 -> U2
        koff = half * 256;
        Bg   = g_Wdd16 + (size_t)(y & 3) * 64 * 512 + koff;
        ldb  = 512; C = half ? g_U2 : g_U1; ldc = 256; col0 = (y & 3) * 64;
    } else {
        koff = 0;
        Bg   = g_Whh16 + (size_t)(y - 8) * 64 * 256;
        ldb  = 256; C = g_GATES; ldc = 1024; col0 = (y - 8) * 64;
    }

    float acc[2][2][4] = {};
    hmma_block(g_HCh + (size_t)blockIdx.x * 64 * 512 + koff, 512, Bg, ldb, 8,
               acc, &As[0][0], &Bs[0][0]);

    const int lane = threadIdx.x & 31, warp = threadIdx.x >> 5;
    const int gid = lane >> 2, tig = lane & 3;
    const int mrow0 = blockIdx.x * 64 + (warp >> 2) * 32;
    const int c0 = col0 + (warp & 3) * 16;
#pragma unroll
    for (int mt = 0; mt < 2; mt++)
#pragma unroll
        for (int nt = 0; nt < 2; nt++) {
            const float* a = acc[mt][nt];
            const int r  = mrow0 + mt * 16 + gid;
            const int cc = c0 + nt * 8 + tig * 2;
            *(float2*)&C[(size_t)r * ldc + cc]       = make_float2(a[0], a[1]);
            *(float2*)&C[(size_t)(r + 8) * ldc + cc] = make_float2(a[2], a[3]);
        }
}

// ---------------- A precompute via HMMA: A half of g_AX ----------------------
// input X = g_AX[:, 256:] (lda=512), output A -> g_AX[:, :256]
__global__ void precompute_A_hmma() {
    __shared__ __half As[2][HM_BUFH];
    __shared__ __half Bs[2][HM_BUFH];

    float acc[2][2][4] = {};
    hmma_block(g_AX + (size_t)blockIdx.x * 64 * 512 + 256, 512,
               g_Wdx16 + (size_t)blockIdx.y * 64 * 256, 256, 8,
               acc, &As[0][0], &Bs[0][0]);

    const int lane = threadIdx.x & 31, warp = threadIdx.x >> 5;
    const int gid = lane >> 2, tig = lane & 3;
    const int mrow0 = blockIdx.x * 64 + (warp >> 2) * 32;
    const int c0 = blockIdx.y * 64 + (warp & 3) * 16;
#pragma unroll
    for (int mt = 0; mt < 2; mt++)
#pragma unroll
        for (int nt = 0; nt < 2; nt++) {
            const float* a = acc[mt][nt];
            const int r  = mrow0 + mt * 16 + gid;
            const int cc = c0 + nt * 8 + tig * 2;
            *(__half2*)&g_AX[(size_t)r * 512 + cc]       = __floats2half2_rn(a[0], a[1]);
            *(__half2*)&g_AX[(size_t)(r + 8) * 512 + cc] = __floats2half2_rn(a[2], a[3]);
        }
}

// ---------------- fused attention (online softmax) + LSTM step --------------
// one block per batch, 256 threads (8 warps); single pass over interleaved AX
__global__ void __launch_bounds__(256, 4)
attn_lstm_kernel(const float* __restrict__ v_d,
                 const float* __restrict__ Wl,
                 const float* __restrict__ Y,
                 const float* __restrict__ W_ih,
                 int t_step)
{
    __shared__ float ctx_ws[8][M_SZ];
    __shared__ float wM[8], wS[8], redy[8];
    __shared__ float yt_s;

    const int b    = blockIdx.x;
    const int tid  = threadIdx.x;     // 0..255
    const int lane = tid & 31;
    const int warp = tid >> 5;

    // per-lane u,v slices in registers (m = lane*8 .. lane*8+7), reused 16x
    float ureg[8], vreg[8];
    {
        const int mb = lane * 8;
        float4 u1a = __ldg((const float4*)(g_U1 + b * M_SZ + mb));
        float4 u1b = __ldg((const float4*)(g_U1 + b * M_SZ + mb + 4));
        float4 u2a = __ldg((const float4*)(g_U2 + b * M_SZ + mb));
        float4 u2b = __ldg((const float4*)(g_U2 + b * M_SZ + mb + 4));
        float4 va  = __ldg((const float4*)(v_d + mb));
        float4 vb  = __ldg((const float4*)(v_d + mb + 4));
        ureg[0] = u1a.x + u2a.x; ureg[1] = u1a.y + u2a.y;
        ureg[2] = u1a.z + u2a.z; ureg[3] = u1a.w + u2a.w;
        ureg[4] = u1b.x + u2b.x; ureg[5] = u1b.y + u2b.y;
        ureg[6] = u1b.z + u2b.z; ureg[7] = u1b.w + u2b.w;
        vreg[0] = va.x; vreg[1] = va.y; vreg[2] = va.z; vreg[3] = va.w;
        vreg[4] = vb.x; vreg[5] = vb.y; vreg[6] = vb.z; vreg[7] = vb.w;
    }

    // single pass: logits + online softmax + ctx accumulation
    const float4* AXrow = (const float4*)(g_AX + (size_t)b * T_SZ * 512) + lane;

    float C[8] = {0, 0, 0, 0, 0, 0, 0, 0};
    float Mx = -1e30f, S = 0.0f;

    float4 a_cur = __ldg(AXrow + (size_t)warp * 64);
    float4 x_cur = __ldg(AXrow + (size_t)warp * 64 + 32);

#pragma unroll
    for (int i = 0; i < 16; i++) {
        const int t = warp + i * 8;
        float4 a_nx, x_nx;
        if (i < 15) {
            a_nx = __ldg(AXrow + (size_t)(t + 8) * 64);
            x_nx = __ldg(AXrow + (size_t)(t + 8) * 64 + 32);
        }

        // logit partial from this lane's 8 m-values
        const __half2* ahp = (const __half2*)&a_cur;
        float acc = 0.0f;
        float xv[8];
#pragma unroll
        for (int j = 0; j < 4; j++) {
            float2 av = __half22float2(ahp[j]);
            float x0 = ureg[2 * j]     + av.x;
            float x1 = ureg[2 * j + 1] + av.y;
            float t0, t1;
            asm("tanh.approx.f32 %0, %1;" : "=f"(t0) : "f"(x0));
            asm("tanh.approx.f32 %0, %1;" : "=f"(t1) : "f"(x1));
            acc = fmaf(vreg[2 * j],     t0, acc);
            acc = fmaf(vreg[2 * j + 1], t1, acc);
            float2 xf = __half22float2(((const __half2*)&x_cur)[j]);
            xv[2 * j] = xf.x; xv[2 * j + 1] = xf.y;
        }
#pragma unroll
        for (int o = 16; o; o >>= 1) acc += __shfl_xor_sync(0xffffffffu, acc, o);
        // acc = l_t, uniform across warp

        if (acc <= Mx) {                 // warp-uniform branch
            float e = __expf(acc - Mx);
            S += e;
#pragma unroll
            for (int j = 0; j < 8; j++) C[j] = fmaf(e, xv[j], C[j]);
        } else {
            float f = __expf(Mx - acc);
            S = fmaf(S, f, 1.0f);
#pragma unroll
            for (int j = 0; j < 8; j++) C[j] = fmaf(C[j], f, xv[j]);
            Mx = acc;
        }

        a_cur = a_nx; x_cur = x_nx;
    }

    // per-warp results -> smem
    if (lane == 0) { wM[warp] = Mx; wS[warp] = S; }
    *(float4*)&ctx_ws[warp][lane * 8]     = make_float4(C[0], C[1], C[2], C[3]);
    *(float4*)&ctx_ws[warp][lane * 8 + 4] = make_float4(C[4], C[5], C[6], C[7]);
    __syncthreads();

    // combine warps: global max, rescale, normalize
    float Mg = wM[0];
#pragma unroll
    for (int w = 1; w < 8; w++) Mg = fmaxf(Mg, wM[w]);
    float fw[8], Sg = 0.0f;
#pragma unroll
    for (int w = 0; w < 8; w++) { fw[w] = __expf(wM[w] - Mg); Sg = fmaf(wS[w], fw[w], Sg); }
    float c = 0.0f;
#pragma unroll
    for (int w = 0; w < 8; w++) c = fmaf(fw[w], ctx_ws[w][tid], c);
    c /= Sg;

    if (t_step == TS - 1) g_CTX[b * M_SZ + tid] = c;

    // y_tilde = Wl[0]*y_t + sum_m Wl[1+m]*ctx[m]
    float yv = __ldg(Wl + 1 + tid) * c;
#pragma unroll
    for (int o = 16; o; o >>= 1) yv += __shfl_xor_sync(0xffffffffu, yv, o);
    if (lane == 0) redy[warp] = yv;
    __syncthreads();
    if (tid == 0) {
        float s = redy[0] + redy[1] + redy[2] + redy[3]
                + redy[4] + redy[5] + redy[6] + redy[7];
        yt_s = fmaf(__ldg(Wl), Y[(size_t)b * TS + t_step], s);
    }
    __syncthreads();

    // fused LSTM pointwise update
    const float yt = yt_s;
    const int p = tid;
    const float* gr = g_GATES + (size_t)b * 4 * P_SZ;
    float ig = gr[p]            + yt * __ldg(W_ih + p)            + g_bias[p];
    float fg = gr[P_SZ + p]     + yt * __ldg(W_ih + P_SZ + p)     + g_bias[P_SZ + p];
    float gg = gr[2 * P_SZ + p] + yt * __ldg(W_ih + 2 * P_SZ + p) + g_bias[2 * P_SZ + p];
    float og = gr[3 * P_SZ + p] + yt * __ldg(W_ih + 3 * P_SZ + p) + g_bias[3 * P_SZ + p];

    float cold = g_HC[(size_t)b * 512 + 256 + p];
    float si = 1.0f / (1.0f + __expf(-ig));
    float sf = 1.0f / (1.0f + __expf(-fg));
    float so = 1.0f / (1.0f + __expf(-og));
    float cn = sf * cold + si * tanhf(gg);
    float hn = so * tanhf(cn);

    g_HC[(size_t)b * 512 + p]        = hn;
    g_HC[(size_t)b * 512 + 256 + p]  = cn;
    g_HCh[(size_t)b * 512 + p]       = __float2half_rn(hn);
    g_HCh[(size_t)b * 512 + 256 + p] = __float2half_rn(cn);
}

// ---------------- final head: out = ([h,ctx] @ Wb^T + b) @ vb^T + vb_b -----
__global__ void final_head_kernel(const float* __restrict__ Wb_w,
                                  const float* __restrict__ Wb_b,
                                  const float* __restrict__ vb_w,
                                  const float* __restrict__ vb_b,
                                  float* __restrict__ out)
{
    const int b   = blockIdx.x;
    const int tid = threadIdx.x;  // 0..255 = p
    __shared__ float hc_s[512];
    __shared__ float red[8];

    hc_s[tid]        = g_HC[(size_t)b * 512 + tid];        // h
    hc_s[P_SZ + tid] = g_CTX[(size_t)b * M_SZ + tid];      // ctx
    __syncthreads();

    const float* wr = Wb_w + (size_t)tid * (P_SZ + M_SZ);
    float t = __ldg(Wb_b + tid);
#pragma unroll 4
    for (int k = 0; k < 2 * P_SZ; k++)
        t = fmaf(__ldg(wr + k), hc_s[k], t);
    float val = __ldg(vb_w + tid) * t;

    int lane = tid & 31, warp = tid >> 5;
#pragma unroll
    for (int o = 16; o; o >>= 1) val += __shfl_xor_sync(0xffffffffu, val, o);
    if (lane == 0) red[warp] = val;
    __syncthreads();
    if (tid == 0)
        out[b] = vb_b[0] + red[0] + red[1] + red[2] + red[3]
                         + red[4] + red[5] + red[6] + red[7];
}

// ---------------- launch ----------------------------------------------------
extern "C" void kernel_launch(void* const* d_in, const int* in_sizes, int n_in,
                              void* d_out, int out_size)
{
    const float* Y    = (const float*)d_in[0];
    const float* X    = (const float*)d_in[1];
    const float* WU_d = (const float*)d_in[2];
    const float* v_d  = (const float*)d_in[3];
    const float* Wl   = (const float*)d_in[4];
    const float* W_ih = (const float*)d_in[5];
    const float* W_hh = (const float*)d_in[6];
    const float* b_ih = (const float*)d_in[7];
    const float* b_hh = (const float*)d_in[8];
    const float* Wb_w = (const float*)d_in[9];
    const float* Wb_b = (const float*)d_in[10];
    const float* vb_w = (const float*)d_in[11];
    const float* vb_b = (const float*)d_in[12];
    float* out = (float*)d_out;

    // init h, c = 0 (fp32 + fp16 mirrors)
    init_hc_kernel<<<(B_SZ * 512 + 255) / 256, 256>>>();

    // X -> interleaved AX (X half) fp16 ; weights -> fp16 ; fused bias
    convert_x_kernel<<<(T_SZ * B_SZ) / 4, 256>>>(X);
    convert_w_kernel<<<1024, 256>>>(WU_d, W_hh, b_ih, b_hh);

    // A half of g_AX = X16 @ Wdx^T (HMMA)
    precompute_A_hmma<<<dim3((B_SZ * T_SZ) / 64, M_SZ / 64), 256>>>();

    for (int t = 0; t < TS; t++) {
        step_gemm_hmma<<<dim3(B_SZ / 64, 24), 256>>>();
        attn_lstm_kernel<<<B_SZ, 256>>>(v_d, Wl, Y, W_ih, t);
    }

    final_head_kernel<<<B_SZ, 256>>>(Wb_w, Wb_b, vb_w, vb_b, out);
}

// round 10
// speedup vs baseline: 3.1869x; 1.0179x over previous
#include <cuda_runtime.h>
#include <cuda_fp16.h>
#include <cstdint>
#include <cstddef>

#define B_SZ 1024
#define T_SZ 128
#define M_SZ 256
#define P_SZ 256
#define TS   127   // T-1 recurrence steps

// ---------------- scratch (static device globals) ---------------------------
// interleaved per-(b,t) row: [ A[0..255] | X[0..255] ] fp16, stride 512
__device__ __half g_AX[(size_t)B_SZ * T_SZ * 512];
__device__ __half g_HCh[B_SZ * 512];                 // fp16 mirror of [h|c]
__device__ __half g_Wdd16[256 * 512];                // WU_d[:, :512] fp16
__device__ __half g_Whh16[1024 * 256];               // W_hh fp16
__device__ __half g_Wdx16[256 * 256];                // WU_d[:, 512:768] fp16
__device__ float  g_bias[4 * P_SZ];                  // b_ih + b_hh
__device__ float  g_U1[B_SZ * M_SZ];                 // d-part preact, K 0:256
__device__ float  g_U2[B_SZ * M_SZ];                 // d-part preact, K 256:512
__device__ float  g_HC[B_SZ * 512];                  // fp32 master [h|c]
__device__ float  g_CTX[B_SZ * M_SZ];                // attention context (last step)
__device__ float  g_GATES[B_SZ * 4 * P_SZ];          // h @ W_hh^T

// ---------------- init ------------------------------------------------------
__global__ void init_hc_kernel() {
    int i = blockIdx.x * blockDim.x + threadIdx.x;
    if (i < B_SZ * 512) { g_HC[i] = 0.0f; g_HCh[i] = __float2half_rn(0.0f); }
}

// ---------------- X (t,b,m) fp32 -> g_AX[b,t, 256+m] fp16 -------------------
__global__ void convert_x_kernel(const float* __restrict__ X) {
    int row = blockIdx.x * 4 + (threadIdx.x >> 6);   // row = t*B + b
    int c4  = (threadIdx.x & 63) * 4;
    int t = row >> 10;
    int b = row & 1023;
    float4 v = __ldg((const float4*)(X + (size_t)row * M_SZ + c4));
    __half2* dst = (__half2*)(g_AX + ((size_t)(b << 7) + t) * 512 + 256 + c4);
    dst[0] = __floats2half2_rn(v.x, v.y);
    dst[1] = __floats2half2_rn(v.z, v.w);
}

// ---------------- weights -> fp16, fused bias -------------------------------
__global__ void convert_w_kernel(const float* __restrict__ WU_d,
                                 const float* __restrict__ W_hh,
                                 const float* __restrict__ b_ih,
                                 const float* __restrict__ b_hh) {
    int i = blockIdx.x * 256 + threadIdx.x;          // 0 .. 262143
    if (i < 256 * 512) {
        int r = i >> 9, k = i & 511;
        g_Wdd16[i] = __float2half_rn(WU_d[r * 768 + k]);
    }
    if (i < 256 * 256) {
        int r = i >> 8, k = i & 255;
        g_Wdx16[i] = __float2half_rn(WU_d[r * 768 + 512 + k]);
    }
    if (i < 1024 * 256) {
        g_Whh16[i] = __float2half_rn(W_hh[i]);
    }
    if (i < 1024) {
        g_bias[i] = b_ih[i] + b_hh[i];
    }
}

// ---------------- HMMA helpers ----------------------------------------------
__device__ __forceinline__ void ldsm4(uint32_t* r, uint32_t addr) {
    asm volatile("ldmatrix.sync.aligned.m8n8.x4.shared.b16 {%0,%1,%2,%3}, [%4];"
                 : "=r"(r[0]), "=r"(r[1]), "=r"(r[2]), "=r"(r[3]) : "r"(addr));
}

__device__ __forceinline__ void mma_16816(float* acc, const uint32_t* a,
                                          uint32_t b0, uint32_t b1) {
    asm volatile(
        "mma.sync.aligned.m16n8k16.row.col.f32.f16.f16.f32 "
        "{%0,%1,%2,%3},{%4,%5,%6,%7},{%8,%9},{%0,%1,%2,%3};"
        : "+f"(acc[0]), "+f"(acc[1]), "+f"(acc[2]), "+f"(acc[3])
        : "r"(a[0]), "r"(a[1]), "r"(a[2]), "r"(a[3]), "r"(b0), "r"(b1));
}

__device__ __forceinline__ __half2 h2tanh_fast(__half2 x) {
    uint32_t xi = *(uint32_t*)&x, yo;
    asm("tanh.approx.f16x2 %0, %1;" : "=r"(yo) : "r"(xi));
    return *(__half2*)&yo;
}

// 64x64 block tile, 256 threads (8 warps as 2m x 4n, warp tile 32x16).
#define HM_STRIDE 40
#define HM_BUFH   (64 * HM_STRIDE)
__device__ __forceinline__ void hmma_block(
    const __half* __restrict__ Ag0, int lda,
    const __half* __restrict__ Bg0, int ldb,
    int nit, float acc[2][2][4], __half* As, __half* Bs)
{
    const int tid  = threadIdx.x;
    const int lane = tid & 31, warp = tid >> 5;

    const __half* Ag = Ag0 + (size_t)(tid >> 2) * lda + (tid & 3) * 8;
    const __half* Bg = Bg0 + (size_t)(tid >> 2) * ldb + (tid & 3) * 8;
    const uint32_t st_off = ((tid >> 2) * HM_STRIDE + (tid & 3) * 8) * 2;
    const uint32_t as_base = (uint32_t)__cvta_generic_to_shared(As);
    const uint32_t bs_base = (uint32_t)__cvta_generic_to_shared(Bs);

    const int arow = (warp >> 2) * 32 + (lane & 7) + ((lane >> 3) & 1) * 8;
    const uint32_t a_off0 = (arow * HM_STRIDE + (lane >> 4) * 8) * 2;
    const uint32_t a_off1 = a_off0 + 16 * HM_STRIDE * 2;
    const int brow = (warp & 3) * 16 + (lane & 7) + (lane >> 4) * 8;
    const uint32_t b_off = (brow * HM_STRIDE + ((lane >> 3) & 1) * 8) * 2;

    *(uint4*)((char*)As + st_off) = *(const uint4*)Ag;
    *(uint4*)((char*)Bs + st_off) = *(const uint4*)Bg;
    __syncthreads();

    const uint32_t BUFB = HM_BUFH * 2;
    int buf = 0;
#pragma unroll 1
    for (int it = 0; it < nit; it++) {
        uint4 pa, pb;
        const bool more = (it + 1 < nit);
        if (more) {
            pa = *(const uint4*)(Ag + (it + 1) * 32);
            pb = *(const uint4*)(Bg + (it + 1) * 32);
        }
        const uint32_t ab = as_base + buf * BUFB;
        const uint32_t bb = bs_base + buf * BUFB;
#pragma unroll
        for (int kk = 0; kk < 2; kk++) {
            uint32_t af0[4], af1[4], bf[4];
            ldsm4(af0, ab + a_off0 + kk * 32);
            ldsm4(af1, ab + a_off1 + kk * 32);
            ldsm4(bf,  bb + b_off  + kk * 32);
            mma_16816(acc[0][0], af0, bf[0], bf[1]);
            mma_16816(acc[0][1], af0, bf[2], bf[3]);
            mma_16816(acc[1][0], af1, bf[0], bf[1]);
            mma_16816(acc[1][1], af1, bf[2], bf[3]);
        }
        if (more) {
            const int nb = buf ^ 1;
            *(uint4*)((char*)As + nb * BUFB + st_off) = pa;
            *(uint4*)((char*)Bs + nb * BUFB + st_off) = pb;
            __syncthreads();
            buf = nb;
        }
    }
}

// ---------------- per-step GEMMs via HMMA, uniform K=256 tiles ---------------
// grid (16, 24): y 0..3 -> U1 (K 0:256); y 4..7 -> U2 (K 256:512);
//                y 8..23 -> GATES (K=256)
__global__ void step_gemm_hmma() {
    __shared__ __half As[2][HM_BUFH];
    __shared__ __half Bs[2][HM_BUFH];

    const int y = blockIdx.y;
    const __half* Bg; float* C; int ldb, ldc, col0, koff;
    if (y < 8) {
        const int half = y >> 2;                 // 0 -> U1, 1 -> U2
        koff = half * 256;
        Bg   = g_Wdd16 + (size_t)(y & 3) * 64 * 512 + koff;
        ldb  = 512; C = half ? g_U2 : g_U1; ldc = 256; col0 = (y & 3) * 64;
    } else {
        koff = 0;
        Bg   = g_Whh16 + (size_t)(y - 8) * 64 * 256;
        ldb  = 256; C = g_GATES; ldc = 1024; col0 = (y - 8) * 64;
    }

    float acc[2][2][4] = {};
    hmma_block(g_HCh + (size_t)blockIdx.x * 64 * 512 + koff, 512, Bg, ldb, 8,
               acc, &As[0][0], &Bs[0][0]);

    const int lane = threadIdx.x & 31, warp = threadIdx.x >> 5;
    const int gid = lane >> 2, tig = lane & 3;
    const int mrow0 = blockIdx.x * 64 + (warp >> 2) * 32;
    const int c0 = col0 + (warp & 3) * 16;
#pragma unroll
    for (int mt = 0; mt < 2; mt++)
#pragma unroll
        for (int nt = 0; nt < 2; nt++) {
            const float* a = acc[mt][nt];
            const int r  = mrow0 + mt * 16 + gid;
            const int cc = c0 + nt * 8 + tig * 2;
            *(float2*)&C[(size_t)r * ldc + cc]       = make_float2(a[0], a[1]);
            *(float2*)&C[(size_t)(r + 8) * ldc + cc] = make_float2(a[2], a[3]);
        }
}

// ---------------- A precompute via HMMA: A half of g_AX ----------------------
__global__ void precompute_A_hmma() {
    __shared__ __half As[2][HM_BUFH];
    __shared__ __half Bs[2][HM_BUFH];

    float acc[2][2][4] = {};
    hmma_block(g_AX + (size_t)blockIdx.x * 64 * 512 + 256, 512,
               g_Wdx16 + (size_t)blockIdx.y * 64 * 256, 256, 8,
               acc, &As[0][0], &Bs[0][0]);

    const int lane = threadIdx.x & 31, warp = threadIdx.x >> 5;
    const int gid = lane >> 2, tig = lane & 3;
    const int mrow0 = blockIdx.x * 64 + (warp >> 2) * 32;
    const int c0 = blockIdx.y * 64 + (warp & 3) * 16;
#pragma unroll
    for (int mt = 0; mt < 2; mt++)
#pragma unroll
        for (int nt = 0; nt < 2; nt++) {
            const float* a = acc[mt][nt];
            const int r  = mrow0 + mt * 16 + gid;
            const int cc = c0 + nt * 8 + tig * 2;
            *(__half2*)&g_AX[(size_t)r * 512 + cc]       = __floats2half2_rn(a[0], a[1]);
            *(__half2*)&g_AX[(size_t)(r + 8) * 512 + cc] = __floats2half2_rn(a[2], a[3]);
        }
}

// ---------------- fused attention (online softmax) + LSTM step --------------
// one block per batch, 256 threads (8 warps); single pass over interleaved AX
// depth-3 load pipeline; f16x2 logit math
__global__ void __launch_bounds__(256, 4)
attn_lstm_kernel(const float* __restrict__ v_d,
                 const float* __restrict__ Wl,
                 const float* __restrict__ Y,
                 const float* __restrict__ W_ih,
                 int t_step)
{
    __shared__ float ctx_ws[8][M_SZ];
    __shared__ float wM[8], wS[8], redy[8];
    __shared__ float yt_s;

    const int b    = blockIdx.x;
    const int tid  = threadIdx.x;     // 0..255
    const int lane = tid & 31;
    const int warp = tid >> 5;

    // per-lane u,v slices as half2 (m = lane*8 .. lane*8+7), reused 16x
    __half2 u2[4], v2[4];
    {
        const int mb = lane * 8;
        float4 u1a = __ldg((const float4*)(g_U1 + b * M_SZ + mb));
        float4 u1b = __ldg((const float4*)(g_U1 + b * M_SZ + mb + 4));
        float4 u2a = __ldg((const float4*)(g_U2 + b * M_SZ + mb));
        float4 u2b = __ldg((const float4*)(g_U2 + b * M_SZ + mb + 4));
        float4 va  = __ldg((const float4*)(v_d + mb));
        float4 vb  = __ldg((const float4*)(v_d + mb + 4));
        u2[0] = __floats2half2_rn(u1a.x + u2a.x, u1a.y + u2a.y);
        u2[1] = __floats2half2_rn(u1a.z + u2a.z, u1a.w + u2a.w);
        u2[2] = __floats2half2_rn(u1b.x + u2b.x, u1b.y + u2b.y);
        u2[3] = __floats2half2_rn(u1b.z + u2b.z, u1b.w + u2b.w);
        v2[0] = __floats2half2_rn(va.x, va.y);
        v2[1] = __floats2half2_rn(va.z, va.w);
        v2[2] = __floats2half2_rn(vb.x, vb.y);
        v2[3] = __floats2half2_rn(vb.z, vb.w);
    }

    // single pass: logits + online softmax + ctx accumulation
    const float4* AXrow = (const float4*)(g_AX + (size_t)b * T_SZ * 512) + lane;

    float C[8] = {0, 0, 0, 0, 0, 0, 0, 0};
    float Mx = -1e30f, S = 0.0f;

    float4 a0 = __ldg(AXrow + (size_t)warp * 64);
    float4 x0 = __ldg(AXrow + (size_t)warp * 64 + 32);
    float4 a1 = __ldg(AXrow + (size_t)(warp + 8) * 64);
    float4 x1 = __ldg(AXrow + (size_t)(warp + 8) * 64 + 32);

#pragma unroll
    for (int i = 0; i < 16; i++) {
        const int t = warp + i * 8;
        float4 a2, x2;
        if (i < 14) {
            a2 = __ldg(AXrow + (size_t)(t + 16) * 64);
            x2 = __ldg(AXrow + (size_t)(t + 16) * 64 + 32);
        }

        // logit partial from this lane's 8 m-values (f16x2 path)
        const __half2* ahp = (const __half2*)&a0;
        const __half2* xhp = (const __half2*)&x0;
        __half2 acch = __floats2half2_rn(0.0f, 0.0f);
        float xv[8];
#pragma unroll
        for (int j = 0; j < 4; j++) {
            __half2 s  = __hadd2(u2[j], ahp[j]);
            __half2 th = h2tanh_fast(s);
            acch = __hfma2(v2[j], th, acch);
            float2 xf = __half22float2(xhp[j]);
            xv[2 * j] = xf.x; xv[2 * j + 1] = xf.y;
        }
        float acc = __low2float(acch) + __high2float(acch);
#pragma unroll
        for (int o = 16; o; o >>= 1) acc += __shfl_xor_sync(0xffffffffu, acc, o);
        // acc = l_t, uniform across warp

        if (acc <= Mx) {                 // warp-uniform branch
            float e = __expf(acc - Mx);
            S += e;
#pragma unroll
            for (int j = 0; j < 8; j++) C[j] = fmaf(e, xv[j], C[j]);
        } else {
            float f = __expf(Mx - acc);
            S = fmaf(S, f, 1.0f);
#pragma unroll
            for (int j = 0; j < 8; j++) C[j] = fmaf(C[j], f, xv[j]);
            Mx = acc;
        }

        a0 = a1; x0 = x1; a1 = a2; x1 = x2;
    }

    // per-warp results -> smem
    if (lane == 0) { wM[warp] = Mx; wS[warp] = S; }
    *(float4*)&ctx_ws[warp][lane * 8]     = make_float4(C[0], C[1], C[2], C[3]);
    *(float4*)&ctx_ws[warp][lane * 8 + 4] = make_float4(C[4], C[5], C[6], C[7]);
    __syncthreads();

    // combine warps: global max, rescale, normalize
    float Mg = wM[0];
#pragma unroll
    for (int w = 1; w < 8; w++) Mg = fmaxf(Mg, wM[w]);
    float fw[8], Sg = 0.0f;
#pragma unroll
    for (int w = 0; w < 8; w++) { fw[w] = __expf(wM[w] - Mg); Sg = fmaf(wS[w], fw[w], Sg); }
    float c = 0.0f;
#pragma unroll
    for (int w = 0; w < 8; w++) c = fmaf(fw[w], ctx_ws[w][tid], c);
    c /= Sg;

    if (t_step == TS - 1) g_CTX[b * M_SZ + tid] = c;

    // y_tilde = Wl[0]*y_t + sum_m Wl[1+m]*ctx[m]
    float yv = __ldg(Wl + 1 + tid) * c;
#pragma unroll
    for (int o = 16; o; o >>= 1) yv += __shfl_xor_sync(0xffffffffu, yv, o);
    if (lane == 0) redy[warp] = yv;
    __syncthreads();
    if (tid == 0) {
        float s = redy[0] + redy[1] + redy[2] + redy[3]
                + redy[4] + redy[5] + redy[6] + redy[7];
        yt_s = fmaf(__ldg(Wl), Y[(size_t)b * TS + t_step], s);
    }
    __syncthreads();

    // fused LSTM pointwise update
    const float yt = yt_s;
    const int p = tid;
    const float* gr = g_GATES + (size_t)b * 4 * P_SZ;
    float ig = gr[p]            + yt * __ldg(W_ih + p)            + g_bias[p];
    float fg = gr[P_SZ + p]     + yt * __ldg(W_ih + P_SZ + p)     + g_bias[P_SZ + p];
    float gg = gr[2 * P_SZ + p] + yt * __ldg(W_ih + 2 * P_SZ + p) + g_bias[2 * P_SZ + p];
    float og = gr[3 * P_SZ + p] + yt * __ldg(W_ih + 3 * P_SZ + p) + g_bias[3 * P_SZ + p];

    float cold = g_HC[(size_t)b * 512 + 256 + p];
    float si = 1.0f / (1.0f + __expf(-ig));
    float sf = 1.0f / (1.0f + __expf(-fg));
    float so = 1.0f / (1.0f + __expf(-og));
    float cn = sf * cold + si * tanhf(gg);
    float hn = so * tanhf(cn);

    g_HC[(size_t)b * 512 + p]        = hn;
    g_HC[(size_t)b * 512 + 256 + p]  = cn;
    g_HCh[(size_t)b * 512 + p]       = __float2half_rn(hn);
    g_HCh[(size_t)b * 512 + 256 + p] = __float2half_rn(cn);
}

// ---------------- final head: out = ([h,ctx] @ Wb^T + b) @ vb^T + vb_b -----
__global__ void final_head_kernel(const float* __restrict__ Wb_w,
                                  const float* __restrict__ Wb_b,
                                  const float* __restrict__ vb_w,
                                  const float* __restrict__ vb_b,
                                  float* __restrict__ out)
{
    const int b   = blockIdx.x;
    const int tid = threadIdx.x;  // 0..255 = p
    __shared__ float hc_s[512];
    __shared__ float red[8];

    hc_s[tid]        = g_HC[(size_t)b * 512 + tid];        // h
    hc_s[P_SZ + tid] = g_CTX[(size_t)b * M_SZ + tid];      // ctx
    __syncthreads();

    const float* wr = Wb_w + (size_t)tid * (P_SZ + M_SZ);
    float t = __ldg(Wb_b + tid);
#pragma unroll 4
    for (int k = 0; k < 2 * P_SZ; k++)
        t = fmaf(__ldg(wr + k), hc_s[k], t);
    float val = __ldg(vb_w + tid) * t;

    int lane = tid & 31, warp = tid >> 5;
#pragma unroll
    for (int o = 16; o; o >>= 1) val += __shfl_xor_sync(0xffffffffu, val, o);
    if (lane == 0) red[warp] = val;
    __syncthreads();
    if (tid == 0)
        out[b] = vb_b[0] + red[0] + red[1] + red[2] + red[3]
                         + red[4] + red[5] + red[6] + red[7];
}

// ---------------- launch ----------------------------------------------------
extern "C" void kernel_launch(void* const* d_in, const int* in_sizes, int n_in,
                              void* d_out, int out_size)
{
    const float* Y    = (const float*)d_in[0];
    const float* X    = (const float*)d_in[1];
    const float* WU_d = (const float*)d_in[2];
    const float* v_d  = (const float*)d_in[3];
    const float* Wl   = (const float*)d_in[4];
    const float* W_ih = (const float*)d_in[5];
    const float* W_hh = (const float*)d_in[6];
    const float* b_ih = (const float*)d_in[7];
    const float* b_hh = (const float*)d_in[8];
    const float* Wb_w = (const float*)d_in[9];
    const float* Wb_b = (const float*)d_in[10];
    const float* vb_w = (const float*)d_in[11];
    const float* vb_b = (const float*)d_in[12];
    float* out = (float*)d_out;

    // init h, c = 0 (fp32 + fp16 mirrors)
    init_hc_kernel<<<(B_SZ * 512 + 255) / 256, 256>>>();

    // X -> interleaved AX (X half) fp16 ; weights -> fp16 ; fused bias
    convert_x_kernel<<<(T_SZ * B_SZ) / 4, 256>>>(X);
    convert_w_kernel<<<1024, 256>>>(WU_d, W_hh, b_ih, b_hh);

    // A half of g_AX = X16 @ Wdx^T (HMMA)
    precompute_A_hmma<<<dim3((B_SZ * T_SZ) / 64, M_SZ / 64), 256>>>();

    for (int t = 0; t < TS; t++) {
        step_gemm_hmma<<<dim3(B_SZ / 64, 24), 256>>>();
        attn_lstm_kernel<<<B_SZ, 256>>>(v_d, Wl, Y, W_ih, t);
    }

    final_head_kernel<<<B_SZ, 256>>>(Wb_w, Wb_b, vb_w, vb_b, out);
}

// round 11
// speedup vs baseline: 3.2147x; 1.0087x over previous
#include <cuda_runtime.h>
#include <cuda_fp16.h>
#include <cstdint>
#include <cstddef>

#define B_SZ 1024
#define T_SZ 128
#define M_SZ 256
#define P_SZ 256
#define TS   127   // T-1 recurrence steps

// ---------------- scratch (static device globals) ---------------------------
// interleaved per-(b,t) row: [ A[0..255] | X[0..255] ] fp16, stride 512
__device__ __half g_AX[(size_t)B_SZ * T_SZ * 512];
__device__ __half g_HCh[B_SZ * 512];                 // fp16 mirror of [h|c]
__device__ __half g_Wdd16[256 * 512];                // WU_d[:, :512] fp16
__device__ __half g_Whh16[1024 * 256];               // W_hh fp16
__device__ __half g_Wdx16[256 * 256];                // WU_d[:, 512:768] fp16
__device__ float  g_bias[4 * P_SZ];                  // b_ih + b_hh
__device__ float  g_U1[B_SZ * M_SZ];                 // d-part preact, K 0:256
__device__ float  g_U2[B_SZ * M_SZ];                 // d-part preact, K 256:512
__device__ float  g_HC[B_SZ * 512];                  // fp32 master [h|c]
__device__ float  g_CTX[B_SZ * M_SZ];                // attention context (last step)
__device__ float  g_GATES[B_SZ * 4 * P_SZ];          // h @ W_hh^T

// ---------------- init ------------------------------------------------------
__global__ void init_hc_kernel() {
    int i = blockIdx.x * blockDim.x + threadIdx.x;
    if (i < B_SZ * 512) { g_HC[i] = 0.0f; g_HCh[i] = __float2half_rn(0.0f); }
}

// ---------------- X (t,b,m) fp32 -> g_AX[b,t, 256+m] fp16 -------------------
__global__ void convert_x_kernel(const float* __restrict__ X) {
    int row = blockIdx.x * 4 + (threadIdx.x >> 6);   // row = t*B + b
    int c4  = (threadIdx.x & 63) * 4;
    int t = row >> 10;
    int b = row & 1023;
    float4 v = __ldg((const float4*)(X + (size_t)row * M_SZ + c4));
    __half2* dst = (__half2*)(g_AX + ((size_t)(b << 7) + t) * 512 + 256 + c4);
    dst[0] = __floats2half2_rn(v.x, v.y);
    dst[1] = __floats2half2_rn(v.z, v.w);
}

// ---------------- weights -> fp16, fused bias -------------------------------
__global__ void convert_w_kernel(const float* __restrict__ WU_d,
                                 const float* __restrict__ W_hh,
                                 const float* __restrict__ b_ih,
                                 const float* __restrict__ b_hh) {
    int i = blockIdx.x * 256 + threadIdx.x;          // 0 .. 262143
    if (i < 256 * 512) {
        int r = i >> 9, k = i & 511;
        g_Wdd16[i] = __float2half_rn(WU_d[r * 768 + k]);
    }
    if (i < 256 * 256) {
        int r = i >> 8, k = i & 255;
        g_Wdx16[i] = __float2half_rn(WU_d[r * 768 + 512 + k]);
    }
    if (i < 1024 * 256) {
        g_Whh16[i] = __float2half_rn(W_hh[i]);
    }
    if (i < 1024) {
        g_bias[i] = b_ih[i] + b_hh[i];
    }
}

// ---------------- HMMA helpers ----------------------------------------------
__device__ __forceinline__ void ldsm4(uint32_t* r, uint32_t addr) {
    asm volatile("ldmatrix.sync.aligned.m8n8.x4.shared.b16 {%0,%1,%2,%3}, [%4];"
                 : "=r"(r[0]), "=r"(r[1]), "=r"(r[2]), "=r"(r[3]) : "r"(addr));
}

__device__ __forceinline__ void mma_16816(float* acc, const uint32_t* a,
                                          uint32_t b0, uint32_t b1) {
    asm volatile(
        "mma.sync.aligned.m16n8k16.row.col.f32.f16.f16.f32 "
        "{%0,%1,%2,%3},{%4,%5,%6,%7},{%8,%9},{%0,%1,%2,%3};"
        : "+f"(acc[0]), "+f"(acc[1]), "+f"(acc[2]), "+f"(acc[3])
        : "r"(a[0]), "r"(a[1]), "r"(a[2]), "r"(a[3]), "r"(b0), "r"(b1));
}

__device__ __forceinline__ __half2 h2tanh_fast(__half2 x) {
    uint32_t xi = *(uint32_t*)&x, yo;
    asm("tanh.approx.f16x2 %0, %1;" : "=r"(yo) : "r"(xi));
    return *(__half2*)&yo;
}

// 64x64 block tile, 256 threads (8 warps as 2m x 4n, warp tile 32x16).
#define HM_STRIDE 40
#define HM_BUFH   (64 * HM_STRIDE)
__device__ __forceinline__ void hmma_block(
    const __half* __restrict__ Ag0, int lda,
    const __half* __restrict__ Bg0, int ldb,
    int nit, float acc[2][2][4], __half* As, __half* Bs)
{
    const int tid  = threadIdx.x;
    const int lane = tid & 31, warp = tid >> 5;

    const __half* Ag = Ag0 + (size_t)(tid >> 2) * lda + (tid & 3) * 8;
    const __half* Bg = Bg0 + (size_t)(tid >> 2) * ldb + (tid & 3) * 8;
    const uint32_t st_off = ((tid >> 2) * HM_STRIDE + (tid & 3) * 8) * 2;
    const uint32_t as_base = (uint32_t)__cvta_generic_to_shared(As);
    const uint32_t bs_base = (uint32_t)__cvta_generic_to_shared(Bs);

    const int arow = (warp >> 2) * 32 + (lane & 7) + ((lane >> 3) & 1) * 8;
    const uint32_t a_off0 = (arow * HM_STRIDE + (lane >> 4) * 8) * 2;
    const uint32_t a_off1 = a_off0 + 16 * HM_STRIDE * 2;
    const int brow = (warp & 3) * 16 + (lane & 7) + (lane >> 4) * 8;
    const uint32_t b_off = (brow * HM_STRIDE + ((lane >> 3) & 1) * 8) * 2;

    *(uint4*)((char*)As + st_off) = *(const uint4*)Ag;
    *(uint4*)((char*)Bs + st_off) = *(const uint4*)Bg;
    __syncthreads();

    const uint32_t BUFB = HM_BUFH * 2;
    int buf = 0;
#pragma unroll 1
    for (int it = 0; it < nit; it++) {
        uint4 pa, pb;
        const bool more = (it + 1 < nit);
        if (more) {
            pa = *(const uint4*)(Ag + (it + 1) * 32);
            pb = *(const uint4*)(Bg + (it + 1) * 32);
        }
        const uint32_t ab = as_base + buf * BUFB;
        const uint32_t bb = bs_base + buf * BUFB;
#pragma unroll
        for (int kk = 0; kk < 2; kk++) {
            uint32_t af0[4], af1[4], bf[4];
            ldsm4(af0, ab + a_off0 + kk * 32);
            ldsm4(af1, ab + a_off1 + kk * 32);
            ldsm4(bf,  bb + b_off  + kk * 32);
            mma_16816(acc[0][0], af0, bf[0], bf[1]);
            mma_16816(acc[0][1], af0, bf[2], bf[3]);
            mma_16816(acc[1][0], af1, bf[0], bf[1]);
            mma_16816(acc[1][1], af1, bf[2], bf[3]);
        }
        if (more) {
            const int nb = buf ^ 1;
            *(uint4*)((char*)As + nb * BUFB + st_off) = pa;
            *(uint4*)((char*)Bs + nb * BUFB + st_off) = pb;
            __syncthreads();
            buf = nb;
        }
    }
}

// ---------------- per-step GEMMs via HMMA, uniform K=256 tiles ---------------
// grid (16, 24): y 0..3 -> U1 (K 0:256); y 4..7 -> U2 (K 256:512);
//                y 8..23 -> GATES (K=256)
__global__ void step_gemm_hmma() {
    __shared__ __half As[2][HM_BUFH];
    __shared__ __half Bs[2][HM_BUFH];

    const int y = blockIdx.y;
    const __half* Bg; float* C; int ldb, ldc, col0, koff;
    if (y < 8) {
        const int half = y >> 2;                 // 0 -> U1, 1 -> U2
        koff = half * 256;
        Bg   = g_Wdd16 + (size_t)(y & 3) * 64 * 512 + koff;
        ldb  = 512; C = half ? g_U2 : g_U1; ldc = 256; col0 = (y & 3) * 64;
    } else {
        koff = 0;
        Bg   = g_Whh16 + (size_t)(y - 8) * 64 * 256;
        ldb  = 256; C = g_GATES; ldc = 1024; col0 = (y - 8) * 64;
    }

    float acc[2][2][4] = {};
    hmma_block(g_HCh + (size_t)blockIdx.x * 64 * 512 + koff, 512, Bg, ldb, 8,
               acc, &As[0][0], &Bs[0][0]);

    const int lane = threadIdx.x & 31, warp = threadIdx.x >> 5;
    const int gid = lane >> 2, tig = lane & 3;
    const int mrow0 = blockIdx.x * 64 + (warp >> 2) * 32;
    const int c0 = col0 + (warp & 3) * 16;
#pragma unroll
    for (int mt = 0; mt < 2; mt++)
#pragma unroll
        for (int nt = 0; nt < 2; nt++) {
            const float* a = acc[mt][nt];
            const int r  = mrow0 + mt * 16 + gid;
            const int cc = c0 + nt * 8 + tig * 2;
            *(float2*)&C[(size_t)r * ldc + cc]       = make_float2(a[0], a[1]);
            *(float2*)&C[(size_t)(r + 8) * ldc + cc] = make_float2(a[2], a[3]);
        }
}

// ---------------- A precompute via HMMA: A half of g_AX ----------------------
__global__ void precompute_A_hmma() {
    __shared__ __half As[2][HM_BUFH];
    __shared__ __half Bs[2][HM_BUFH];

    float acc[2][2][4] = {};
    hmma_block(g_AX + (size_t)blockIdx.x * 64 * 512 + 256, 512,
               g_Wdx16 + (size_t)blockIdx.y * 64 * 256, 256, 8,
               acc, &As[0][0], &Bs[0][0]);

    const int lane = threadIdx.x & 31, warp = threadIdx.x >> 5;
    const int gid = lane >> 2, tig = lane & 3;
    const int mrow0 = blockIdx.x * 64 + (warp >> 2) * 32;
    const int c0 = blockIdx.y * 64 + (warp & 3) * 16;
#pragma unroll
    for (int mt = 0; mt < 2; mt++)
#pragma unroll
        for (int nt = 0; nt < 2; nt++) {
            const float* a = acc[mt][nt];
            const int r  = mrow0 + mt * 16 + gid;
            const int cc = c0 + nt * 8 + tig * 2;
            *(__half2*)&g_AX[(size_t)r * 512 + cc]       = __floats2half2_rn(a[0], a[1]);
            *(__half2*)&g_AX[(size_t)(r + 8) * 512 + cc] = __floats2half2_rn(a[2], a[3]);
        }
}

// ---------------- fused attention (online softmax) + LSTM step --------------
// 512 blocks (single wave), 2 batches per block; warps 0-3 -> batch0,
// warps 4-7 -> batch1; each warp sweeps 32 t-rows (stride 4)
__global__ void __launch_bounds__(256, 4)
attn_lstm_kernel(const float* __restrict__ v_d,
                 const float* __restrict__ Wl,
                 const float* __restrict__ Y,
                 const float* __restrict__ W_ih,
                 int t_step)
{
    __shared__ float ctx_ws[8][M_SZ];
    __shared__ float wM[8], wS[8];
    __shared__ float redy[2][8];
    __shared__ float yt_s[2];

    const int tid  = threadIdx.x;     // 0..255
    const int lane = tid & 31;
    const int warp = tid >> 5;
    const int wg   = warp & 3;        // t offset within batch
    const int bg   = warp >> 2;       // which batch of the pair
    const int b    = blockIdx.x * 2 + bg;

    // per-lane u,v slices as half2 (m = lane*8 .. lane*8+7), reused 32x
    __half2 u2[4], v2[4];
    {
        const int mb = lane * 8;
        float4 u1a = __ldg((const float4*)(g_U1 + b * M_SZ + mb));
        float4 u1b = __ldg((const float4*)(g_U1 + b * M_SZ + mb + 4));
        float4 u2a = __ldg((const float4*)(g_U2 + b * M_SZ + mb));
        float4 u2b = __ldg((const float4*)(g_U2 + b * M_SZ + mb + 4));
        float4 va  = __ldg((const float4*)(v_d + mb));
        float4 vb  = __ldg((const float4*)(v_d + mb + 4));
        u2[0] = __floats2half2_rn(u1a.x + u2a.x, u1a.y + u2a.y);
        u2[1] = __floats2half2_rn(u1a.z + u2a.z, u1a.w + u2a.w);
        u2[2] = __floats2half2_rn(u1b.x + u2b.x, u1b.y + u2b.y);
        u2[3] = __floats2half2_rn(u1b.z + u2b.z, u1b.w + u2b.w);
        v2[0] = __floats2half2_rn(va.x, va.y);
        v2[1] = __floats2half2_rn(va.z, va.w);
        v2[2] = __floats2half2_rn(vb.x, vb.y);
        v2[3] = __floats2half2_rn(vb.z, vb.w);
    }

    // single pass: logits + online softmax + ctx accumulation
    const float4* AXrow = (const float4*)(g_AX + (size_t)b * T_SZ * 512) + lane;

    float C[8] = {0, 0, 0, 0, 0, 0, 0, 0};
    float Mx = -1e30f, S = 0.0f;

    float4 a0 = __ldg(AXrow + (size_t)wg * 64);
    float4 x0 = __ldg(AXrow + (size_t)wg * 64 + 32);
    float4 a1 = __ldg(AXrow + (size_t)(wg + 4) * 64);
    float4 x1 = __ldg(AXrow + (size_t)(wg + 4) * 64 + 32);

#pragma unroll 4
    for (int i = 0; i < 32; i++) {
        const int t = wg + i * 4;
        float4 a2, x2;
        if (i < 30) {
            a2 = __ldg(AXrow + (size_t)(t + 8) * 64);
            x2 = __ldg(AXrow + (size_t)(t + 8) * 64 + 32);
        }

        // logit partial from this lane's 8 m-values (f16x2 path)
        const __half2* ahp = (const __half2*)&a0;
        const __half2* xhp = (const __half2*)&x0;
        __half2 acch = __floats2half2_rn(0.0f, 0.0f);
        float xv[8];
#pragma unroll
        for (int j = 0; j < 4; j++) {
            __half2 s  = __hadd2(u2[j], ahp[j]);
            __half2 th = h2tanh_fast(s);
            acch = __hfma2(v2[j], th, acch);
            float2 xf = __half22float2(xhp[j]);
            xv[2 * j] = xf.x; xv[2 * j + 1] = xf.y;
        }
        float acc = __low2float(acch) + __high2float(acch);
#pragma unroll
        for (int o = 16; o; o >>= 1) acc += __shfl_xor_sync(0xffffffffu, acc, o);
        // acc = l_t, uniform across warp

        if (acc <= Mx) {                 // warp-uniform branch
            float e = __expf(acc - Mx);
            S += e;
#pragma unroll
            for (int j = 0; j < 8; j++) C[j] = fmaf(e, xv[j], C[j]);
        } else {
            float f = __expf(Mx - acc);
            S = fmaf(S, f, 1.0f);
#pragma unroll
            for (int j = 0; j < 8; j++) C[j] = fmaf(C[j], f, xv[j]);
            Mx = acc;
        }

        a0 = a1; x0 = x1; a1 = a2; x1 = x2;
    }

    // per-warp results -> smem
    if (lane == 0) { wM[warp] = Mx; wS[warp] = S; }
    *(float4*)&ctx_ws[warp][lane * 8]     = make_float4(C[0], C[1], C[2], C[3]);
    *(float4*)&ctx_ws[warp][lane * 8 + 4] = make_float4(C[4], C[5], C[6], C[7]);
    __syncthreads();

    // per-batch combine (each thread computes ctx[m=tid] for both batches)
    float cg[2];
#pragma unroll
    for (int g = 0; g < 2; g++) {
        float Mg = fmaxf(fmaxf(wM[4 * g], wM[4 * g + 1]),
                         fmaxf(wM[4 * g + 2], wM[4 * g + 3]));
        float Sg = 0.0f, c = 0.0f;
#pragma unroll
        for (int w = 0; w < 4; w++) {
            float f = __expf(wM[4 * g + w] - Mg);
            Sg = fmaf(wS[4 * g + w], f, Sg);
            c  = fmaf(f, ctx_ws[4 * g + w][tid], c);
        }
        cg[g] = c / Sg;
    }

    if (t_step == TS - 1) {
        g_CTX[(blockIdx.x * 2)     * M_SZ + tid] = cg[0];
        g_CTX[(blockIdx.x * 2 + 1) * M_SZ + tid] = cg[1];
    }

    // y_tilde per batch: Wl[0]*y_t + sum_m Wl[1+m]*ctx[m]
    const float wl = __ldg(Wl + 1 + tid);
#pragma unroll
    for (int g = 0; g < 2; g++) {
        float yv = wl * cg[g];
#pragma unroll
        for (int o = 16; o; o >>= 1) yv += __shfl_xor_sync(0xffffffffu, yv, o);
        if (lane == 0) redy[g][warp] = yv;
    }
    __syncthreads();
    if (tid < 2) {
        float s = redy[tid][0] + redy[tid][1] + redy[tid][2] + redy[tid][3]
                + redy[tid][4] + redy[tid][5] + redy[tid][6] + redy[tid][7];
        yt_s[tid] = fmaf(__ldg(Wl),
                         Y[(size_t)(blockIdx.x * 2 + tid) * TS + t_step], s);
    }
    __syncthreads();

    // fused LSTM pointwise update for both batches
    const int p = tid;
    const float wi0 = __ldg(W_ih + p);
    const float wi1 = __ldg(W_ih + P_SZ + p);
    const float wi2 = __ldg(W_ih + 2 * P_SZ + p);
    const float wi3 = __ldg(W_ih + 3 * P_SZ + p);
    const float bz0 = g_bias[p], bz1 = g_bias[P_SZ + p];
    const float bz2 = g_bias[2 * P_SZ + p], bz3 = g_bias[3 * P_SZ + p];

#pragma unroll
    for (int g = 0; g < 2; g++) {
        const int bb = blockIdx.x * 2 + g;
        const float yt = yt_s[g];
        const float* gr = g_GATES + (size_t)bb * 4 * P_SZ;
        float ig = gr[p]            + yt * wi0 + bz0;
        float fg = gr[P_SZ + p]     + yt * wi1 + bz1;
        float gg = gr[2 * P_SZ + p] + yt * wi2 + bz2;
        float og = gr[3 * P_SZ + p] + yt * wi3 + bz3;

        float cold = g_HC[(size_t)bb * 512 + 256 + p];
        float si = 1.0f / (1.0f + __expf(-ig));
        float sf = 1.0f / (1.0f + __expf(-fg));
        float so = 1.0f / (1.0f + __expf(-og));
        float cn = sf * cold + si * tanhf(gg);
        float hn = so * tanhf(cn);

        g_HC[(size_t)bb * 512 + p]        = hn;
        g_HC[(size_t)bb * 512 + 256 + p]  = cn;
        g_HCh[(size_t)bb * 512 + p]       = __float2half_rn(hn);
        g_HCh[(size_t)bb * 512 + 256 + p] = __float2half_rn(cn);
    }
}

// ---------------- final head: out = ([h,ctx] @ Wb^T + b) @ vb^T + vb_b -----
__global__ void final_head_kernel(const float* __restrict__ Wb_w,
                                  const float* __restrict__ Wb_b,
                                  const float* __restrict__ vb_w,
                                  const float* __restrict__ vb_b,
                                  float* __restrict__ out)
{
    const int b   = blockIdx.x;
    const int tid = threadIdx.x;  // 0..255 = p
    __shared__ float hc_s[512];
    __shared__ float red[8];

    hc_s[tid]        = g_HC[(size_t)b * 512 + tid];        // h
    hc_s[P_SZ + tid] = g_CTX[(size_t)b * M_SZ + tid];      // ctx
    __syncthreads();

    const float* wr = Wb_w + (size_t)tid * (P_SZ + M_SZ);
    float t = __ldg(Wb_b + tid);
#pragma unroll 4
    for (int k = 0; k < 2 * P_SZ; k++)
        t = fmaf(__ldg(wr + k), hc_s[k], t);
    float val = __ldg(vb_w + tid) * t;

    int lane = tid & 31, warp = tid >> 5;
#pragma unroll
    for (int o = 16; o; o >>= 1) val += __shfl_xor_sync(0xffffffffu, val, o);
    if (lane == 0) red[warp] = val;
    __syncthreads();
    if (tid == 0)
        out[b] = vb_b[0] + red[0] + red[1] + red[2] + red[3]
                         + red[4] + red[5] + red[6] + red[7];
}

// ---------------- launch ----------------------------------------------------
extern "C" void kernel_launch(void* const* d_in, const int* in_sizes, int n_in,
                              void* d_out, int out_size)
{
    const float* Y    = (const float*)d_in[0];
    const float* X    = (const float*)d_in[1];
    const float* WU_d = (const float*)d_in[2];
    const float* v_d  = (const float*)d_in[3];
    const float* Wl   = (const float*)d_in[4];
    const float* W_ih = (const float*)d_in[5];
    const float* W_hh = (const float*)d_in[6];
    const float* b_ih = (const float*)d_in[7];
    const float* b_hh = (const float*)d_in[8];
    const float* Wb_w = (const float*)d_in[9];
    const float* Wb_b = (const float*)d_in[10];
    const float* vb_w = (const float*)d_in[11];
    const float* vb_b = (const float*)d_in[12];
    float* out = (float*)d_out;

    // init h, c = 0 (fp32 + fp16 mirrors)
    init_hc_kernel<<<(B_SZ * 512 + 255) / 256, 256>>>();

    // X -> interleaved AX (X half) fp16 ; weights -> fp16 ; fused bias
    convert_x_kernel<<<(T_SZ * B_SZ) / 4, 256>>>(X);
    convert_w_kernel<<<1024, 256>>>(WU_d, W_hh, b_ih, b_hh);

    // A half of g_AX = X16 @ Wdx^T (HMMA)
    precompute_A_hmma<<<dim3((B_SZ * T_SZ) / 64, M_SZ / 64), 256>>>();

    for (int t = 0; t < TS; t++) {
        step_gemm_hmma<<<dim3(B_SZ / 64, 24), 256>>>();
        attn_lstm_kernel<<<B_SZ / 2, 256>>>(v_d, Wl, Y, W_ih, t);
    }

    final_head_kernel<<<B_SZ, 256>>>(Wb_w, Wb_b, vb_w, vb_b, out);
}

// round 12
// speedup vs baseline: 3.2946x; 1.0248x over previous
#include <cuda_runtime.h>
#include <cuda_fp16.h>
#include <cstdint>
#include <cstddef>

#define B_SZ 1024
#define T_SZ 128
#define M_SZ 256
#define P_SZ 256
#define TS   127   // T-1 recurrence steps

// ---------------- scratch (static device globals) ---------------------------
// interleaved per-(b,t) row: [ A[0..255] | X[0..255] ] fp16, stride 512
__device__ __half g_AX[(size_t)B_SZ * T_SZ * 512];
__device__ __half g_HCh[B_SZ * 512];                 // fp16 mirror of [h|c]
__device__ __half g_Wdd16[256 * 512];                // WU_d[:, :512] fp16
__device__ __half g_Whh16[1024 * 256];               // W_hh fp16
__device__ __half g_Wdx16[256 * 256];                // WU_d[:, 512:768] fp16
__device__ float  g_bias[4 * P_SZ];                  // b_ih + b_hh
__device__ __half g_U1h[B_SZ * M_SZ];                // d-part preact, K 0:256 (fp16)
__device__ __half g_U2h[B_SZ * M_SZ];                // d-part preact, K 256:512 (fp16)
__device__ __half g_GATESh[B_SZ * 4 * P_SZ];         // h @ W_hh^T (fp16)
__device__ float  g_HC[B_SZ * 512];                  // fp32 master [h|c]
__device__ float  g_CTX[B_SZ * M_SZ];                // attention context (last step)

// ---------------- init ------------------------------------------------------
__global__ void init_hc_kernel() {
    int i = blockIdx.x * blockDim.x + threadIdx.x;
    if (i < B_SZ * 512) { g_HC[i] = 0.0f; g_HCh[i] = __float2half_rn(0.0f); }
}

// ---------------- X (t,b,m) fp32 -> g_AX[b,t, 256+m] fp16 -------------------
__global__ void convert_x_kernel(const float* __restrict__ X) {
    int row = blockIdx.x * 4 + (threadIdx.x >> 6);   // row = t*B + b
    int c4  = (threadIdx.x & 63) * 4;
    int t = row >> 10;
    int b = row & 1023;
    float4 v = __ldg((const float4*)(X + (size_t)row * M_SZ + c4));
    __half2* dst = (__half2*)(g_AX + ((size_t)(b << 7) + t) * 512 + 256 + c4);
    dst[0] = __floats2half2_rn(v.x, v.y);
    dst[1] = __floats2half2_rn(v.z, v.w);
}

// ---------------- weights -> fp16, fused bias -------------------------------
__global__ void convert_w_kernel(const float* __restrict__ WU_d,
                                 const float* __restrict__ W_hh,
                                 const float* __restrict__ b_ih,
                                 const float* __restrict__ b_hh) {
    int i = blockIdx.x * 256 + threadIdx.x;          // 0 .. 262143
    if (i < 256 * 512) {
        int r = i >> 9, k = i & 511;
        g_Wdd16[i] = __float2half_rn(WU_d[r * 768 + k]);
    }
    if (i < 256 * 256) {
        int r = i >> 8, k = i & 255;
        g_Wdx16[i] = __float2half_rn(WU_d[r * 768 + 512 + k]);
    }
    if (i < 1024 * 256) {
        g_Whh16[i] = __float2half_rn(W_hh[i]);
    }
    if (i < 1024) {
        g_bias[i] = b_ih[i] + b_hh[i];
    }
}

// ---------------- HMMA helpers ----------------------------------------------
__device__ __forceinline__ void ldsm4(uint32_t* r, uint32_t addr) {
    asm volatile("ldmatrix.sync.aligned.m8n8.x4.shared.b16 {%0,%1,%2,%3}, [%4];"
                 : "=r"(r[0]), "=r"(r[1]), "=r"(r[2]), "=r"(r[3]) : "r"(addr));
}

__device__ __forceinline__ void mma_16816(float* acc, const uint32_t* a,
                                          uint32_t b0, uint32_t b1) {
    asm volatile(
        "mma.sync.aligned.m16n8k16.row.col.f32.f16.f16.f32 "
        "{%0,%1,%2,%3},{%4,%5,%6,%7},{%8,%9},{%0,%1,%2,%3};"
        : "+f"(acc[0]), "+f"(acc[1]), "+f"(acc[2]), "+f"(acc[3])
        : "r"(a[0]), "r"(a[1]), "r"(a[2]), "r"(a[3]), "r"(b0), "r"(b1));
}

__device__ __forceinline__ __half2 h2tanh_fast(__half2 x) {
    uint32_t xi = *(uint32_t*)&x, yo;
    asm("tanh.approx.f16x2 %0, %1;" : "=r"(yo) : "r"(xi));
    return *(__half2*)&yo;
}

// 64x64 block tile, 256 threads (8 warps as 2m x 4n, warp tile 32x16).
// PDL=true: B (weight) tile-0 load is issued BEFORE the grid dependency sync;
// A (recurrent state) is only touched after.
#define HM_STRIDE 40
#define HM_BUFH   (64 * HM_STRIDE)
template<bool PDL>
__device__ __forceinline__ void hmma_block(
    const __half* __restrict__ Ag0, int lda,
    const __half* __restrict__ Bg0, int ldb,
    int nit, float acc[2][2][4], __half* As, __half* Bs)
{
    const int tid  = threadIdx.x;
    const int lane = tid & 31, warp = tid >> 5;

    const __half* Ag = Ag0 + (size_t)(tid >> 2) * lda + (tid & 3) * 8;
    const __half* Bg = Bg0 + (size_t)(tid >> 2) * ldb + (tid & 3) * 8;
    const uint32_t st_off = ((tid >> 2) * HM_STRIDE + (tid & 3) * 8) * 2;
    const uint32_t as_base = (uint32_t)__cvta_generic_to_shared(As);
    const uint32_t bs_base = (uint32_t)__cvta_generic_to_shared(Bs);

    const int arow = (warp >> 2) * 32 + (lane & 7) + ((lane >> 3) & 1) * 8;
    const uint32_t a_off0 = (arow * HM_STRIDE + (lane >> 4) * 8) * 2;
    const uint32_t a_off1 = a_off0 + 16 * HM_STRIDE * 2;
    const int brow = (warp & 3) * 16 + (lane & 7) + (lane >> 4) * 8;
    const uint32_t b_off = (brow * HM_STRIDE + ((lane >> 3) & 1) * 8) * 2;

    // weight tile 0 first (independent of predecessor kernel)
    uint4 pb0 = *(const uint4*)Bg;
    if (PDL) cudaGridDependencySynchronize();
    uint4 pa0 = *(const uint4*)Ag;

    *(uint4*)((char*)As + st_off) = pa0;
    *(uint4*)((char*)Bs + st_off) = pb0;
    __syncthreads();

    const uint32_t BUFB = HM_BUFH * 2;
    int buf = 0;
#pragma unroll 1
    for (int it = 0; it < nit; it++) {
        uint4 pa, pb;
        const bool more = (it + 1 < nit);
        if (more) {
            pa = *(const uint4*)(Ag + (it + 1) * 32);
            pb = *(const uint4*)(Bg + (it + 1) * 32);
        }
        const uint32_t ab = as_base + buf * BUFB;
        const uint32_t bb = bs_base + buf * BUFB;
#pragma unroll
        for (int kk = 0; kk < 2; kk++) {
            uint32_t af0[4], af1[4], bf[4];
            ldsm4(af0, ab + a_off0 + kk * 32);
            ldsm4(af1, ab + a_off1 + kk * 32);
            ldsm4(bf,  bb + b_off  + kk * 32);
            mma_16816(acc[0][0], af0, bf[0], bf[1]);
            mma_16816(acc[0][1], af0, bf[2], bf[3]);
            mma_16816(acc[1][0], af1, bf[0], bf[1]);
            mma_16816(acc[1][1], af1, bf[2], bf[3]);
        }
        if (more) {
            const int nb = buf ^ 1;
            *(uint4*)((char*)As + nb * BUFB + st_off) = pa;
            *(uint4*)((char*)Bs + nb * BUFB + st_off) = pb;
            __syncthreads();
            buf = nb;
        }
    }
}

// ---------------- per-step GEMMs via HMMA, uniform K=256 tiles ---------------
// grid (16, 24): y 0..3 -> U1 (K 0:256); y 4..7 -> U2 (K 256:512);
//                y 8..23 -> GATES (K=256). Outputs fp16.
__global__ void step_gemm_hmma() {
    __shared__ __half As[2][HM_BUFH];
    __shared__ __half Bs[2][HM_BUFH];

    const int y = blockIdx.y;
    const __half* Bg; __half* C; int ldb, ldc, col0, koff;
    if (y < 8) {
        const int half = y >> 2;                 // 0 -> U1, 1 -> U2
        koff = half * 256;
        Bg   = g_Wdd16 + (size_t)(y & 3) * 64 * 512 + koff;
        ldb  = 512; C = half ? g_U2h : g_U1h; ldc = 256; col0 = (y & 3) * 64;
    } else {
        koff = 0;
        Bg   = g_Whh16 + (size_t)(y - 8) * 64 * 256;
        ldb  = 256; C = g_GATESh; ldc = 1024; col0 = (y - 8) * 64;
    }

    float acc[2][2][4] = {};
    hmma_block<true>(g_HCh + (size_t)blockIdx.x * 64 * 512 + koff, 512,
                     Bg, ldb, 8, acc, &As[0][0], &Bs[0][0]);

    const int lane = threadIdx.x & 31, warp = threadIdx.x >> 5;
    const int gid = lane >> 2, tig = lane & 3;
    const int mrow0 = blockIdx.x * 64 + (warp >> 2) * 32;
    const int c0 = col0 + (warp & 3) * 16;
#pragma unroll
    for (int mt = 0; mt < 2; mt++)
#pragma unroll
        for (int nt = 0; nt < 2; nt++) {
            const float* a = acc[mt][nt];
            const int r  = mrow0 + mt * 16 + gid;
            const int cc = c0 + nt * 8 + tig * 2;
            *(__half2*)&C[(size_t)r * ldc + cc]       = __floats2half2_rn(a[0], a[1]);
            *(__half2*)&C[(size_t)(r + 8) * ldc + cc] = __floats2half2_rn(a[2], a[3]);
        }
}

// ---------------- A precompute via HMMA: A half of g_AX ----------------------
__global__ void precompute_A_hmma() {
    __shared__ __half As[2][HM_BUFH];
    __shared__ __half Bs[2][HM_BUFH];

    float acc[2][2][4] = {};
    hmma_block<false>(g_AX + (size_t)blockIdx.x * 64 * 512 + 256, 512,
                      g_Wdx16 + (size_t)blockIdx.y * 64 * 256, 256, 8,
                      acc, &As[0][0], &Bs[0][0]);

    const int lane = threadIdx.x & 31, warp = threadIdx.x >> 5;
    const int gid = lane >> 2, tig = lane & 3;
    const int mrow0 = blockIdx.x * 64 + (warp >> 2) * 32;
    const int c0 = blockIdx.y * 64 + (warp & 3) * 16;
#pragma unroll
    for (int mt = 0; mt < 2; mt++)
#pragma unroll
        for (int nt = 0; nt < 2; nt++) {
            const float* a = acc[mt][nt];
            const int r  = mrow0 + mt * 16 + gid;
            const int cc = c0 + nt * 8 + tig * 2;
            *(__half2*)&g_AX[(size_t)r * 512 + cc]       = __floats2half2_rn(a[0], a[1]);
            *(__half2*)&g_AX[(size_t)(r + 8) * 512 + cc] = __floats2half2_rn(a[2], a[3]);
        }
}

// ---------------- fused attention (online softmax) + LSTM step --------------
// 512 blocks, 2 batches per block; warps 0-3 -> batch0, warps 4-7 -> batch1.
// PDL: AX/v_d prefetch before dependency sync; trigger right after h,c stores.
__global__ void __launch_bounds__(256, 4)
attn_lstm_kernel(const float* __restrict__ v_d,
                 const float* __restrict__ Wl,
                 const float* __restrict__ Y,
                 const float* __restrict__ W_ih,
                 int t_step)
{
    __shared__ float ctx_ws[8][M_SZ];
    __shared__ float wM[8], wS[8];
    __shared__ float redy[2][8];
    __shared__ float yt_s[2];

    const int tid  = threadIdx.x;     // 0..255
    const int lane = tid & 31;
    const int warp = tid >> 5;
    const int wg   = warp & 3;        // t offset within batch
    const int bg   = warp >> 2;       // which batch of the pair
    const int b    = blockIdx.x * 2 + bg;

    // ---- prologue independent of predecessor: AX pipeline warm-up + v_d ----
    const float4* AXrow = (const float4*)(g_AX + (size_t)b * T_SZ * 512) + lane;
    float4 a0 = __ldg(AXrow + (size_t)wg * 64);
    float4 x0 = __ldg(AXrow + (size_t)wg * 64 + 32);
    float4 a1 = __ldg(AXrow + (size_t)(wg + 4) * 64);
    float4 x1 = __ldg(AXrow + (size_t)(wg + 4) * 64 + 32);
    const int mb = lane * 8;
    float4 va  = __ldg((const float4*)(v_d + mb));
    float4 vb  = __ldg((const float4*)(v_d + mb + 4));

    // ---- wait for step_gemm's U/GATES ----
    cudaGridDependencySynchronize();

    // per-lane u,v slices as half2 (m = lane*8 .. lane*8+7), reused 32x
    __half2 u2[4], v2[4];
    {
        uint4 u1r = __ldg((const uint4*)(g_U1h + b * M_SZ) + lane);
        uint4 u2r = __ldg((const uint4*)(g_U2h + b * M_SZ) + lane);
        const __half2* p1 = (const __half2*)&u1r;
        const __half2* p2 = (const __half2*)&u2r;
#pragma unroll
        for (int j = 0; j < 4; j++) u2[j] = __hadd2(p1[j], p2[j]);
        v2[0] = __floats2half2_rn(va.x, va.y);
        v2[1] = __floats2half2_rn(va.z, va.w);
        v2[2] = __floats2half2_rn(vb.x, vb.y);
        v2[3] = __floats2half2_rn(vb.z, vb.w);
    }

    // single pass: logits + online softmax + ctx accumulation
    float C[8] = {0, 0, 0, 0, 0, 0, 0, 0};
    float Mx = -1e30f, S = 0.0f;

#pragma unroll 4
    for (int i = 0; i < 32; i++) {
        const int t = wg + i * 4;
        float4 a2, x2;
        if (i < 30) {
            a2 = __ldg(AXrow + (size_t)(t + 8) * 64);
            x2 = __ldg(AXrow + (size_t)(t + 8) * 64 + 32);
        }

        // logit partial from this lane's 8 m-values (f16x2 path)
        const __half2* ahp = (const __half2*)&a0;
        const __half2* xhp = (const __half2*)&x0;
        __half2 acch = __floats2half2_rn(0.0f, 0.0f);
        float xv[8];
#pragma unroll
        for (int j = 0; j < 4; j++) {
            __half2 s  = __hadd2(u2[j], ahp[j]);
            __half2 th = h2tanh_fast(s);
            acch = __hfma2(v2[j], th, acch);
            float2 xf = __half22float2(xhp[j]);
            xv[2 * j] = xf.x; xv[2 * j + 1] = xf.y;
        }
        float acc = __low2float(acch) + __high2float(acch);
#pragma unroll
        for (int o = 16; o; o >>= 1) acc += __shfl_xor_sync(0xffffffffu, acc, o);
        // acc = l_t, uniform across warp

        if (acc <= Mx) {                 // warp-uniform branch
            float e = __expf(acc - Mx);
            S += e;
#pragma unroll
            for (int j = 0; j < 8; j++) C[j] = fmaf(e, xv[j], C[j]);
        } else {
            float f = __expf(Mx - acc);
            S = fmaf(S, f, 1.0f);
#pragma unroll
            for (int j = 0; j < 8; j++) C[j] = fmaf(C[j], f, xv[j]);
            Mx = acc;
        }

        a0 = a1; x0 = x1; a1 = a2; x1 = x2;
    }

    // per-warp results -> smem
    if (lane == 0) { wM[warp] = Mx; wS[warp] = S; }
    *(float4*)&ctx_ws[warp][lane * 8]     = make_float4(C[0], C[1], C[2], C[3]);
    *(float4*)&ctx_ws[warp][lane * 8 + 4] = make_float4(C[4], C[5], C[6], C[7]);
    __syncthreads();

    // per-batch combine (each thread computes ctx[m=tid] for both batches)
    float cg[2];
#pragma unroll
    for (int g = 0; g < 2; g++) {
        float Mg = fmaxf(fmaxf(wM[4 * g], wM[4 * g + 1]),
                         fmaxf(wM[4 * g + 2], wM[4 * g + 3]));
        float Sg = 0.0f, c = 0.0f;
#pragma unroll
        for (int w = 0; w < 4; w++) {
            float f = __expf(wM[4 * g + w] - Mg);
            Sg = fmaf(wS[4 * g + w], f, Sg);
            c  = fmaf(f, ctx_ws[4 * g + w][tid], c);
        }
        cg[g] = c / Sg;
    }

    if (t_step == TS - 1) {
        g_CTX[(blockIdx.x * 2)     * M_SZ + tid] = cg[0];
        g_CTX[(blockIdx.x * 2 + 1) * M_SZ + tid] = cg[1];
    }

    // y_tilde per batch: Wl[0]*y_t + sum_m Wl[1+m]*ctx[m]
    const float wl = __ldg(Wl + 1 + tid);
#pragma unroll
    for (int g = 0; g < 2; g++) {
        float yv = wl * cg[g];
#pragma unroll
        for (int o = 16; o; o >>= 1) yv += __shfl_xor_sync(0xffffffffu, yv, o);
        if (lane == 0) redy[g][warp] = yv;
    }
    __syncthreads();
    if (tid < 2) {
        float s = redy[tid][0] + redy[tid][1] + redy[tid][2] + redy[tid][3]
                + redy[tid][4] + redy[tid][5] + redy[tid][6] + redy[tid][7];
        yt_s[tid] = fmaf(__ldg(Wl),
                         Y[(size_t)(blockIdx.x * 2 + tid) * TS + t_step], s);
    }
    __syncthreads();

    // fused LSTM pointwise update for both batches
    const int p = tid;
    const float wi0 = __ldg(W_ih + p);
    const float wi1 = __ldg(W_ih + P_SZ + p);
    const float wi2 = __ldg(W_ih + 2 * P_SZ + p);
    const float wi3 = __ldg(W_ih + 3 * P_SZ + p);
    const float bz0 = g_bias[p], bz1 = g_bias[P_SZ + p];
    const float bz2 = g_bias[2 * P_SZ + p], bz3 = g_bias[3 * P_SZ + p];

#pragma unroll
    for (int g = 0; g < 2; g++) {
        const int bb = blockIdx.x * 2 + g;
        const float yt = yt_s[g];
        const __half* gr = g_GATESh + (size_t)bb * 4 * P_SZ;
        float ig = __half2float(gr[p])            + yt * wi0 + bz0;
        float fg = __half2float(gr[P_SZ + p])     + yt * wi1 + bz1;
        float gg = __half2float(gr[2 * P_SZ + p]) + yt * wi2 + bz2;
        float og = __half2float(gr[3 * P_SZ + p]) + yt * wi3 + bz3;

        float cold = g_HC[(size_t)bb * 512 + 256 + p];
        float si = 1.0f / (1.0f + __expf(-ig));
        float sf = 1.0f / (1.0f + __expf(-fg));
        float so = 1.0f / (1.0f + __expf(-og));
        float cn = sf * cold + si * tanhf(gg);
        float hn = so * tanhf(cn);

        g_HC[(size_t)bb * 512 + p]        = hn;
        g_HC[(size_t)bb * 512 + 256 + p]  = cn;
        g_HCh[(size_t)bb * 512 + p]       = __float2half_rn(hn);
        g_HCh[(size_t)bb * 512 + 256 + p] = __float2half_rn(cn);
    }

    // make h,c visible, then let the next step's GEMM launch
    __threadfence();
    __syncthreads();
    cudaTriggerProgrammaticLaunchCompletion();
}

// ---------------- final head: out = ([h,ctx] @ Wb^T + b) @ vb^T + vb_b -----
__global__ void final_head_kernel(const float* __restrict__ Wb_w,
                                  const float* __restrict__ Wb_b,
                                  const float* __restrict__ vb_w,
                                  const float* __restrict__ vb_b,
                                  float* __restrict__ out)
{
    const int b   = blockIdx.x;
    const int tid = threadIdx.x;  // 0..255 = p
    __shared__ float hc_s[512];
    __shared__ float red[8];

    hc_s[tid]        = g_HC[(size_t)b * 512 + tid];        // h
    hc_s[P_SZ + tid] = g_CTX[(size_t)b * M_SZ + tid];      // ctx
    __syncthreads();

    const float* wr = Wb_w + (size_t)tid * (P_SZ + M_SZ);
    float t = __ldg(Wb_b + tid);
#pragma unroll 4
    for (int k = 0; k < 2 * P_SZ; k++)
        t = fmaf(__ldg(wr + k), hc_s[k], t);
    float val = __ldg(vb_w + tid) * t;

    int lane = tid & 31, warp = tid >> 5;
#pragma unroll
    for (int o = 16; o; o >>= 1) val += __shfl_xor_sync(0xffffffffu, val, o);
    if (lane == 0) red[warp] = val;
    __syncthreads();
    if (tid == 0)
        out[b] = vb_b[0] + red[0] + red[1] + red[2] + red[3]
                         + red[4] + red[5] + red[6] + red[7];
}

// ---------------- launch ----------------------------------------------------
extern "C" void kernel_launch(void* const* d_in, const int* in_sizes, int n_in,
                              void* d_out, int out_size)
{
    const float* Y    = (const float*)d_in[0];
    const float* X    = (const float*)d_in[1];
    const float* WU_d = (const float*)d_in[2];
    const float* v_d  = (const float*)d_in[3];
    const float* Wl   = (const float*)d_in[4];
    const float* W_ih = (const float*)d_in[5];
    const float* W_hh = (const float*)d_in[6];
    const float* b_ih = (const float*)d_in[7];
    const float* b_hh = (const float*)d_in[8];
    const float* Wb_w = (const float*)d_in[9];
    const float* Wb_b = (const float*)d_in[10];
    const float* vb_w = (const float*)d_in[11];
    const float* vb_b = (const float*)d_in[12];
    float* out = (float*)d_out;

    // init h, c = 0 (fp32 + fp16 mirrors)
    init_hc_kernel<<<(B_SZ * 512 + 255) / 256, 256>>>();

    // X -> interleaved AX (X half) fp16 ; weights -> fp16 ; fused bias
    convert_x_kernel<<<(T_SZ * B_SZ) / 4, 256>>>(X);
    convert_w_kernel<<<1024, 256>>>(WU_d, W_hh, b_ih, b_hh);

    // A half of g_AX = X16 @ Wdx^T (HMMA)
    precompute_A_hmma<<<dim3((B_SZ * T_SZ) / 64, M_SZ / 64), 256>>>();

    // PDL-chained recurrence
    cudaLaunchAttribute pdl[1];
    pdl[0].id = cudaLaunchAttributeProgrammaticStreamSerialization;
    pdl[0].val.programmaticStreamSerializationAllowed = 1;

    cudaLaunchConfig_t cfg_g = {};
    cfg_g.gridDim  = dim3(B_SZ / 64, 24);
    cfg_g.blockDim = dim3(256);
    cfg_g.stream   = 0;
    cfg_g.attrs    = pdl;
    cfg_g.numAttrs = 1;

    cudaLaunchConfig_t cfg_a = {};
    cfg_a.gridDim  = dim3(B_SZ / 2);
    cfg_a.blockDim = dim3(256);
    cfg_a.stream   = 0;
    cfg_a.attrs    = pdl;
    cfg_a.numAttrs = 1;

    for (int t = 0; t < TS; t++) {
        cudaLaunchKernelEx(&cfg_g, step_gemm_hmma);
        cudaLaunchKernelEx(&cfg_a, attn_lstm_kernel, v_d, Wl, Y, W_ih, t);
    }

    final_head_kernel<<<B_SZ, 256>>>(Wb_w, Wb_b, vb_w, vb_b, out);
}

// round 13
// speedup vs baseline: 3.7358x; 1.1339x over previous
#include <cuda_runtime.h>
#include <cuda_fp16.h>
#include <cstdint>
#include <cstddef>

#define B_SZ 1024
#define T_SZ 128
#define M_SZ 256
#define P_SZ 256
#define TS   127   // T-1 recurrence steps

// ---------------- scratch (static device globals) ---------------------------
// interleaved per-(b,t) row: [ A[0..255] | X[0..255] ] fp16, stride 512
__device__ __half g_AX[(size_t)B_SZ * T_SZ * 512];
__device__ __half g_HCh[B_SZ * 512];                 // fp16 mirror of [h|c]
__device__ __half g_Wdd16[256 * 512];                // WU_d[:, :512] fp16
__device__ __half g_Whh16[1024 * 256];               // W_hh fp16
__device__ __half g_Wdx16[256 * 256];                // WU_d[:, 512:768] fp16
__device__ float  g_bias[4 * P_SZ];                  // b_ih + b_hh
__device__ __half g_U1h[B_SZ * M_SZ];                // d-part preact, K 0:256 (fp16)
__device__ __half g_U2h[B_SZ * M_SZ];                // d-part preact, K 256:512 (fp16)
__device__ __half g_GATESh[B_SZ * 4 * P_SZ];         // h @ W_hh^T (fp16)
__device__ float  g_HC[B_SZ * 512];                  // fp32 master [h|c]
__device__ float  g_CTX[B_SZ * M_SZ];                // attention context (last step)

// ---------------- init ------------------------------------------------------
__global__ void init_hc_kernel() {
    int i = blockIdx.x * blockDim.x + threadIdx.x;
    if (i < B_SZ * 512) { g_HC[i] = 0.0f; g_HCh[i] = __float2half_rn(0.0f); }
}

// ---------------- X (t,b,m) fp32 -> g_AX[b,t, 256+m] fp16 -------------------
__global__ void convert_x_kernel(const float* __restrict__ X) {
    int row = blockIdx.x * 4 + (threadIdx.x >> 6);   // row = t*B + b
    int c4  = (threadIdx.x & 63) * 4;
    int t = row >> 10;
    int b = row & 1023;
    float4 v = __ldg((const float4*)(X + (size_t)row * M_SZ + c4));
    __half2* dst = (__half2*)(g_AX + ((size_t)(b << 7) + t) * 512 + 256 + c4);
    dst[0] = __floats2half2_rn(v.x, v.y);
    dst[1] = __floats2half2_rn(v.z, v.w);
}

// ---------------- weights -> fp16, fused bias -------------------------------
__global__ void convert_w_kernel(const float* __restrict__ WU_d,
                                 const float* __restrict__ W_hh,
                                 const float* __restrict__ b_ih,
                                 const float* __restrict__ b_hh) {
    int i = blockIdx.x * 256 + threadIdx.x;          // 0 .. 262143
    if (i < 256 * 512) {
        int r = i >> 9, k = i & 511;
        g_Wdd16[i] = __float2half_rn(WU_d[r * 768 + k]);
    }
    if (i < 256 * 256) {
        int r = i >> 8, k = i & 255;
        g_Wdx16[i] = __float2half_rn(WU_d[r * 768 + 512 + k]);
    }
    if (i < 1024 * 256) {
        g_Whh16[i] = __float2half_rn(W_hh[i]);
    }
    if (i < 1024) {
        g_bias[i] = b_ih[i] + b_hh[i];
    }
}

// ---------------- HMMA helpers ----------------------------------------------
__device__ __forceinline__ void ldsm4(uint32_t* r, uint32_t addr) {
    asm volatile("ldmatrix.sync.aligned.m8n8.x4.shared.b16 {%0,%1,%2,%3}, [%4];"
                 : "=r"(r[0]), "=r"(r[1]), "=r"(r[2]), "=r"(r[3]) : "r"(addr));
}

__device__ __forceinline__ void mma_16816(float* acc, const uint32_t* a,
                                          uint32_t b0, uint32_t b1) {
    asm volatile(
        "mma.sync.aligned.m16n8k16.row.col.f32.f16.f16.f32 "
        "{%0,%1,%2,%3},{%4,%5,%6,%7},{%8,%9},{%0,%1,%2,%3};"
        : "+f"(acc[0]), "+f"(acc[1]), "+f"(acc[2]), "+f"(acc[3])
        : "r"(a[0]), "r"(a[1]), "r"(a[2]), "r"(a[3]), "r"(b0), "r"(b1));
}

__device__ __forceinline__ __half2 h2tanh_fast(__half2 x) {
    uint32_t xi = *(uint32_t*)&x, yo;
    asm("tanh.approx.f16x2 %0, %1;" : "=r"(yo) : "r"(xi));
    return *(__half2*)&yo;
}

// 64x64 block tile, 256 threads (8 warps as 2m x 4n, warp tile 32x16).
// PDL=true: B (weight) tile-0 load is issued BEFORE the grid dependency sync;
// A (recurrent state) is only touched after.
#define HM_STRIDE 40
#define HM_BUFH   (64 * HM_STRIDE)
template<bool PDL>
__device__ __forceinline__ void hmma_block(
    const __half* __restrict__ Ag0, int lda,
    const __half* __restrict__ Bg0, int ldb,
    int nit, float acc[2][2][4], __half* As, __half* Bs)
{
    const int tid  = threadIdx.x;
    const int lane = tid & 31, warp = tid >> 5;

    const __half* Ag = Ag0 + (size_t)(tid >> 2) * lda + (tid & 3) * 8;
    const __half* Bg = Bg0 + (size_t)(tid >> 2) * ldb + (tid & 3) * 8;
    const uint32_t st_off = ((tid >> 2) * HM_STRIDE + (tid & 3) * 8) * 2;
    const uint32_t as_base = (uint32_t)__cvta_generic_to_shared(As);
    const uint32_t bs_base = (uint32_t)__cvta_generic_to_shared(Bs);

    const int arow = (warp >> 2) * 32 + (lane & 7) + ((lane >> 3) & 1) * 8;
    const uint32_t a_off0 = (arow * HM_STRIDE + (lane >> 4) * 8) * 2;
    const uint32_t a_off1 = a_off0 + 16 * HM_STRIDE * 2;
    const int brow = (warp & 3) * 16 + (lane & 7) + (lane >> 4) * 8;
    const uint32_t b_off = (brow * HM_STRIDE + ((lane >> 3) & 1) * 8) * 2;

    // weight tile 0 first (independent of predecessor kernel)
    uint4 pb0 = *(const uint4*)Bg;
    if (PDL) cudaGridDependencySynchronize();
    uint4 pa0 = *(const uint4*)Ag;

    *(uint4*)((char*)As + st_off) = pa0;
    *(uint4*)((char*)Bs + st_off) = pb0;
    __syncthreads();

    const uint32_t BUFB = HM_BUFH * 2;
    int buf = 0;
#pragma unroll 1
    for (int it = 0; it < nit; it++) {
        uint4 pa, pb;
        const bool more = (it + 1 < nit);
        if (more) {
            pa = *(const uint4*)(Ag + (it + 1) * 32);
            pb = *(const uint4*)(Bg + (it + 1) * 32);
        }
        const uint32_t ab = as_base + buf * BUFB;
        const uint32_t bb = bs_base + buf * BUFB;
#pragma unroll
        for (int kk = 0; kk < 2; kk++) {
            uint32_t af0[4], af1[4], bf[4];
            ldsm4(af0, ab + a_off0 + kk * 32);
            ldsm4(af1, ab + a_off1 + kk * 32);
            ldsm4(bf,  bb + b_off  + kk * 32);
            mma_16816(acc[0][0], af0, bf[0], bf[1]);
            mma_16816(acc[0][1], af0, bf[2], bf[3]);
            mma_16816(acc[1][0], af1, bf[0], bf[1]);
            mma_16816(acc[1][1], af1, bf[2], bf[3]);
        }
        if (more) {
            const int nb = buf ^ 1;
            *(uint4*)((char*)As + nb * BUFB + st_off) = pa;
            *(uint4*)((char*)Bs + nb * BUFB + st_off) = pb;
            __syncthreads();
            buf = nb;
        }
    }
}

// ---------------- per-step GEMMs via HMMA, uniform K=256 tiles ---------------
// grid (16, 24): y 0..3 -> U1 (K 0:256); y 4..7 -> U2 (K 256:512);
//                y 8..23 -> GATES (K=256). Outputs fp16.
__global__ void step_gemm_hmma() {
    __shared__ __half As[2][HM_BUFH];
    __shared__ __half Bs[2][HM_BUFH];

    const int y = blockIdx.y;
    const __half* Bg; __half* C; int ldb, ldc, col0, koff;
    if (y < 8) {
        const int half = y >> 2;                 // 0 -> U1, 1 -> U2
        koff = half * 256;
        Bg   = g_Wdd16 + (size_t)(y & 3) * 64 * 512 + koff;
        ldb  = 512; C = half ? g_U2h : g_U1h; ldc = 256; col0 = (y & 3) * 64;
    } else {
        koff = 0;
        Bg   = g_Whh16 + (size_t)(y - 8) * 64 * 256;
        ldb  = 256; C = g_GATESh; ldc = 1024; col0 = (y - 8) * 64;
    }

    float acc[2][2][4] = {};
    hmma_block<true>(g_HCh + (size_t)blockIdx.x * 64 * 512 + koff, 512,
                     Bg, ldb, 8, acc, &As[0][0], &Bs[0][0]);

    const int lane = threadIdx.x & 31, warp = threadIdx.x >> 5;
    const int gid = lane >> 2, tig = lane & 3;
    const int mrow0 = blockIdx.x * 64 + (warp >> 2) * 32;
    const int c0 = col0 + (warp & 3) * 16;
#pragma unroll
    for (int mt = 0; mt < 2; mt++)
#pragma unroll
        for (int nt = 0; nt < 2; nt++) {
            const float* a = acc[mt][nt];
            const int r  = mrow0 + mt * 16 + gid;
            const int cc = c0 + nt * 8 + tig * 2;
            *(__half2*)&C[(size_t)r * ldc + cc]       = __floats2half2_rn(a[0], a[1]);
            *(__half2*)&C[(size_t)(r + 8) * ldc + cc] = __floats2half2_rn(a[2], a[3]);
        }
}

// ---------------- A precompute via HMMA: A half of g_AX ----------------------
__global__ void precompute_A_hmma() {
    __shared__ __half As[2][HM_BUFH];
    __shared__ __half Bs[2][HM_BUFH];

    float acc[2][2][4] = {};
    hmma_block<false>(g_AX + (size_t)blockIdx.x * 64 * 512 + 256, 512,
                      g_Wdx16 + (size_t)blockIdx.y * 64 * 256, 256, 8,
                      acc, &As[0][0], &Bs[0][0]);

    const int lane = threadIdx.x & 31, warp = threadIdx.x >> 5;
    const int gid = lane >> 2, tig = lane & 3;
    const int mrow0 = blockIdx.x * 64 + (warp >> 2) * 32;
    const int c0 = blockIdx.y * 64 + (warp & 3) * 16;
#pragma unroll
    for (int mt = 0; mt < 2; mt++)
#pragma unroll
        for (int nt = 0; nt < 2; nt++) {
            const float* a = acc[mt][nt];
            const int r  = mrow0 + mt * 16 + gid;
            const int cc = c0 + nt * 8 + tig * 2;
            *(__half2*)&g_AX[(size_t)r * 512 + cc]       = __floats2half2_rn(a[0], a[1]);
            *(__half2*)&g_AX[(size_t)(r + 8) * 512 + cc] = __floats2half2_rn(a[2], a[3]);
        }
}

// ---------------- fused attention (online softmax) + LSTM step --------------
// 512 blocks, 2 batches per block; warps 0-3 -> batch0, warps 4-7 -> batch1.
// Serpentine t-sweep: even steps forward, odd steps backward -> L2-resident
// re-reads instead of LRU cyclic thrash. Online softmax is order-invariant.
__global__ void __launch_bounds__(256, 4)
attn_lstm_kernel(const float* __restrict__ v_d,
                 const float* __restrict__ Wl,
                 const float* __restrict__ Y,
                 const float* __restrict__ W_ih,
                 int t_step)
{
    __shared__ float ctx_ws[8][M_SZ];
    __shared__ float wM[8], wS[8];
    __shared__ float redy[2][8];
    __shared__ float yt_s[2];

    const int tid  = threadIdx.x;     // 0..255
    const int lane = tid & 31;
    const int warp = tid >> 5;
    const int wg   = warp & 3;        // t offset within batch
    const int bg   = warp >> 2;       // which batch of the pair
    const int b    = blockIdx.x * 2 + bg;

    // serpentine direction
    const int dir   = t_step & 1;
    const int r0    = dir ? (T_SZ - 1 - wg) : wg;
    const int rstep = dir ? -4 : 4;

    // ---- prologue independent of predecessor: AX pipeline warm-up + v_d ----
    const float4* AXrow = (const float4*)(g_AX + (size_t)b * T_SZ * 512) + lane;
    float4 a0 = __ldg(AXrow + (size_t)r0 * 64);
    float4 x0 = __ldg(AXrow + (size_t)r0 * 64 + 32);
    float4 a1 = __ldg(AXrow + (size_t)(r0 + rstep) * 64);
    float4 x1 = __ldg(AXrow + (size_t)(r0 + rstep) * 64 + 32);
    const int mb = lane * 8;
    float4 va  = __ldg((const float4*)(v_d + mb));
    float4 vb  = __ldg((const float4*)(v_d + mb + 4));

    // ---- wait for step_gemm's U/GATES ----
    cudaGridDependencySynchronize();

    // per-lane u,v slices as half2 (m = lane*8 .. lane*8+7), reused 32x
    __half2 u2[4], v2[4];
    {
        uint4 u1r = __ldg((const uint4*)(g_U1h + b * M_SZ) + lane);
        uint4 u2r = __ldg((const uint4*)(g_U2h + b * M_SZ) + lane);
        const __half2* p1 = (const __half2*)&u1r;
        const __half2* p2 = (const __half2*)&u2r;
#pragma unroll
        for (int j = 0; j < 4; j++) u2[j] = __hadd2(p1[j], p2[j]);
        v2[0] = __floats2half2_rn(va.x, va.y);
        v2[1] = __floats2half2_rn(va.z, va.w);
        v2[2] = __floats2half2_rn(vb.x, vb.y);
        v2[3] = __floats2half2_rn(vb.z, vb.w);
    }

    // single pass: logits + online softmax + ctx accumulation
    float C[8] = {0, 0, 0, 0, 0, 0, 0, 0};
    float Mx = -1e30f, S = 0.0f;

#pragma unroll 4
    for (int i = 0; i < 32; i++) {
        float4 a2, x2;
        if (i < 30) {
            const int rn = r0 + (i + 2) * rstep;
            a2 = __ldg(AXrow + (size_t)rn * 64);
            x2 = __ldg(AXrow + (size_t)rn * 64 + 32);
        }

        // logit partial from this lane's 8 m-values (f16x2 path)
        const __half2* ahp = (const __half2*)&a0;
        const __half2* xhp = (const __half2*)&x0;
        __half2 acch = __floats2half2_rn(0.0f, 0.0f);
        float xv[8];
#pragma unroll
        for (int j = 0; j < 4; j++) {
            __half2 s  = __hadd2(u2[j], ahp[j]);
            __half2 th = h2tanh_fast(s);
            acch = __hfma2(v2[j], th, acch);
            float2 xf = __half22float2(xhp[j]);
            xv[2 * j] = xf.x; xv[2 * j + 1] = xf.y;
        }
        float acc = __low2float(acch) + __high2float(acch);
#pragma unroll
        for (int o = 16; o; o >>= 1) acc += __shfl_xor_sync(0xffffffffu, acc, o);
        // acc = l_t, uniform across warp

        if (acc <= Mx) {                 // warp-uniform branch
            float e = __expf(acc - Mx);
            S += e;
#pragma unroll
            for (int j = 0; j < 8; j++) C[j] = fmaf(e, xv[j], C[j]);
        } else {
            float f = __expf(Mx - acc);
            S = fmaf(S, f, 1.0f);
#pragma unroll
            for (int j = 0; j < 8; j++) C[j] = fmaf(C[j], f, xv[j]);
            Mx = acc;
        }

        a0 = a1; x0 = x1; a1 = a2; x1 = x2;
    }

    // per-warp results -> smem
    if (lane == 0) { wM[warp] = Mx; wS[warp] = S; }
    *(float4*)&ctx_ws[warp][lane * 8]     = make_float4(C[0], C[1], C[2], C[3]);
    *(float4*)&ctx_ws[warp][lane * 8 + 4] = make_float4(C[4], C[5], C[6], C[7]);
    __syncthreads();

    // per-batch combine (each thread computes ctx[m=tid] for both batches)
    float cg[2];
#pragma unroll
    for (int g = 0; g < 2; g++) {
        float Mg = fmaxf(fmaxf(wM[4 * g], wM[4 * g + 1]),
                         fmaxf(wM[4 * g + 2], wM[4 * g + 3]));
        float Sg = 0.0f, c = 0.0f;
#pragma unroll
        for (int w = 0; w < 4; w++) {
            float f = __expf(wM[4 * g + w] - Mg);
            Sg = fmaf(wS[4 * g + w], f, Sg);
            c  = fmaf(f, ctx_ws[4 * g + w][tid], c);
        }
        cg[g] = c / Sg;
    }

    if (t_step == TS - 1) {
        g_CTX[(blockIdx.x * 2)     * M_SZ + tid] = cg[0];
        g_CTX[(blockIdx.x * 2 + 1) * M_SZ + tid] = cg[1];
    }

    // y_tilde per batch: Wl[0]*y_t + sum_m Wl[1+m]*ctx[m]
    const float wl = __ldg(Wl + 1 + tid);
#pragma unroll
    for (int g = 0; g < 2; g++) {
        float yv = wl * cg[g];
#pragma unroll
        for (int o = 16; o; o >>= 1) yv += __shfl_xor_sync(0xffffffffu, yv, o);
        if (lane == 0) redy[g][warp] = yv;
    }
    __syncthreads();
    if (tid < 2) {
        float s = redy[tid][0] + redy[tid][1] + redy[tid][2] + redy[tid][3]
                + redy[tid][4] + redy[tid][5] + redy[tid][6] + redy[tid][7];
        yt_s[tid] = fmaf(__ldg(Wl),
                         Y[(size_t)(blockIdx.x * 2 + tid) * TS + t_step], s);
    }
    __syncthreads();

    // fused LSTM pointwise update for both batches
    const int p = tid;
    const float wi0 = __ldg(W_ih + p);
    const float wi1 = __ldg(W_ih + P_SZ + p);
    const float wi2 = __ldg(W_ih + 2 * P_SZ + p);
    const float wi3 = __ldg(W_ih + 3 * P_SZ + p);
    const float bz0 = g_bias[p], bz1 = g_bias[P_SZ + p];
    const float bz2 = g_bias[2 * P_SZ + p], bz3 = g_bias[3 * P_SZ + p];

#pragma unroll
    for (int g = 0; g < 2; g++) {
        const int bb = blockIdx.x * 2 + g;
        const float yt = yt_s[g];
        const __half* gr = g_GATESh + (size_t)bb * 4 * P_SZ;
        float ig = __half2float(gr[p])            + yt * wi0 + bz0;
        float fg = __half2float(gr[P_SZ + p])     + yt * wi1 + bz1;
        float gg = __half2float(gr[2 * P_SZ + p]) + yt * wi2 + bz2;
        float og = __half2float(gr[3 * P_SZ + p]) + yt * wi3 + bz3;

        float cold = g_HC[(size_t)bb * 512 + 256 + p];
        float si = 1.0f / (1.0f + __expf(-ig));
        float sf = 1.0f / (1.0f + __expf(-fg));
        float so = 1.0f / (1.0f + __expf(-og));
        float cn = sf * cold + si * tanhf(gg);
        float hn = so * tanhf(cn);

        g_HC[(size_t)bb * 512 + p]        = hn;
        g_HC[(size_t)bb * 512 + 256 + p]  = cn;
        g_HCh[(size_t)bb * 512 + p]       = __float2half_rn(hn);
        g_HCh[(size_t)bb * 512 + 256 + p] = __float2half_rn(cn);
    }

    // make h,c visible, then let the next step's GEMM launch
    __threadfence();
    __syncthreads();
    cudaTriggerProgrammaticLaunchCompletion();
}

// ---------------- final head: out = ([h,ctx] @ Wb^T + b) @ vb^T + vb_b -----
__global__ void final_head_kernel(const float* __restrict__ Wb_w,
                                  const float* __restrict__ Wb_b,
                                  const float* __restrict__ vb_w,
                                  const float* __restrict__ vb_b,
                                  float* __restrict__ out)
{
    const int b   = blockIdx.x;
    const int tid = threadIdx.x;  // 0..255 = p
    __shared__ float hc_s[512];
    __shared__ float red[8];

    hc_s[tid]        = g_HC[(size_t)b * 512 + tid];        // h
    hc_s[P_SZ + tid] = g_CTX[(size_t)b * M_SZ + tid];      // ctx
    __syncthreads();

    const float* wr = Wb_w + (size_t)tid * (P_SZ + M_SZ);
    float t = __ldg(Wb_b + tid);
#pragma unroll 4
    for (int k = 0; k < 2 * P_SZ; k++)
        t = fmaf(__ldg(wr + k), hc_s[k], t);
    float val = __ldg(vb_w + tid) * t;

    int lane = tid & 31, warp = tid >> 5;
#pragma unroll
    for (int o = 16; o; o >>= 1) val += __shfl_xor_sync(0xffffffffu, val, o);
    if (lane == 0) red[warp] = val;
    __syncthreads();
    if (tid == 0)
        out[b] = vb_b[0] + red[0] + red[1] + red[2] + red[3]
                         + red[4] + red[5] + red[6] + red[7];
}

// ---------------- launch ----------------------------------------------------
extern "C" void kernel_launch(void* const* d_in, const int* in_sizes, int n_in,
                              void* d_out, int out_size)
{
    const float* Y    = (const float*)d_in[0];
    const float* X    = (const float*)d_in[1];
    const float* WU_d = (const float*)d_in[2];
    const float* v_d  = (const float*)d_in[3];
    const float* Wl   = (const float*)d_in[4];
    const float* W_ih = (const float*)d_in[5];
    const float* W_hh = (const float*)d_in[6];
    const float* b_ih = (const float*)d_in[7];
    const float* b_hh = (const float*)d_in[8];
    const float* Wb_w = (const float*)d_in[9];
    const float* Wb_b = (const float*)d_in[10];
    const float* vb_w = (const float*)d_in[11];
    const float* vb_b = (const float*)d_in[12];
    float* out = (float*)d_out;

    // init h, c = 0 (fp32 + fp16 mirrors)
    init_hc_kernel<<<(B_SZ * 512 + 255) / 256, 256>>>();

    // X -> interleaved AX (X half) fp16 ; weights -> fp16 ; fused bias
    convert_x_kernel<<<(T_SZ * B_SZ) / 4, 256>>>(X);
    convert_w_kernel<<<1024, 256>>>(WU_d, W_hh, b_ih, b_hh);

    // A half of g_AX = X16 @ Wdx^T (HMMA)
    precompute_A_hmma<<<dim3((B_SZ * T_SZ) / 64, M_SZ / 64), 256>>>();

    // PDL-chained recurrence
    cudaLaunchAttribute pdl[1];
    pdl[0].id = cudaLaunchAttributeProgrammaticStreamSerialization;
    pdl[0].val.programmaticStreamSerializationAllowed = 1;

    cudaLaunchConfig_t cfg_g = {};
    cfg_g.gridDim  = dim3(B_SZ / 64, 24);
    cfg_g.blockDim = dim3(256);
    cfg_g.stream   = 0;
    cfg_g.attrs    = pdl;
    cfg_g.numAttrs = 1;

    cudaLaunchConfig_t cfg_a = {};
    cfg_a.gridDim  = dim3(B_SZ / 2);
    cfg_a.blockDim = dim3(256);
    cfg_a.stream   = 0;
    cfg_a.attrs    = pdl;
    cfg_a.numAttrs = 1;

    for (int t = 0; t < TS; t++) {
        cudaLaunchKernelEx(&cfg_g, step_gemm_hmma);
        cudaLaunchKernelEx(&cfg_a, attn_lstm_kernel, v_d, Wl, Y, W_ih, t);
    }

    final_head_kernel<<<B_SZ, 256>>>(Wb_w, Wb_b, vb_w, vb_b, out);
}